// round 11
// baseline (speedup 1.0000x reference)
#include <cuda_runtime.h>
#include <cuda_bf16.h>
#include <cuda_fp16.h>
#include <math.h>
#include <stdint.h>

// Problem constants
#define S_LEN  2048
#define HDIM   4096     // hidden = NH*HD
#define NHEADS 32
#define HEADD  128
#define HD2    256      // head-dim split storage: [hi(128) | lo(128)]

#define KSEG   4096     // one split segment
#define KST2   8192     // storage row stride: [seg0 | seg1]
#define SC10   0.0009765625f   // 2^-10

// Scratch (device globals: allocation-free rule)
__device__ float g_Q[S_LEN * HDIM];
__device__ float g_K[S_LEN * HDIM];
__device__ __nv_bfloat16 g_A2[S_LEN * KST2];           // X bf16 [hi|lo]
__device__ __half        g_A2f[S_LEN * KST2];          // X fp16 pair / attn out
__device__ __nv_bfloat16 g_W2q[HDIM * KST2];
__device__ __nv_bfloat16 g_W2k[HDIM * KST2];
__device__ __half        g_W2vf[HDIM * KST2];
__device__ __half        g_W2of[HDIM * KST2];
__device__ __nv_bfloat16 g_Q2[NHEADS * S_LEN * HD2];   // [h][s][Qh|Ql]
__device__ __nv_bfloat16 g_K2a[NHEADS * S_LEN * HD2];  // [h][s][Kh|Kl]
__device__ __nv_bfloat16 g_Vb[NHEADS * S_LEN * HD2];   // [h][s][Vh|Vl]

// ===========================================================================
// PTX helpers (base PTX only)
// ===========================================================================
__device__ __forceinline__ uint32_t smem_u32(const void* p) {
    uint32_t a;
    asm("{ .reg .u64 t; cvta.to.shared.u64 t, %1; cvt.u32.u64 %0, t; }" : "=r"(a) : "l"(p));
    return a;
}
__device__ __forceinline__ void cp_async16(uint32_t dst, const void* src) {
    asm volatile("cp.async.cg.shared.global [%0], [%1], 16;" :: "r"(dst), "l"(src));
}
__device__ __forceinline__ void cp_commit() {
    asm volatile("cp.async.commit_group;" ::: "memory");
}
template <int N> __device__ __forceinline__ void cp_wait() {
    asm volatile("cp.async.wait_group %0;" :: "n"(N) : "memory");
}
__device__ __forceinline__ void ldsm_x4(uint32_t& r0, uint32_t& r1, uint32_t& r2,
                                        uint32_t& r3, uint32_t addr) {
    asm volatile("ldmatrix.sync.aligned.m8n8.x4.shared.b16 {%0,%1,%2,%3}, [%4];"
                 : "=r"(r0), "=r"(r1), "=r"(r2), "=r"(r3) : "r"(addr));
}
__device__ __forceinline__ void ldsm_x4t(uint32_t& r0, uint32_t& r1, uint32_t& r2,
                                         uint32_t& r3, uint32_t addr) {
    asm volatile("ldmatrix.sync.aligned.m8n8.x4.trans.shared.b16 {%0,%1,%2,%3}, [%4];"
                 : "=r"(r0), "=r"(r1), "=r"(r2), "=r"(r3) : "r"(addr));
}
__device__ __forceinline__ void mma16816(float* c, const uint32_t* a, const uint32_t* b) {
    asm volatile(
        "mma.sync.aligned.m16n8k16.row.col.f32.bf16.bf16.f32 "
        "{%0,%1,%2,%3}, {%4,%5,%6,%7}, {%8,%9}, {%0,%1,%2,%3};"
        : "+f"(c[0]), "+f"(c[1]), "+f"(c[2]), "+f"(c[3])
        : "r"(a[0]), "r"(a[1]), "r"(a[2]), "r"(a[3]), "r"(b[0]), "r"(b[1]));
}
__device__ __forceinline__ void mma16816f(float* c, const uint32_t* a, const uint32_t* b) {
    asm volatile(
        "mma.sync.aligned.m16n8k16.row.col.f32.f16.f16.f32 "
        "{%0,%1,%2,%3}, {%4,%5,%6,%7}, {%8,%9}, {%0,%1,%2,%3};"
        : "+f"(c[0]), "+f"(c[1]), "+f"(c[2]), "+f"(c[3])
        : "r"(a[0]), "r"(a[1]), "r"(a[2]), "r"(a[3]), "r"(b[0]), "r"(b[1]));
}

__device__ __forceinline__ uint32_t pkb(__nv_bfloat16 a, __nv_bfloat16 b) {
    __nv_bfloat162 t = __halves2bfloat162(a, b);
    return *reinterpret_cast<uint32_t*>(&t);
}
__device__ __forceinline__ uint32_t pkh(__half a, __half b) {
    __half2 t = __halves2half2(a, b);
    return *reinterpret_cast<uint32_t*>(&t);
}
__device__ __forceinline__ void split2(float x, __nv_bfloat16& h, __nv_bfloat16& l) {
    h = __float2bfloat16_rn(x);
    l = __float2bfloat16_rn(x - __bfloat162float(h));
}

// ===========================================================================
// Split kernels
// ===========================================================================
__global__ void __launch_bounds__(256) split_x(const float* __restrict__ src,
                                               __nv_bfloat16* __restrict__ dstb,
                                               __half* __restrict__ dstf,
                                               int total4)
{
    int i = blockIdx.x * 256 + threadIdx.x;
    if (i >= total4) return;
    int row = i >> 10;
    int c4  = (i & 1023) << 2;
    float4 v = ((const float4*)src)[i];
    float in[4] = {v.x, v.y, v.z, v.w};
    __nv_bfloat16 h[4], l[4];
    __half f[4], fs[4];
#pragma unroll
    for (int j = 0; j < 4; ++j) {
        split2(in[j], h[j], l[j]);
        f[j]  = __float2half_rn(in[j]);
        fs[j] = __float2half_rn(in[j] * SC10);
    }
    size_t b = (size_t)row * KST2 + c4;
    *(uint2*)(dstb + b)        = make_uint2(pkb(h[0], h[1]), pkb(h[2], h[3]));
    *(uint2*)(dstb + b + KSEG) = make_uint2(pkb(l[0], l[1]), pkb(l[2], l[3]));
    *(uint2*)(dstf + b)        = make_uint2(pkh(f[0], f[1]), pkh(f[2], f[3]));
    *(uint2*)(dstf + b + KSEG) = make_uint2(pkh(fs[0], fs[1]), pkh(fs[2], fs[3]));
}

__global__ void __launch_bounds__(256) split_hilo(const float* __restrict__ src,
                                                  __nv_bfloat16* __restrict__ dst,
                                                  int total4)
{
    int i = blockIdx.x * 256 + threadIdx.x;
    if (i >= total4) return;
    int row = i >> 10;
    int c4  = (i & 1023) << 2;
    float4 v = ((const float4*)src)[i];
    float in[4] = {v.x, v.y, v.z, v.w};
    __nv_bfloat16 h[4], l[4];
#pragma unroll
    for (int j = 0; j < 4; ++j) split2(in[j], h[j], l[j]);
    size_t b = (size_t)row * KST2 + c4;
    *(uint2*)(dst + b)        = make_uint2(pkb(h[0], h[1]), pkb(h[2], h[3]));
    *(uint2*)(dst + b + KSEG) = make_uint2(pkb(l[0], l[1]), pkb(l[2], l[3]));
}

__global__ void __launch_bounds__(256) split_wf16(const float* __restrict__ src,
                                                  __half* __restrict__ dst,
                                                  int total4)
{
    int i = blockIdx.x * 256 + threadIdx.x;
    if (i >= total4) return;
    int row = i >> 10;
    int c4  = (i & 1023) << 2;
    float4 v = ((const float4*)src)[i];
    float in[4] = {v.x, v.y, v.z, v.w};
    __half h[4], l[4];
#pragma unroll
    for (int j = 0; j < 4; ++j) {
        h[j] = __float2half_rn(in[j]);
        l[j] = __float2half_rn((in[j] - __half2float(h[j])) * 1024.0f);
    }
    size_t b = (size_t)row * KST2 + c4;
    *(uint2*)(dst + b)        = make_uint2(pkh(h[0], h[1]), pkh(h[2], h[3]));
    *(uint2*)(dst + b + KSEG) = make_uint2(pkh(l[0], l[1]), pkh(l[2], l[3]));
}

// ===========================================================================
// GEMM common: CTA 128x128, BK=32, 128 threads (2x2 warps, 64x64/warp),
// 4-stage cp.async, 2 CTAs/SM.
// ===========================================================================
#define BM 128
#define BN 128
#define BK 32
#define NITER   384
#define NITERF  256
#define GSTAGES 4
#define ROWB    80
#define ASZ     (BM * ROWB)
#define STAGE   (2 * ASZ)
#define GSMEM   (GSTAGES * STAGE)

__device__ __forceinline__ void g_load_stage(uint32_t sb,
                                             const __nv_bfloat16* __restrict__ A2,
                                             const __nv_bfloat16* __restrict__ B2,
                                             int m0, int n0, int j, int t)
{
    const int seg  = j >> 7;
    const int kloc = (j & 127) * BK;
    const int aoff = (seg == 2) ? KSEG : 0;
    const int boff = (seg == 1) ? KSEG : 0;
#pragma unroll
    for (int i = 0; i < 4; ++i) {
        int c   = t + (i << 7);
        int row = c >> 2;
        int kc  = c & 3;
        cp_async16(sb + row * ROWB + kc * 16,
                   A2 + (size_t)(m0 + row) * KST2 + aoff + kloc + kc * 8);
    }
#pragma unroll
    for (int i = 0; i < 4; ++i) {
        int c   = t + (i << 7);
        int row = c >> 2;
        int kc  = c & 3;
        cp_async16(sb + ASZ + row * ROWB + kc * 16,
                   B2 + (size_t)(n0 + row) * KST2 + boff + kloc + kc * 8);
    }
    cp_commit();
}

__device__ __forceinline__ void g_load_stage_f(uint32_t sb,
                                               const __half* __restrict__ A2,
                                               const __half* __restrict__ B2,
                                               int m0, int n0, int j, int t)
{
    const int off  = (j >> 7) ? KSEG : 0;
    const int kloc = (j & 127) * BK;
#pragma unroll
    for (int i = 0; i < 4; ++i) {
        int c   = t + (i << 7);
        int row = c >> 2;
        int kc  = c & 3;
        cp_async16(sb + row * ROWB + kc * 16,
                   A2 + (size_t)(m0 + row) * KST2 + off + kloc + kc * 8);
    }
#pragma unroll
    for (int i = 0; i < 4; ++i) {
        int c   = t + (i << 7);
        int row = c >> 2;
        int kc  = c & 3;
        cp_async16(sb + ASZ + row * ROWB + kc * 16,
                   B2 + (size_t)(n0 + row) * KST2 + off + kloc + kc * 8);
    }
    cp_commit();
}

// Shared mainloop body (bf16): accumulates into acc[4][8][4]
#define GEMM_BODY(LOADFN, MMAFN, NITERS, APTR, BPTR)                          \
    float acc[4][8][4];                                                       \
    _Pragma("unroll")                                                         \
    for (int mi = 0; mi < 4; ++mi)                                            \
        _Pragma("unroll")                                                     \
        for (int nj = 0; nj < 8; ++nj)                                        \
            _Pragma("unroll")                                                 \
            for (int q = 0; q < 4; ++q) acc[mi][nj][q] = 0.0f;                \
    _Pragma("unroll")                                                         \
    for (int it = 0; it < GSTAGES - 1; ++it)                                  \
        LOADFN(base + it * STAGE, APTR, BPTR, m0, n0, it, t);                 \
    for (int it = 0; it < NITERS; ++it) {                                     \
        const int st = it & (GSTAGES - 1);                                    \
        cp_wait<GSTAGES - 2>();                                               \
        __syncthreads();                                                      \
        const uint32_t stA = base + st * STAGE;                               \
        const uint32_t stB = stA + ASZ;                                       \
        _Pragma("unroll")                                                     \
        for (int kh = 0; kh < 2; ++kh) {                                      \
            uint32_t a[4][4];                                                 \
            _Pragma("unroll")                                                 \
            for (int mi = 0; mi < 4; ++mi)                                    \
                ldsm_x4(a[mi][0], a[mi][1], a[mi][2], a[mi][3],               \
                        stA + (uint32_t)((wm + mi * 16 + rA) * ROWB           \
                                         + (kh * 2 + selA) * 16));            \
            uint32_t b[4][4];                                                 \
            _Pragma("unroll")                                                 \
            for (int p = 0; p < 4; ++p)                                       \
                ldsm_x4(b[p][0], b[p][1], b[p][2], b[p][3],                   \
                        stB + (uint32_t)((wn + p * 16 + rB) * ROWB            \
                                         + (kh * 2 + selB) * 16));            \
            _Pragma("unroll")                                                 \
            for (int mi = 0; mi < 4; ++mi) {                                  \
                _Pragma("unroll")                                             \
                for (int p = 0; p < 4; ++p) {                                 \
                    MMAFN(acc[mi][2 * p],     a[mi], &b[p][0]);               \
                    MMAFN(acc[mi][2 * p + 1], a[mi], &b[p][2]);               \
                }                                                             \
            }                                                                 \
        }                                                                     \
        const int j = it + GSTAGES - 1;                                       \
        if (j < NITERS)                                                       \
            LOADFN(base + (j & (GSTAGES - 1)) * STAGE, APTR, BPTR, m0, n0, j, t); \
    }

#define GEMM_PROLOG                                                           \
    extern __shared__ char smraw[];                                           \
    const uint32_t base = smem_u32(smraw);                                    \
    const int t    = threadIdx.x;                                             \
    const int wid  = t >> 5;                                                  \
    const int lane = t & 31;                                                  \
    const int m0   = blockIdx.y * BM;                                         \
    const int n0   = blockIdx.x * BN;                                         \
    const int wm   = (wid >> 1) * 64;                                         \
    const int wn   = (wid & 1) * 64;                                          \
    const int rA   = lane & 15;                                               \
    const int selA = lane >> 4;                                               \
    const int rB   = ((lane >> 4) << 3) | (lane & 7);                         \
    const int selB = (lane >> 3) & 1;

__global__ void __launch_bounds__(128, 2)
gemm_mma(const __nv_bfloat16* __restrict__ A2,
         const __nv_bfloat16* __restrict__ B2,
         float* __restrict__ C)
{
    GEMM_PROLOG
    GEMM_BODY(g_load_stage, mma16816, NITER, A2, B2)

    const int er = lane >> 2;
    const int ec = (lane & 3) << 1;
#pragma unroll
    for (int mi = 0; mi < 4; ++mi) {
#pragma unroll
        for (int nj = 0; nj < 8; ++nj) {
            size_t r0 = (size_t)(m0 + wm + mi * 16 + er) * HDIM
                        + (n0 + wn + nj * 8 + ec);
            *(float2*)&C[r0]            = make_float2(acc[mi][nj][0], acc[mi][nj][1]);
            *(float2*)&C[r0 + 8 * HDIM] = make_float2(acc[mi][nj][2], acc[mi][nj][3]);
        }
    }
}

// fp16 GEMM, fp32 output (O projection)
__global__ void __launch_bounds__(128, 2)
gemm_f16(const __half* __restrict__ A2,
         const __half* __restrict__ B2,
         float* __restrict__ C)
{
    GEMM_PROLOG
    GEMM_BODY(g_load_stage_f, mma16816f, NITERF, A2, B2)

    const int er = lane >> 2;
    const int ec = (lane & 3) << 1;
#pragma unroll
    for (int mi = 0; mi < 4; ++mi) {
#pragma unroll
        for (int nj = 0; nj < 8; ++nj) {
            size_t r0 = (size_t)(m0 + wm + mi * 16 + er) * HDIM
                        + (n0 + wn + nj * 8 + ec);
            *(float2*)&C[r0]            = make_float2(acc[mi][nj][0], acc[mi][nj][1]);
            *(float2*)&C[r0 + 8 * HDIM] = make_float2(acc[mi][nj][2], acc[mi][nj][3]);
        }
    }
}

// fp16 GEMM, fused V epilogue: writes split bf16 g_Vb [h][s][Vh|Vl]
__global__ void __launch_bounds__(128, 2)
gemm_f16v(const __half* __restrict__ A2,
          const __half* __restrict__ B2,
          __nv_bfloat16* __restrict__ Vb)
{
    GEMM_PROLOG
    GEMM_BODY(g_load_stage_f, mma16816f, NITERF, A2, B2)

    const int er = lane >> 2;
    const int ec = (lane & 3) << 1;
#pragma unroll
    for (int mi = 0; mi < 4; ++mi) {
        int s0 = m0 + wm + mi * 16 + er;
#pragma unroll
        for (int nj = 0; nj < 8; ++nj) {
            int col = n0 + wn + nj * 8 + ec;
            int h   = col >> 7;
            int hc  = col & 127;
            size_t b0 = ((size_t)h * S_LEN + s0) * HD2 + hc;
            size_t b1 = ((size_t)h * S_LEN + s0 + 8) * HD2 + hc;
            __nv_bfloat16 h0, l0, h1, l1;
            split2(acc[mi][nj][0], h0, l0); split2(acc[mi][nj][1], h1, l1);
            *(uint32_t*)(Vb + b0)       = pkb(h0, h1);
            *(uint32_t*)(Vb + b0 + 128) = pkb(l0, l1);
            split2(acc[mi][nj][2], h0, l0); split2(acc[mi][nj][3], h1, l1);
            *(uint32_t*)(Vb + b1)       = pkb(h0, h1);
            *(uint32_t*)(Vb + b1 + 128) = pkb(l0, l1);
        }
    }
}

// ===========================================================================
// Fused RoPE + head-dim split (validated)
// ===========================================================================
#define ATT_SCALE 0.08838834764831843f

__global__ void __launch_bounds__(256) rope_split_qk(
    const float* __restrict__ Q, const float* __restrict__ K,
    const int* __restrict__ pos,
    __nv_bfloat16* __restrict__ Q2, __nv_bfloat16* __restrict__ K2o)
{
    int idx = blockIdx.x * 256 + threadIdx.x;
    if (idx >= S_LEN * NHEADS * 16) return;
    int j4 = (idx & 15) << 2;
    int h  = (idx >> 4) & (NHEADS - 1);
    int s  = idx >> 9;
    int p  = pos[s];

    float sn[4], cs[4];
#pragma unroll
    for (int i = 0; i < 4; ++i) {
        float inv = 1.0f / powf(10000.0f, (float)(j4 + i) * (1.0f / 64.0f));
        sincosf((float)p * inv, &sn[i], &cs[i]);
    }

    size_t gb = (size_t)s * HDIM + (size_t)h * HEADD + j4;
    float4 qa4 = *(const float4*)&Q[gb];
    float4 qb4 = *(const float4*)&Q[gb + 64];
    float4 ka4 = *(const float4*)&K[gb];
    float4 kb4 = *(const float4*)&K[gb + 64];
    float qa[4] = {qa4.x, qa4.y, qa4.z, qa4.w};
    float qb[4] = {qb4.x, qb4.y, qb4.z, qb4.w};
    float ka[4] = {ka4.x, ka4.y, ka4.z, ka4.w};
    float kb[4] = {kb4.x, kb4.y, kb4.z, kb4.w};

    __nv_bfloat16 qah[4], qal[4], qbh[4], qbl[4];
    __nv_bfloat16 kah[4], kal[4], kbh[4], kbl[4];
#pragma unroll
    for (int i = 0; i < 4; ++i) {
        float r1 = (qa[i] * cs[i] - qb[i] * sn[i]) * ATT_SCALE;
        float r2 = (qb[i] * cs[i] + qa[i] * sn[i]) * ATT_SCALE;
        split2(r1, qah[i], qal[i]);
        split2(r2, qbh[i], qbl[i]);
        float t1 = ka[i] * cs[i] - kb[i] * sn[i];
        float t2 = kb[i] * cs[i] + ka[i] * sn[i];
        split2(t1, kah[i], kal[i]);
        split2(t2, kbh[i], kbl[i]);
    }

    size_t ob = ((size_t)h * S_LEN + s) * HD2 + j4;
    *(uint2*)(Q2 + ob)       = make_uint2(pkb(qah[0], qah[1]), pkb(qah[2], qah[3]));
    *(uint2*)(Q2 + ob + 64)  = make_uint2(pkb(qbh[0], qbh[1]), pkb(qbh[2], qbh[3]));
    *(uint2*)(Q2 + ob + 128) = make_uint2(pkb(qal[0], qal[1]), pkb(qal[2], qal[3]));
    *(uint2*)(Q2 + ob + 192) = make_uint2(pkb(qbl[0], qbl[1]), pkb(qbl[2], qbl[3]));

    *(uint2*)(K2o + ob)       = make_uint2(pkb(kah[0], kah[1]), pkb(kah[2], kah[3]));
    *(uint2*)(K2o + ob + 64)  = make_uint2(pkb(kbh[0], kbh[1]), pkb(kbh[2], kbh[3]));
    *(uint2*)(K2o + ob + 128) = make_uint2(pkb(kal[0], kal[1]), pkb(kal[2], kal[3]));
    *(uint2*)(K2o + ob + 192) = make_uint2(pkb(kbl[0], kbl[1]), pkb(kbl[2], kbl[3]));
}

// ===========================================================================
// Flash attention v4: 128 threads / 4 warps (2x2). Crossbar redundancy halved.
// Scores 3-pass split, fp32 softmax, PV 3-pass split. K/V double-buffered.
// ===========================================================================
#define NEG_BIG (-3.0e38f)
#define FROW2  528
#define FROWP  272
#define OFF_K2S  (64 * FROW2)
#define OFF_VS   (OFF_K2S + 2 * 64 * FROW2)
#define OFF_SS   (OFF_VS + 2 * 64 * FROW2)
#define OFF_PS   (OFF_SS + 64 * 68 * 4)
#define OFF_RW   (OFF_PS + 64 * FROWP)
#define FSMEM    (OFF_RW + 3 * 64 * 4)

__device__ __forceinline__ void f_load_kv(uint32_t sb, int buf,
                                          const __nv_bfloat16* __restrict__ K2g,
                                          const __nv_bfloat16* __restrict__ Vg,
                                          int t)
{
    uint32_t kb = sb + OFF_K2S + buf * (64 * FROW2);
    for (int c = t; c < 64 * 32; c += 128) {
        int r = c >> 5, ch = c & 31;
        cp_async16(kb + r * FROW2 + ch * 16,
                   (const char*)K2g + (size_t)r * (HD2 * 2) + ch * 16);
    }
    uint32_t vb = sb + OFF_VS + buf * (64 * FROW2);
    for (int c = t; c < 64 * 32; c += 128) {
        int r = c >> 5, ch = c & 31;
        cp_async16(vb + r * FROW2 + ch * 16,
                   (const char*)Vg + (size_t)r * (HD2 * 2) + ch * 16);
    }
    cp_commit();
}

__global__ void __launch_bounds__(128) flash3(
    const __nv_bfloat16* __restrict__ Q2,
    const __nv_bfloat16* __restrict__ K2g,
    const __nv_bfloat16* __restrict__ Vb,
    __half* __restrict__ A2out)
{
    extern __shared__ char smraw[];
    const uint32_t sb = smem_u32(smraw);
    float* Ss  = (float*)(smraw + OFF_SS);
    __nv_bfloat16* Ps = (__nv_bfloat16*)(smraw + OFF_PS);
    float* mrow = (float*)(smraw + OFF_RW);
    float* lrow = mrow + 64;
    float* srow = lrow + 64;

    const int h  = blockIdx.x;
    const int qb = (gridDim.y - 1) - blockIdx.y;
    const int q0 = qb * 64;
    const int t = threadIdx.x, wid = t >> 5, lane = t & 31;
    const int wm  = (wid >> 1) * 32;    // 2x2 warps: 32 q-rows each
    const int wn  = (wid & 1) * 32;     // score cols: 2 x 32
    const int wnv = (wid & 1) * 64;     // PV cols: 2 x 64
    const int rA = lane & 15, selA = lane >> 4;
    const int rB = ((lane >> 4) << 3) | (lane & 7), selB = (lane >> 3) & 1;
    const int er = lane >> 2, ec = (lane & 3) << 1;

    const __nv_bfloat16* Qg = Q2 + ((size_t)h * S_LEN + q0) * HD2;
    for (int c = t; c < 64 * 32; c += 128) {
        int r = c >> 5, ch = c & 31;
        cp_async16(sb + r * FROW2 + ch * 16,
                   (const char*)Qg + (size_t)r * (HD2 * 2) + ch * 16);
    }
    cp_commit();
    if (t < 64) { mrow[t] = NEG_BIG; lrow[t] = 0.0f; }

    f_load_kv(sb, 0, K2g + ((size_t)h * S_LEN) * HD2,
              Vb + ((size_t)h * S_LEN) * HD2, t);

    float oacc[2][8][4];
#pragma unroll
    for (int mi = 0; mi < 2; ++mi)
#pragma unroll
        for (int nj = 0; nj < 8; ++nj)
#pragma unroll
            for (int q = 0; q < 4; ++q) oacc[mi][nj][q] = 0.0f;

    for (int kb = 0; kb <= qb; ++kb) {
        const int buf = kb & 1;
        cp_wait<0>();
        __syncthreads();

        if (kb + 1 <= qb)
            f_load_kv(sb, buf ^ 1,
                      K2g + ((size_t)h * S_LEN + (kb + 1) * 64) * HD2,
                      Vb + ((size_t)h * S_LEN + (kb + 1) * 64) * HD2, t);

        const uint32_t kbase = sb + OFF_K2S + buf * (64 * FROW2);
        const uint32_t vbase = sb + OFF_VS + buf * (64 * FROW2);

        // ---- scores: warp tile 32x32, 3 passes x 8 k16 ----
        float sacc[2][4][4];
#pragma unroll
        for (int mi = 0; mi < 2; ++mi)
#pragma unroll
            for (int nj = 0; nj < 4; ++nj)
#pragma unroll
                for (int q = 0; q < 4; ++q) sacc[mi][nj][q] = 0.0f;

        const uint32_t sAoff[3] = {0u, 0u, 256u};
        const uint32_t sBoff[3] = {0u, 256u, 0u};
#pragma unroll
        for (int ps = 0; ps < 3; ++ps) {
#pragma unroll
            for (int k16 = 0; k16 < 8; ++k16) {
                uint32_t a[2][4], b[2][4];
#pragma unroll
                for (int mi = 0; mi < 2; ++mi)
                    ldsm_x4(a[mi][0], a[mi][1], a[mi][2], a[mi][3],
                            sb + (uint32_t)((wm + mi * 16 + rA) * FROW2)
                               + sAoff[ps] + k16 * 32 + selA * 16);
#pragma unroll
                for (int p = 0; p < 2; ++p)
                    ldsm_x4(b[p][0], b[p][1], b[p][2], b[p][3],
                            kbase + (uint32_t)((wn + p * 16 + rB) * FROW2)
                                  + sBoff[ps] + k16 * 32 + selB * 16);
#pragma unroll
                for (int mi = 0; mi < 2; ++mi)
#pragma unroll
                    for (int p = 0; p < 2; ++p) {
                        mma16816(sacc[mi][2 * p],     a[mi], &b[p][0]);
                        mma16816(sacc[mi][2 * p + 1], a[mi], &b[p][2]);
                    }
            }
        }

        const bool diag = (kb == qb);
#pragma unroll
        for (int mi = 0; mi < 2; ++mi) {
#pragma unroll
            for (int nj = 0; nj < 4; ++nj) {
                int row = wm + mi * 16 + er;
                int col = wn + nj * 8 + ec;
                float v0 = sacc[mi][nj][0], v1 = sacc[mi][nj][1];
                float v2 = sacc[mi][nj][2], v3 = sacc[mi][nj][3];
                if (diag) {
                    if (col > row)     v0 = NEG_BIG;
                    if (col + 1 > row) v1 = NEG_BIG;
                    if (col > row + 8)     v2 = NEG_BIG;
                    if (col + 1 > row + 8) v3 = NEG_BIG;
                }
                Ss[row * 68 + col]       = v0;
                Ss[row * 68 + col + 1]   = v1;
                Ss[(row + 8) * 68 + col]     = v2;
                Ss[(row + 8) * 68 + col + 1] = v3;
            }
        }
        __syncthreads();

        // ---- online softmax: 2 threads/row, 32 cols each ----
        {
            int r  = t >> 1;
            int qd = t & 1;
            float* srw = &Ss[r * 68 + qd * 32];
            __nv_bfloat16* prw = &Ps[r * 136 + qd * 32];
            float vals[32];
            float mx = NEG_BIG;
#pragma unroll
            for (int i = 0; i < 32; ++i) { vals[i] = srw[i]; mx = fmaxf(mx, vals[i]); }
            mx = fmaxf(mx, __shfl_xor_sync(0xffffffffu, mx, 1));
            float mold = mrow[r];
            float mnew = fmaxf(mold, mx);
            float sum = 0.0f;
#pragma unroll
            for (int i = 0; i < 32; ++i) {
                float p = __expf(vals[i] - mnew);
                __nv_bfloat16 ph, pl;
                split2(p, ph, pl);
                prw[i]      = ph;
                prw[i + 64] = pl;
                sum += p;
            }
            sum += __shfl_xor_sync(0xffffffffu, sum, 1);
            float corr = __expf(mold - mnew);
            if (qd == 0) {
                mrow[r] = mnew;
                lrow[r] = lrow[r] * corr + sum;
                srow[r] = corr;
            }
        }
        __syncthreads();

        // ---- rescale + PV: warp tile 32x64, 3 passes x 4 kk ----
#pragma unroll
        for (int mi = 0; mi < 2; ++mi) {
            float c0 = srow[wm + mi * 16 + er];
            float c1 = srow[wm + mi * 16 + er + 8];
#pragma unroll
            for (int nj = 0; nj < 8; ++nj) {
                oacc[mi][nj][0] *= c0; oacc[mi][nj][1] *= c0;
                oacc[mi][nj][2] *= c1; oacc[mi][nj][3] *= c1;
            }
        }

        const int vkr = ((lane >> 3) & 1) * 8 + (lane & 7);
        const int vnc = (lane >> 4) * 8;
        const uint32_t pAoff[3] = {0u, 0u, 128u};
        const uint32_t pVoff[3] = {0u, 256u, 0u};
#pragma unroll
        for (int ps = 0; ps < 3; ++ps) {
#pragma unroll
            for (int kk = 0; kk < 4; ++kk) {
                uint32_t a[2][4], bq[4][4];
#pragma unroll
                for (int mi = 0; mi < 2; ++mi)
                    ldsm_x4(a[mi][0], a[mi][1], a[mi][2], a[mi][3],
                            sb + OFF_PS + (uint32_t)((wm + mi * 16 + rA) * FROWP)
                               + pAoff[ps] + kk * 32 + selA * 16);
                uint32_t vaddr = vbase + (uint32_t)((kk * 16 + vkr) * FROW2)
                               + pVoff[ps];
#pragma unroll
                for (int q16 = 0; q16 < 4; ++q16)
                    ldsm_x4t(bq[q16][0], bq[q16][1], bq[q16][2], bq[q16][3],
                             vaddr + (wnv + q16 * 16 + vnc) * 2);
#pragma unroll
                for (int mi = 0; mi < 2; ++mi)
#pragma unroll
                    for (int q16 = 0; q16 < 4; ++q16) {
                        mma16816(oacc[mi][2 * q16],     a[mi], &bq[q16][0]);
                        mma16816(oacc[mi][2 * q16 + 1], a[mi], &bq[q16][2]);
                    }
            }
        }
    }

    // epilogue: normalize, write fp16 [xh | xh*2^-10] into A2f
#pragma unroll
    for (int mi = 0; mi < 2; ++mi) {
        float l0 = 1.0f / lrow[wm + mi * 16 + er];
        float l1 = 1.0f / lrow[wm + mi * 16 + er + 8];
#pragma unroll
        for (int nj = 0; nj < 8; ++nj) {
            int col = h * HEADD + wnv + nj * 8 + ec;
            size_t r0 = (size_t)(q0 + wm + mi * 16 + er) * KST2 + col;
            size_t r1 = r0 + (size_t)8 * KST2;
            float x0 = oacc[mi][nj][0] * l0, x1 = oacc[mi][nj][1] * l0;
            float y0 = oacc[mi][nj][2] * l1, y1 = oacc[mi][nj][3] * l1;
            *(uint32_t*)(A2out + r0) =
                pkh(__float2half_rn(x0), __float2half_rn(x1));
            *(uint32_t*)(A2out + r0 + KSEG) =
                pkh(__float2half_rn(x0 * SC10), __float2half_rn(x1 * SC10));
            *(uint32_t*)(A2out + r1) =
                pkh(__float2half_rn(y0), __float2half_rn(y1));
            *(uint32_t*)(A2out + r1 + KSEG) =
                pkh(__float2half_rn(y0 * SC10), __float2half_rn(y1 * SC10));
        }
    }
}

// ===========================================================================
// Launch
// ===========================================================================
extern "C" void kernel_launch(void* const* d_in, const int* in_sizes, int n_in,
                              void* d_out, int out_size)
{
    (void)in_sizes; (void)n_in; (void)out_size;

    const float* X   = (const float*)d_in[0];
    const int*   pos = (const int*)d_in[2];
    const float* Wq  = (const float*)d_in[3];
    const float* Wk  = (const float*)d_in[4];
    const float* Wv  = (const float*)d_in[5];
    const float* Wo  = (const float*)d_in[6];
    float* out = (float*)d_out;

    float *Qd, *Kd;
    __nv_bfloat16 *A2d, *W2qd, *W2kd, *Q2d, *K2d, *Vbd;
    __half *A2fd, *W2vfd, *W2ofd;
    cudaGetSymbolAddress((void**)&Qd, g_Q);
    cudaGetSymbolAddress((void**)&Kd, g_K);
    cudaGetSymbolAddress((void**)&A2d, g_A2);
    cudaGetSymbolAddress((void**)&A2fd, g_A2f);
    cudaGetSymbolAddress((void**)&W2qd, g_W2q);
    cudaGetSymbolAddress((void**)&W2kd, g_W2k);
    cudaGetSymbolAddress((void**)&W2vfd, g_W2vf);
    cudaGetSymbolAddress((void**)&W2ofd, g_W2of);
    cudaGetSymbolAddress((void**)&Q2d, g_Q2);
    cudaGetSymbolAddress((void**)&K2d, g_K2a);
    cudaGetSymbolAddress((void**)&Vbd, g_Vb);

    cudaFuncSetAttribute(gemm_mma, cudaFuncAttributeMaxDynamicSharedMemorySize, GSMEM);
    cudaFuncSetAttribute(gemm_f16, cudaFuncAttributeMaxDynamicSharedMemorySize, GSMEM);
    cudaFuncSetAttribute(gemm_f16v, cudaFuncAttributeMaxDynamicSharedMemorySize, GSMEM);
    cudaFuncSetAttribute(flash3, cudaFuncAttributeMaxDynamicSharedMemorySize, FSMEM);

    split_x<<<(S_LEN * 1024) / 256, 256>>>(X, A2d, A2fd, S_LEN * 1024);
    split_hilo<<<(HDIM * 1024) / 256, 256>>>(Wq, W2qd, HDIM * 1024);
    split_hilo<<<(HDIM * 1024) / 256, 256>>>(Wk, W2kd, HDIM * 1024);
    split_wf16<<<(HDIM * 1024) / 256, 256>>>(Wv, W2vfd, HDIM * 1024);
    split_wf16<<<(HDIM * 1024) / 256, 256>>>(Wo, W2ofd, HDIM * 1024);

    dim3 ggrid(HDIM / BN, S_LEN / BM);

    gemm_mma<<<ggrid, 128, GSMEM>>>(A2d, W2qd, Qd);
    gemm_mma<<<ggrid, 128, GSMEM>>>(A2d, W2kd, Kd);
    gemm_f16v<<<ggrid, 128, GSMEM>>>(A2fd, W2vfd, Vbd);   // fused V split

    rope_split_qk<<<(S_LEN * NHEADS * 16) / 256, 256>>>(Qd, Kd, pos, Q2d, K2d);

    flash3<<<dim3(NHEADS, S_LEN / 64), 128, FSMEM>>>(Q2d, K2d, Vbd, A2fd);

    gemm_f16<<<ggrid, 128, GSMEM>>>(A2fd, W2ofd, out);
}

// round 12
// speedup vs baseline: 1.0585x; 1.0585x over previous
#include <cuda_runtime.h>
#include <cuda_bf16.h>
#include <cuda_fp16.h>
#include <math.h>
#include <stdint.h>

// Problem constants
#define S_LEN  2048
#define HDIM   4096
#define NHEADS 32
#define HEADD  128
#define HD2    256      // Q/K head-dim split storage: [hi(128) | lo(128)]

#define KSEG   4096
#define KST2   8192
#define SC10   0.0009765625f   // 2^-10

// Scratch (device globals)
__device__ float g_Q[S_LEN * HDIM];
__device__ float g_K[S_LEN * HDIM];
__device__ __nv_bfloat16 g_A2[S_LEN * KST2];           // X bf16 [hi|lo]
__device__ __half        g_A2f[S_LEN * KST2];          // X fp16 pair / attn out
__device__ __nv_bfloat16 g_W2q[HDIM * KST2];
__device__ __nv_bfloat16 g_W2k[HDIM * KST2];
__device__ __half        g_W2vf[HDIM * KST2];
__device__ __half        g_W2of[HDIM * KST2];
__device__ __nv_bfloat16 g_Q2[NHEADS * S_LEN * HD2];   // [h][s][Qh|Ql]
__device__ __nv_bfloat16 g_K2a[NHEADS * S_LEN * HD2];  // [h][s][Kh|Kl]
__device__ __half        g_Vf[NHEADS * S_LEN * HEADD]; // [h][s][128] fp16

// ===========================================================================
// PTX helpers
// ===========================================================================
__device__ __forceinline__ uint32_t smem_u32(const void* p) {
    uint32_t a;
    asm("{ .reg .u64 t; cvta.to.shared.u64 t, %1; cvt.u32.u64 %0, t; }" : "=r"(a) : "l"(p));
    return a;
}
__device__ __forceinline__ void cp_async16(uint32_t dst, const void* src) {
    asm volatile("cp.async.cg.shared.global [%0], [%1], 16;" :: "r"(dst), "l"(src));
}
__device__ __forceinline__ void cp_commit() {
    asm volatile("cp.async.commit_group;" ::: "memory");
}
template <int N> __device__ __forceinline__ void cp_wait() {
    asm volatile("cp.async.wait_group %0;" :: "n"(N) : "memory");
}
__device__ __forceinline__ void ldsm_x4(uint32_t& r0, uint32_t& r1, uint32_t& r2,
                                        uint32_t& r3, uint32_t addr) {
    asm volatile("ldmatrix.sync.aligned.m8n8.x4.shared.b16 {%0,%1,%2,%3}, [%4];"
                 : "=r"(r0), "=r"(r1), "=r"(r2), "=r"(r3) : "r"(addr));
}
__device__ __forceinline__ void ldsm_x4t(uint32_t& r0, uint32_t& r1, uint32_t& r2,
                                         uint32_t& r3, uint32_t addr) {
    asm volatile("ldmatrix.sync.aligned.m8n8.x4.trans.shared.b16 {%0,%1,%2,%3}, [%4];"
                 : "=r"(r0), "=r"(r1), "=r"(r2), "=r"(r3) : "r"(addr));
}
__device__ __forceinline__ void mma16816(float* c, const uint32_t* a, const uint32_t* b) {
    asm volatile(
        "mma.sync.aligned.m16n8k16.row.col.f32.bf16.bf16.f32 "
        "{%0,%1,%2,%3}, {%4,%5,%6,%7}, {%8,%9}, {%0,%1,%2,%3};"
        : "+f"(c[0]), "+f"(c[1]), "+f"(c[2]), "+f"(c[3])
        : "r"(a[0]), "r"(a[1]), "r"(a[2]), "r"(a[3]), "r"(b[0]), "r"(b[1]));
}
__device__ __forceinline__ void mma16816f(float* c, const uint32_t* a, const uint32_t* b) {
    asm volatile(
        "mma.sync.aligned.m16n8k16.row.col.f32.f16.f16.f32 "
        "{%0,%1,%2,%3}, {%4,%5,%6,%7}, {%8,%9}, {%0,%1,%2,%3};"
        : "+f"(c[0]), "+f"(c[1]), "+f"(c[2]), "+f"(c[3])
        : "r"(a[0]), "r"(a[1]), "r"(a[2]), "r"(a[3]), "r"(b[0]), "r"(b[1]));
}

__device__ __forceinline__ uint32_t pkb(__nv_bfloat16 a, __nv_bfloat16 b) {
    __nv_bfloat162 t = __halves2bfloat162(a, b);
    return *reinterpret_cast<uint32_t*>(&t);
}
__device__ __forceinline__ uint32_t pkh(__half a, __half b) {
    __half2 t = __halves2half2(a, b);
    return *reinterpret_cast<uint32_t*>(&t);
}
__device__ __forceinline__ void split2(float x, __nv_bfloat16& h, __nv_bfloat16& l) {
    h = __float2bfloat16_rn(x);
    l = __float2bfloat16_rn(x - __bfloat162float(h));
}

// ===========================================================================
// Split kernels
// ===========================================================================
__global__ void __launch_bounds__(256) split_x(const float* __restrict__ src,
                                               __nv_bfloat16* __restrict__ dstb,
                                               __half* __restrict__ dstf,
                                               int total4)
{
    int i = blockIdx.x * 256 + threadIdx.x;
    if (i >= total4) return;
    int row = i >> 10;
    int c4  = (i & 1023) << 2;
    float4 v = ((const float4*)src)[i];
    float in[4] = {v.x, v.y, v.z, v.w};
    __nv_bfloat16 h[4], l[4];
    __half f[4], fs[4];
#pragma unroll
    for (int j = 0; j < 4; ++j) {
        split2(in[j], h[j], l[j]);
        f[j]  = __float2half_rn(in[j]);
        fs[j] = __float2half_rn(in[j] * SC10);
    }
    size_t b = (size_t)row * KST2 + c4;
    *(uint2*)(dstb + b)        = make_uint2(pkb(h[0], h[1]), pkb(h[2], h[3]));
    *(uint2*)(dstb + b + KSEG) = make_uint2(pkb(l[0], l[1]), pkb(l[2], l[3]));
    *(uint2*)(dstf + b)        = make_uint2(pkh(f[0], f[1]), pkh(f[2], f[3]));
    *(uint2*)(dstf + b + KSEG) = make_uint2(pkh(fs[0], fs[1]), pkh(fs[2], fs[3]));
}

__global__ void __launch_bounds__(256) split_hilo(const float* __restrict__ src,
                                                  __nv_bfloat16* __restrict__ dst,
                                                  int total4)
{
    int i = blockIdx.x * 256 + threadIdx.x;
    if (i >= total4) return;
    int row = i >> 10;
    int c4  = (i & 1023) << 2;
    float4 v = ((const float4*)src)[i];
    float in[4] = {v.x, v.y, v.z, v.w};
    __nv_bfloat16 h[4], l[4];
#pragma unroll
    for (int j = 0; j < 4; ++j) split2(in[j], h[j], l[j]);
    size_t b = (size_t)row * KST2 + c4;
    *(uint2*)(dst + b)        = make_uint2(pkb(h[0], h[1]), pkb(h[2], h[3]));
    *(uint2*)(dst + b + KSEG) = make_uint2(pkb(l[0], l[1]), pkb(l[2], l[3]));
}

__global__ void __launch_bounds__(256) split_wf16(const float* __restrict__ src,
                                                  __half* __restrict__ dst,
                                                  int total4)
{
    int i = blockIdx.x * 256 + threadIdx.x;
    if (i >= total4) return;
    int row = i >> 10;
    int c4  = (i & 1023) << 2;
    float4 v = ((const float4*)src)[i];
    float in[4] = {v.x, v.y, v.z, v.w};
    __half h[4], l[4];
#pragma unroll
    for (int j = 0; j < 4; ++j) {
        h[j] = __float2half_rn(in[j]);
        l[j] = __float2half_rn((in[j] - __half2float(h[j])) * 1024.0f);
    }
    size_t b = (size_t)row * KST2 + c4;
    *(uint2*)(dst + b)        = make_uint2(pkh(h[0], h[1]), pkh(h[2], h[3]));
    *(uint2*)(dst + b + KSEG) = make_uint2(pkh(l[0], l[1]), pkh(l[2], l[3]));
}

// ===========================================================================
// GEMM common: CTA 128x128, BK=32, 128 threads (2x2 warps, 64x64/warp),
// 4-stage cp.async, 2 CTAs/SM.
// ===========================================================================
#define BM 128
#define BN 128
#define BK 32
#define NITER   384
#define NITERF  256
#define GSTAGES 4
#define ROWB    80
#define ASZ     (BM * ROWB)
#define STAGE   (2 * ASZ)
#define GSMEM   (GSTAGES * STAGE)

__device__ __forceinline__ void g_load_stage(uint32_t sb,
                                             const __nv_bfloat16* __restrict__ A2,
                                             const __nv_bfloat16* __restrict__ B2,
                                             int m0, int n0, int j, int t)
{
    const int seg  = j >> 7;
    const int kloc = (j & 127) * BK;
    const int aoff = (seg == 2) ? KSEG : 0;
    const int boff = (seg == 1) ? KSEG : 0;
#pragma unroll
    for (int i = 0; i < 4; ++i) {
        int c   = t + (i << 7);
        int row = c >> 2;
        int kc  = c & 3;
        cp_async16(sb + row * ROWB + kc * 16,
                   A2 + (size_t)(m0 + row) * KST2 + aoff + kloc + kc * 8);
    }
#pragma unroll
    for (int i = 0; i < 4; ++i) {
        int c   = t + (i << 7);
        int row = c >> 2;
        int kc  = c & 3;
        cp_async16(sb + ASZ + row * ROWB + kc * 16,
                   B2 + (size_t)(n0 + row) * KST2 + boff + kloc + kc * 8);
    }
    cp_commit();
}

__device__ __forceinline__ void g_load_stage_f(uint32_t sb,
                                               const __half* __restrict__ A2,
                                               const __half* __restrict__ B2,
                                               int m0, int n0, int j, int t)
{
    const int off  = (j >> 7) ? KSEG : 0;
    const int kloc = (j & 127) * BK;
#pragma unroll
    for (int i = 0; i < 4; ++i) {
        int c   = t + (i << 7);
        int row = c >> 2;
        int kc  = c & 3;
        cp_async16(sb + row * ROWB + kc * 16,
                   A2 + (size_t)(m0 + row) * KST2 + off + kloc + kc * 8);
    }
#pragma unroll
    for (int i = 0; i < 4; ++i) {
        int c   = t + (i << 7);
        int row = c >> 2;
        int kc  = c & 3;
        cp_async16(sb + ASZ + row * ROWB + kc * 16,
                   B2 + (size_t)(n0 + row) * KST2 + off + kloc + kc * 8);
    }
    cp_commit();
}

#define GEMM_BODY(LOADFN, MMAFN, NITERS, APTR, BPTR)                          \
    float acc[4][8][4];                                                       \
    _Pragma("unroll")                                                         \
    for (int mi = 0; mi < 4; ++mi)                                            \
        _Pragma("unroll")                                                     \
        for (int nj = 0; nj < 8; ++nj)                                        \
            _Pragma("unroll")                                                 \
            for (int q = 0; q < 4; ++q) acc[mi][nj][q] = 0.0f;                \
    _Pragma("unroll")                                                         \
    for (int it = 0; it < GSTAGES - 1; ++it)                                  \
        LOADFN(base + it * STAGE, APTR, BPTR, m0, n0, it, t);                 \
    for (int it = 0; it < NITERS; ++it) {                                     \
        const int st = it & (GSTAGES - 1);                                    \
        cp_wait<GSTAGES - 2>();                                               \
        __syncthreads();                                                      \
        const uint32_t stA = base + st * STAGE;                               \
        const uint32_t stB = stA + ASZ;                                       \
        _Pragma("unroll")                                                     \
        for (int kh = 0; kh < 2; ++kh) {                                      \
            uint32_t a[4][4];                                                 \
            _Pragma("unroll")                                                 \
            for (int mi = 0; mi < 4; ++mi)                                    \
                ldsm_x4(a[mi][0], a[mi][1], a[mi][2], a[mi][3],               \
                        stA + (uint32_t)((wm + mi * 16 + rA) * ROWB           \
                                         + (kh * 2 + selA) * 16));            \
            uint32_t b[4][4];                                                 \
            _Pragma("unroll")                                                 \
            for (int p = 0; p < 4; ++p)                                       \
                ldsm_x4(b[p][0], b[p][1], b[p][2], b[p][3],                   \
                        stB + (uint32_t)((wn + p * 16 + rB) * ROWB            \
                                         + (kh * 2 + selB) * 16));            \
            _Pragma("unroll")                                                 \
            for (int mi = 0; mi < 4; ++mi) {                                  \
                _Pragma("unroll")                                             \
                for (int p = 0; p < 4; ++p) {                                 \
                    MMAFN(acc[mi][2 * p],     a[mi], &b[p][0]);               \
                    MMAFN(acc[mi][2 * p + 1], a[mi], &b[p][2]);               \
                }                                                             \
            }                                                                 \
        }                                                                     \
        const int j = it + GSTAGES - 1;                                       \
        if (j < NITERS)                                                       \
            LOADFN(base + (j & (GSTAGES - 1)) * STAGE, APTR, BPTR, m0, n0, j, t); \
    }

#define GEMM_PROLOG_COMMON                                                    \
    extern __shared__ char smraw[];                                           \
    const uint32_t base = smem_u32(smraw);                                    \
    const int t    = threadIdx.x;                                             \
    const int wid  = t >> 5;                                                  \
    const int lane = t & 31;                                                  \
    const int m0   = blockIdx.y * BM;                                         \
    const int wm   = (wid >> 1) * 64;                                         \
    const int wn   = (wid & 1) * 64;                                          \
    const int rA   = lane & 15;                                               \
    const int selA = lane >> 4;                                               \
    const int rB   = ((lane >> 4) << 3) | (lane & 7);                         \
    const int selB = (lane >> 3) & 1;

// Merged Q+K projection GEMM: grid.x covers N=8192 (Q cols then K cols)
__global__ void __launch_bounds__(128, 2)
gemm_qk(const __nv_bfloat16* __restrict__ A2,
        const __nv_bfloat16* __restrict__ Bq,
        const __nv_bfloat16* __restrict__ Bk,
        float* __restrict__ Cq,
        float* __restrict__ Ck)
{
    GEMM_PROLOG_COMMON
    const int n0g = blockIdx.x * BN;
    const __nv_bfloat16* B2 = (n0g < HDIM) ? Bq : Bk;
    float* C = (n0g < HDIM) ? Cq : Ck;
    const int n0 = n0g & (HDIM - 1);

    GEMM_BODY(g_load_stage, mma16816, NITER, A2, B2)

    const int er = lane >> 2;
    const int ec = (lane & 3) << 1;
#pragma unroll
    for (int mi = 0; mi < 4; ++mi) {
#pragma unroll
        for (int nj = 0; nj < 8; ++nj) {
            size_t r0 = (size_t)(m0 + wm + mi * 16 + er) * HDIM
                        + (n0 + wn + nj * 8 + ec);
            *(float2*)&C[r0]            = make_float2(acc[mi][nj][0], acc[mi][nj][1]);
            *(float2*)&C[r0 + 8 * HDIM] = make_float2(acc[mi][nj][2], acc[mi][nj][3]);
        }
    }
}

// fp16 GEMM, fp32 output (O projection)
__global__ void __launch_bounds__(128, 2)
gemm_f16(const __half* __restrict__ A2,
         const __half* __restrict__ B2,
         float* __restrict__ C)
{
    GEMM_PROLOG_COMMON
    const int n0 = blockIdx.x * BN;
    GEMM_BODY(g_load_stage_f, mma16816f, NITERF, A2, B2)

    const int er = lane >> 2;
    const int ec = (lane & 3) << 1;
#pragma unroll
    for (int mi = 0; mi < 4; ++mi) {
#pragma unroll
        for (int nj = 0; nj < 8; ++nj) {
            size_t r0 = (size_t)(m0 + wm + mi * 16 + er) * HDIM
                        + (n0 + wn + nj * 8 + ec);
            *(float2*)&C[r0]            = make_float2(acc[mi][nj][0], acc[mi][nj][1]);
            *(float2*)&C[r0 + 8 * HDIM] = make_float2(acc[mi][nj][2], acc[mi][nj][3]);
        }
    }
}

// fp16 GEMM, fused V epilogue: writes fp16 g_Vf [h][s][128]
__global__ void __launch_bounds__(128, 2)
gemm_f16v(const __half* __restrict__ A2,
          const __half* __restrict__ B2,
          __half* __restrict__ Vf)
{
    GEMM_PROLOG_COMMON
    const int n0 = blockIdx.x * BN;
    GEMM_BODY(g_load_stage_f, mma16816f, NITERF, A2, B2)

    const int er = lane >> 2;
    const int ec = (lane & 3) << 1;
#pragma unroll
    for (int mi = 0; mi < 4; ++mi) {
        int s0 = m0 + wm + mi * 16 + er;
#pragma unroll
        for (int nj = 0; nj < 8; ++nj) {
            int col = n0 + wn + nj * 8 + ec;
            int h   = col >> 7;
            int hc  = col & 127;
            size_t b0 = ((size_t)h * S_LEN + s0) * HEADD + hc;
            size_t b1 = ((size_t)h * S_LEN + s0 + 8) * HEADD + hc;
            *(uint32_t*)(Vf + b0) = pkh(__float2half_rn(acc[mi][nj][0]),
                                        __float2half_rn(acc[mi][nj][1]));
            *(uint32_t*)(Vf + b1) = pkh(__float2half_rn(acc[mi][nj][2]),
                                        __float2half_rn(acc[mi][nj][3]));
        }
    }
}

// ===========================================================================
// Fused RoPE + head-dim split (validated)
// ===========================================================================
#define ATT_SCALE 0.08838834764831843f

__global__ void __launch_bounds__(256) rope_split_qk(
    const float* __restrict__ Q, const float* __restrict__ K,
    const int* __restrict__ pos,
    __nv_bfloat16* __restrict__ Q2, __nv_bfloat16* __restrict__ K2o)
{
    int idx = blockIdx.x * 256 + threadIdx.x;
    if (idx >= S_LEN * NHEADS * 16) return;
    int j4 = (idx & 15) << 2;
    int h  = (idx >> 4) & (NHEADS - 1);
    int s  = idx >> 9;
    int p  = pos[s];

    float sn[4], cs[4];
#pragma unroll
    for (int i = 0; i < 4; ++i) {
        float inv = 1.0f / powf(10000.0f, (float)(j4 + i) * (1.0f / 64.0f));
        sincosf((float)p * inv, &sn[i], &cs[i]);
    }

    size_t gb = (size_t)s * HDIM + (size_t)h * HEADD + j4;
    float4 qa4 = *(const float4*)&Q[gb];
    float4 qb4 = *(const float4*)&Q[gb + 64];
    float4 ka4 = *(const float4*)&K[gb];
    float4 kb4 = *(const float4*)&K[gb + 64];
    float qa[4] = {qa4.x, qa4.y, qa4.z, qa4.w};
    float qb[4] = {qb4.x, qb4.y, qb4.z, qb4.w};
    float ka[4] = {ka4.x, ka4.y, ka4.z, ka4.w};
    float kb[4] = {kb4.x, kb4.y, kb4.z, kb4.w};

    __nv_bfloat16 qah[4], qal[4], qbh[4], qbl[4];
    __nv_bfloat16 kah[4], kal[4], kbh[4], kbl[4];
#pragma unroll
    for (int i = 0; i < 4; ++i) {
        float r1 = (qa[i] * cs[i] - qb[i] * sn[i]) * ATT_SCALE;
        float r2 = (qb[i] * cs[i] + qa[i] * sn[i]) * ATT_SCALE;
        split2(r1, qah[i], qal[i]);
        split2(r2, qbh[i], qbl[i]);
        float t1 = ka[i] * cs[i] - kb[i] * sn[i];
        float t2 = kb[i] * cs[i] + ka[i] * sn[i];
        split2(t1, kah[i], kal[i]);
        split2(t2, kbh[i], kbl[i]);
    }

    size_t ob = ((size_t)h * S_LEN + s) * HD2 + j4;
    *(uint2*)(Q2 + ob)       = make_uint2(pkb(qah[0], qah[1]), pkb(qah[2], qah[3]));
    *(uint2*)(Q2 + ob + 64)  = make_uint2(pkb(qbh[0], qbh[1]), pkb(qbh[2], qbh[3]));
    *(uint2*)(Q2 + ob + 128) = make_uint2(pkb(qal[0], qal[1]), pkb(qal[2], qal[3]));
    *(uint2*)(Q2 + ob + 192) = make_uint2(pkb(qbl[0], qbl[1]), pkb(qbl[2], qbl[3]));

    *(uint2*)(K2o + ob)       = make_uint2(pkb(kah[0], kah[1]), pkb(kah[2], kah[3]));
    *(uint2*)(K2o + ob + 64)  = make_uint2(pkb(kbh[0], kbh[1]), pkb(kbh[2], kbh[3]));
    *(uint2*)(K2o + ob + 128) = make_uint2(pkb(kal[0], kal[1]), pkb(kal[2], kal[3]));
    *(uint2*)(K2o + ob + 192) = make_uint2(pkb(kbl[0], kbl[1]), pkb(kbl[2], kbl[3]));
}

// ===========================================================================
// Flash attention v5: 256 threads (validated R10 shape).
// Scores: bf16 3-pass split. Softmax fp32 -> single fp16 P.
// PV: single-pass fp16 (P fp16 x V fp16). K double-buffered, V fp16 halved.
// ===========================================================================
#define NEG_BIG (-3.0e38f)
#define FROW2  528    // 256 bf16 + pad
#define FROWV  272    // 128 fp16 + pad
#define FROWP  144    // 64 fp16 + pad
#define OFF_K2S  (64 * FROW2)                         // 33792
#define OFF_VS   (OFF_K2S + 2 * 64 * FROW2)           // 101376
#define OFF_SS   (OFF_VS + 2 * 64 * FROWV)            // 136192
#define OFF_PS   (OFF_SS + 64 * 68 * 4)               // 153600
#define OFF_RW   (OFF_PS + 64 * FROWP)                // 162816
#define FSMEM    (OFF_RW + 3 * 64 * 4)                // 163584

__device__ __forceinline__ void f_load_kv(uint32_t sb, int buf,
                                          const __nv_bfloat16* __restrict__ K2g,
                                          const __half* __restrict__ Vg,
                                          int t)
{
    uint32_t kb = sb + OFF_K2S + buf * (64 * FROW2);
    for (int c = t; c < 64 * 32; c += 256) {
        int r = c >> 5, ch = c & 31;
        cp_async16(kb + r * FROW2 + ch * 16,
                   (const char*)K2g + (size_t)r * (HD2 * 2) + ch * 16);
    }
    uint32_t vb = sb + OFF_VS + buf * (64 * FROWV);
    for (int c = t; c < 64 * 16; c += 256) {
        int r = c >> 4, ch = c & 15;
        cp_async16(vb + r * FROWV + ch * 16,
                   (const char*)Vg + (size_t)r * (HEADD * 2) + ch * 16);
    }
    cp_commit();
}

__global__ void __launch_bounds__(256) flash2(
    const __nv_bfloat16* __restrict__ Q2,
    const __nv_bfloat16* __restrict__ K2g,
    const __half* __restrict__ Vf,
    __half* __restrict__ A2out)
{
    extern __shared__ char smraw[];
    const uint32_t sb = smem_u32(smraw);
    float* Ss  = (float*)(smraw + OFF_SS);
    __half* Ps = (__half*)(smraw + OFF_PS);
    float* mrow = (float*)(smraw + OFF_RW);
    float* lrow = mrow + 64;
    float* srow = lrow + 64;

    const int h  = blockIdx.x;
    const int qb = (gridDim.y - 1) - blockIdx.y;   // heavy blocks first
    const int q0 = qb * 64;
    const int t = threadIdx.x, wid = t >> 5, lane = t & 31;
    const int wm = (wid >> 2) * 32;
    const int wn = (wid & 3) * 16;
    const int wnv = (wid & 3) * 32;
    const int rA = lane & 15, selA = lane >> 4;
    const int rB = ((lane >> 4) << 3) | (lane & 7), selB = (lane >> 3) & 1;
    const int er = lane >> 2, ec = (lane & 3) << 1;

    const __nv_bfloat16* Qg = Q2 + ((size_t)h * S_LEN + q0) * HD2;
    for (int c = t; c < 64 * 32; c += 256) {
        int r = c >> 5, ch = c & 31;
        cp_async16(sb + r * FROW2 + ch * 16,
                   (const char*)Qg + (size_t)r * (HD2 * 2) + ch * 16);
    }
    cp_commit();
    if (t < 64) { mrow[t] = NEG_BIG; lrow[t] = 0.0f; }

    f_load_kv(sb, 0, K2g + ((size_t)h * S_LEN) * HD2,
              Vf + ((size_t)h * S_LEN) * HEADD, t);

    float oacc[2][4][4];
#pragma unroll
    for (int mi = 0; mi < 2; ++mi)
#pragma unroll
        for (int nj = 0; nj < 4; ++nj)
#pragma unroll
            for (int q = 0; q < 4; ++q) oacc[mi][nj][q] = 0.0f;

    for (int kb = 0; kb <= qb; ++kb) {
        const int buf = kb & 1;
        cp_wait<0>();
        __syncthreads();

        if (kb + 1 <= qb)
            f_load_kv(sb, buf ^ 1,
                      K2g + ((size_t)h * S_LEN + (kb + 1) * 64) * HD2,
                      Vf + ((size_t)h * S_LEN + (kb + 1) * 64) * HEADD, t);

        const uint32_t kbase = sb + OFF_K2S + buf * (64 * FROW2);
        const uint32_t vbase = sb + OFF_VS + buf * (64 * FROWV);

        // ---- scores: bf16 3-pass split (validated) ----
        float sacc[2][2][4];
#pragma unroll
        for (int mi = 0; mi < 2; ++mi)
#pragma unroll
            for (int nj = 0; nj < 2; ++nj)
#pragma unroll
                for (int q = 0; q < 4; ++q) sacc[mi][nj][q] = 0.0f;

        const uint32_t sAoff[3] = {0u, 0u, 256u};
        const uint32_t sBoff[3] = {0u, 256u, 0u};
#pragma unroll
        for (int ps = 0; ps < 3; ++ps) {
#pragma unroll
            for (int k16 = 0; k16 < 8; ++k16) {
                uint32_t a[2][4], b[4];
#pragma unroll
                for (int mi = 0; mi < 2; ++mi)
                    ldsm_x4(a[mi][0], a[mi][1], a[mi][2], a[mi][3],
                            sb + (uint32_t)((wm + mi * 16 + rA) * FROW2)
                               + sAoff[ps] + k16 * 32 + selA * 16);
                ldsm_x4(b[0], b[1], b[2], b[3],
                        kbase + (uint32_t)((wn + rB) * FROW2)
                              + sBoff[ps] + k16 * 32 + selB * 16);
#pragma unroll
                for (int mi = 0; mi < 2; ++mi)
#pragma unroll
                    for (int nj = 0; nj < 2; ++nj)
                        mma16816(sacc[mi][nj], a[mi], &b[nj << 1]);
            }
        }

        const bool diag = (kb == qb);
#pragma unroll
        for (int mi = 0; mi < 2; ++mi) {
#pragma unroll
            for (int nj = 0; nj < 2; ++nj) {
                int row = wm + mi * 16 + er;
                int col = wn + nj * 8 + ec;
                float v0 = sacc[mi][nj][0], v1 = sacc[mi][nj][1];
                float v2 = sacc[mi][nj][2], v3 = sacc[mi][nj][3];
                if (diag) {
                    if (col > row)     v0 = NEG_BIG;
                    if (col + 1 > row) v1 = NEG_BIG;
                    if (col > row + 8)     v2 = NEG_BIG;
                    if (col + 1 > row + 8) v3 = NEG_BIG;
                }
                Ss[row * 68 + col]       = v0;
                Ss[row * 68 + col + 1]   = v1;
                Ss[(row + 8) * 68 + col]     = v2;
                Ss[(row + 8) * 68 + col + 1] = v3;
            }
        }
        __syncthreads();

        // ---- online softmax: fp32, emits single fp16 P ----
        {
            int r  = t >> 2;
            int qd = t & 3;
            float* srw = &Ss[r * 68 + qd * 16];
            __half* prw = &Ps[r * 72 + qd * 16];
            float vals[16];
            float mx = NEG_BIG;
#pragma unroll
            for (int i = 0; i < 16; ++i) { vals[i] = srw[i]; mx = fmaxf(mx, vals[i]); }
            mx = fmaxf(mx, __shfl_xor_sync(0xffffffffu, mx, 1));
            mx = fmaxf(mx, __shfl_xor_sync(0xffffffffu, mx, 2));
            float mold = mrow[r];
            float mnew = fmaxf(mold, mx);
            float sum = 0.0f;
#pragma unroll
            for (int i = 0; i < 16; ++i) {
                float p = __expf(vals[i] - mnew);
                prw[i] = __float2half_rn(p);
                sum += p;
            }
            sum += __shfl_xor_sync(0xffffffffu, sum, 1);
            sum += __shfl_xor_sync(0xffffffffu, sum, 2);
            float corr = __expf(mold - mnew);
            if (qd == 0) {
                mrow[r] = mnew;
                lrow[r] = lrow[r] * corr + sum;
                srow[r] = corr;
            }
        }
        __syncthreads();

        // ---- rescale + PV: single-pass fp16 ----
#pragma unroll
        for (int mi = 0; mi < 2; ++mi) {
            float c0 = srow[wm + mi * 16 + er];
            float c1 = srow[wm + mi * 16 + er + 8];
#pragma unroll
            for (int nj = 0; nj < 4; ++nj) {
                oacc[mi][nj][0] *= c0; oacc[mi][nj][1] *= c0;
                oacc[mi][nj][2] *= c1; oacc[mi][nj][3] *= c1;
            }
        }

        const int vkr = ((lane >> 3) & 1) * 8 + (lane & 7);
        const int vnc = (lane >> 4) * 8;
#pragma unroll
        for (int kk = 0; kk < 4; ++kk) {
            uint32_t a[2][4], b0[4], b1[4];
#pragma unroll
            for (int mi = 0; mi < 2; ++mi)
                ldsm_x4(a[mi][0], a[mi][1], a[mi][2], a[mi][3],
                        sb + OFF_PS + (uint32_t)((wm + mi * 16 + rA) * FROWP)
                           + kk * 32 + selA * 16);
            uint32_t vaddr = vbase + (uint32_t)((kk * 16 + vkr) * FROWV);
            ldsm_x4t(b0[0], b0[1], b0[2], b0[3], vaddr + (wnv + vnc) * 2);
            ldsm_x4t(b1[0], b1[1], b1[2], b1[3], vaddr + (wnv + 16 + vnc) * 2);
#pragma unroll
            for (int mi = 0; mi < 2; ++mi) {
                mma16816f(oacc[mi][0], a[mi], &b0[0]);
                mma16816f(oacc[mi][1], a[mi], &b0[2]);
                mma16816f(oacc[mi][2], a[mi], &b1[0]);
                mma16816f(oacc[mi][3], a[mi], &b1[2]);
            }
        }
    }

    // epilogue: normalize, write fp16 [xh | xh*2^-10] into A2f
#pragma unroll
    for (int mi = 0; mi < 2; ++mi) {
        float l0 = 1.0f / lrow[wm + mi * 16 + er];
        float l1 = 1.0f / lrow[wm + mi * 16 + er + 8];
#pragma unroll
        for (int nj = 0; nj < 4; ++nj) {
            int col = h * HEADD + wnv + nj * 8 + ec;
            size_t r0 = (size_t)(q0 + wm + mi * 16 + er) * KST2 + col;
            size_t r1 = r0 + (size_t)8 * KST2;
            float x0 = oacc[mi][nj][0] * l0, x1 = oacc[mi][nj][1] * l0;
            float y0 = oacc[mi][nj][2] * l1, y1 = oacc[mi][nj][3] * l1;
            *(uint32_t*)(A2out + r0) =
                pkh(__float2half_rn(x0), __float2half_rn(x1));
            *(uint32_t*)(A2out + r0 + KSEG) =
                pkh(__float2half_rn(x0 * SC10), __float2half_rn(x1 * SC10));
            *(uint32_t*)(A2out + r1) =
                pkh(__float2half_rn(y0), __float2half_rn(y1));
            *(uint32_t*)(A2out + r1 + KSEG) =
                pkh(__float2half_rn(y0 * SC10), __float2half_rn(y1 * SC10));
        }
    }
}

// ===========================================================================
// Launch
// ===========================================================================
extern "C" void kernel_launch(void* const* d_in, const int* in_sizes, int n_in,
                              void* d_out, int out_size)
{
    (void)in_sizes; (void)n_in; (void)out_size;

    const float* X   = (const float*)d_in[0];
    const int*   pos = (const int*)d_in[2];
    const float* Wq  = (const float*)d_in[3];
    const float* Wk  = (const float*)d_in[4];
    const float* Wv  = (const float*)d_in[5];
    const float* Wo  = (const float*)d_in[6];
    float* out = (float*)d_out;

    float *Qd, *Kd;
    __nv_bfloat16 *A2d, *W2qd, *W2kd, *Q2d, *K2d;
    __half *A2fd, *W2vfd, *W2ofd, *Vfd;
    cudaGetSymbolAddress((void**)&Qd, g_Q);
    cudaGetSymbolAddress((void**)&Kd, g_K);
    cudaGetSymbolAddress((void**)&A2d, g_A2);
    cudaGetSymbolAddress((void**)&A2fd, g_A2f);
    cudaGetSymbolAddress((void**)&W2qd, g_W2q);
    cudaGetSymbolAddress((void**)&W2kd, g_W2k);
    cudaGetSymbolAddress((void**)&W2vfd, g_W2vf);
    cudaGetSymbolAddress((void**)&W2ofd, g_W2of);
    cudaGetSymbolAddress((void**)&Q2d, g_Q2);
    cudaGetSymbolAddress((void**)&K2d, g_K2a);
    cudaGetSymbolAddress((void**)&Vfd, g_Vf);

    cudaFuncSetAttribute(gemm_qk, cudaFuncAttributeMaxDynamicSharedMemorySize, GSMEM);
    cudaFuncSetAttribute(gemm_f16, cudaFuncAttributeMaxDynamicSharedMemorySize, GSMEM);
    cudaFuncSetAttribute(gemm_f16v, cudaFuncAttributeMaxDynamicSharedMemorySize, GSMEM);
    cudaFuncSetAttribute(flash2, cudaFuncAttributeMaxDynamicSharedMemorySize, FSMEM);

    split_x<<<(S_LEN * 1024) / 256, 256>>>(X, A2d, A2fd, S_LEN * 1024);
    split_hilo<<<(HDIM * 1024) / 256, 256>>>(Wq, W2qd, HDIM * 1024);
    split_hilo<<<(HDIM * 1024) / 256, 256>>>(Wk, W2kd, HDIM * 1024);
    split_wf16<<<(HDIM * 1024) / 256, 256>>>(Wv, W2vfd, HDIM * 1024);
    split_wf16<<<(HDIM * 1024) / 256, 256>>>(Wo, W2ofd, HDIM * 1024);

    // Merged Q+K projection (512 CTAs), then V projection (fused fp16 epilogue)
    gemm_qk<<<dim3(2 * HDIM / BN, S_LEN / BM), 128, GSMEM>>>(A2d, W2qd, W2kd, Qd, Kd);
    gemm_f16v<<<dim3(HDIM / BN, S_LEN / BM), 128, GSMEM>>>(A2fd, W2vfd, Vfd);

    rope_split_qk<<<(S_LEN * NHEADS * 16) / 256, 256>>>(Qd, Kd, pos, Q2d, K2d);

    flash2<<<dim3(NHEADS, S_LEN / 64), 256, FSMEM>>>(Q2d, K2d, Vfd, A2fd);

    gemm_f16<<<dim3(HDIM / BN, S_LEN / BM), 128, GSMEM>>>(A2fd, W2ofd, out);
}

// round 13
// speedup vs baseline: 1.2556x; 1.1862x over previous
#include <cuda_runtime.h>
#include <cuda_bf16.h>
#include <cuda_fp16.h>
#include <math.h>
#include <stdint.h>

// Problem constants
#define S_LEN  2048
#define HDIM   4096
#define NHEADS 32
#define HEADD  128
#define HD2    256      // Q/K head-dim split storage: [hi(128) | lo(128)]

#define KSEG   4096
#define KST2   8192
#define SC10   0.0009765625f   // 2^-10

// Scratch (device globals)
__device__ float g_Q[S_LEN * HDIM];
__device__ float g_K[S_LEN * HDIM];
__device__ __half        g_A2f[S_LEN * KST2];          // X fp16 [xh | xh*2^-10] / attn out
__device__ __half        g_W2qf[HDIM * KST2];          // W fp16 [wh | wl*2^10]
__device__ __half        g_W2kf[HDIM * KST2];
__device__ __half        g_W2vf[HDIM * KST2];
__device__ __half        g_W2of[HDIM * KST2];
__device__ __nv_bfloat16 g_Q2[NHEADS * S_LEN * HD2];   // [h][s][Qh|Ql]
__device__ __nv_bfloat16 g_K2a[NHEADS * S_LEN * HD2];  // [h][s][Kh|Kl]
__device__ __half        g_Vf[NHEADS * S_LEN * HEADD]; // [h][s][128] fp16

// ===========================================================================
// PTX helpers
// ===========================================================================
__device__ __forceinline__ uint32_t smem_u32(const void* p) {
    uint32_t a;
    asm("{ .reg .u64 t; cvta.to.shared.u64 t, %1; cvt.u32.u64 %0, t; }" : "=r"(a) : "l"(p));
    return a;
}
__device__ __forceinline__ void cp_async16(uint32_t dst, const void* src) {
    asm volatile("cp.async.cg.shared.global [%0], [%1], 16;" :: "r"(dst), "l"(src));
}
__device__ __forceinline__ void cp_commit() {
    asm volatile("cp.async.commit_group;" ::: "memory");
}
template <int N> __device__ __forceinline__ void cp_wait() {
    asm volatile("cp.async.wait_group %0;" :: "n"(N) : "memory");
}
__device__ __forceinline__ void ldsm_x4(uint32_t& r0, uint32_t& r1, uint32_t& r2,
                                        uint32_t& r3, uint32_t addr) {
    asm volatile("ldmatrix.sync.aligned.m8n8.x4.shared.b16 {%0,%1,%2,%3}, [%4];"
                 : "=r"(r0), "=r"(r1), "=r"(r2), "=r"(r3) : "r"(addr));
}
__device__ __forceinline__ void ldsm_x4t(uint32_t& r0, uint32_t& r1, uint32_t& r2,
                                         uint32_t& r3, uint32_t addr) {
    asm volatile("ldmatrix.sync.aligned.m8n8.x4.trans.shared.b16 {%0,%1,%2,%3}, [%4];"
                 : "=r"(r0), "=r"(r1), "=r"(r2), "=r"(r3) : "r"(addr));
}
__device__ __forceinline__ void mma16816(float* c, const uint32_t* a, const uint32_t* b) {
    asm volatile(
        "mma.sync.aligned.m16n8k16.row.col.f32.bf16.bf16.f32 "
        "{%0,%1,%2,%3}, {%4,%5,%6,%7}, {%8,%9}, {%0,%1,%2,%3};"
        : "+f"(c[0]), "+f"(c[1]), "+f"(c[2]), "+f"(c[3])
        : "r"(a[0]), "r"(a[1]), "r"(a[2]), "r"(a[3]), "r"(b[0]), "r"(b[1]));
}
__device__ __forceinline__ void mma16816f(float* c, const uint32_t* a, const uint32_t* b) {
    asm volatile(
        "mma.sync.aligned.m16n8k16.row.col.f32.f16.f16.f32 "
        "{%0,%1,%2,%3}, {%4,%5,%6,%7}, {%8,%9}, {%0,%1,%2,%3};"
        : "+f"(c[0]), "+f"(c[1]), "+f"(c[2]), "+f"(c[3])
        : "r"(a[0]), "r"(a[1]), "r"(a[2]), "r"(a[3]), "r"(b[0]), "r"(b[1]));
}

__device__ __forceinline__ uint32_t pkb(__nv_bfloat16 a, __nv_bfloat16 b) {
    __nv_bfloat162 t = __halves2bfloat162(a, b);
    return *reinterpret_cast<uint32_t*>(&t);
}
__device__ __forceinline__ uint32_t pkh(__half a, __half b) {
    __half2 t = __halves2half2(a, b);
    return *reinterpret_cast<uint32_t*>(&t);
}
__device__ __forceinline__ void split2(float x, __nv_bfloat16& h, __nv_bfloat16& l) {
    h = __float2bfloat16_rn(x);
    l = __float2bfloat16_rn(x - __bfloat162float(h));
}

// ===========================================================================
// Split kernels
// ===========================================================================
// X fp32 -> fp16 [xh | xh*2^-10]
__global__ void __launch_bounds__(256) split_xf(const float* __restrict__ src,
                                                __half* __restrict__ dst,
                                                int total4)
{
    int i = blockIdx.x * 256 + threadIdx.x;
    if (i >= total4) return;
    int row = i >> 10;
    int c4  = (i & 1023) << 2;
    float4 v = ((const float4*)src)[i];
    float in[4] = {v.x, v.y, v.z, v.w};
    __half f[4], fs[4];
#pragma unroll
    for (int j = 0; j < 4; ++j) {
        f[j]  = __float2half_rn(in[j]);
        fs[j] = __float2half_rn(in[j] * SC10);
    }
    size_t b = (size_t)row * KST2 + c4;
    *(uint2*)(dst + b)        = make_uint2(pkh(f[0], f[1]), pkh(f[2], f[3]));
    *(uint2*)(dst + b + KSEG) = make_uint2(pkh(fs[0], fs[1]), pkh(fs[2], fs[3]));
}

// W fp32 -> fp16 [wh | wl*2^10]
__global__ void __launch_bounds__(256) split_wf16(const float* __restrict__ src,
                                                  __half* __restrict__ dst,
                                                  int total4)
{
    int i = blockIdx.x * 256 + threadIdx.x;
    if (i >= total4) return;
    int row = i >> 10;
    int c4  = (i & 1023) << 2;
    float4 v = ((const float4*)src)[i];
    float in[4] = {v.x, v.y, v.z, v.w};
    __half h[4], l[4];
#pragma unroll
    for (int j = 0; j < 4; ++j) {
        h[j] = __float2half_rn(in[j]);
        l[j] = __float2half_rn((in[j] - __half2float(h[j])) * 1024.0f);
    }
    size_t b = (size_t)row * KST2 + c4;
    *(uint2*)(dst + b)        = make_uint2(pkh(h[0], h[1]), pkh(h[2], h[3]));
    *(uint2*)(dst + b + KSEG) = make_uint2(pkh(l[0], l[1]), pkh(l[2], l[3]));
}

// ===========================================================================
// GEMM common: CTA 128x128, BK=32, 128 threads (2x2 warps, 64x64/warp),
// 4-stage cp.async, 2 CTAs/SM. All fp16 2-segment now.
// ===========================================================================
#define BM 128
#define BN 128
#define BK 32
#define NITERF  256
#define GSTAGES 4
#define ROWB    80
#define ASZ     (BM * ROWB)
#define STAGE   (2 * ASZ)
#define GSMEM   (GSTAGES * STAGE)

__device__ __forceinline__ void g_load_stage_f(uint32_t sb,
                                               const __half* __restrict__ A2,
                                               const __half* __restrict__ B2,
                                               int m0, int n0, int j, int t)
{
    const int off  = (j >> 7) ? KSEG : 0;
    const int kloc = (j & 127) * BK;
#pragma unroll
    for (int i = 0; i < 4; ++i) {
        int c   = t + (i << 7);
        int row = c >> 2;
        int kc  = c & 3;
        cp_async16(sb + row * ROWB + kc * 16,
                   A2 + (size_t)(m0 + row) * KST2 + off + kloc + kc * 8);
    }
#pragma unroll
    for (int i = 0; i < 4; ++i) {
        int c   = t + (i << 7);
        int row = c >> 2;
        int kc  = c & 3;
        cp_async16(sb + ASZ + row * ROWB + kc * 16,
                   B2 + (size_t)(n0 + row) * KST2 + off + kloc + kc * 8);
    }
    cp_commit();
}

#define GEMM_BODY_F(APTR, BPTR)                                               \
    float acc[4][8][4];                                                       \
    _Pragma("unroll")                                                         \
    for (int mi = 0; mi < 4; ++mi)                                            \
        _Pragma("unroll")                                                     \
        for (int nj = 0; nj < 8; ++nj)                                        \
            _Pragma("unroll")                                                 \
            for (int q = 0; q < 4; ++q) acc[mi][nj][q] = 0.0f;                \
    _Pragma("unroll")                                                         \
    for (int it = 0; it < GSTAGES - 1; ++it)                                  \
        g_load_stage_f(base + it * STAGE, APTR, BPTR, m0, n0, it, t);         \
    for (int it = 0; it < NITERF; ++it) {                                     \
        const int st = it & (GSTAGES - 1);                                    \
        cp_wait<GSTAGES - 2>();                                               \
        __syncthreads();                                                      \
        const uint32_t stA = base + st * STAGE;                               \
        const uint32_t stB = stA + ASZ;                                       \
        _Pragma("unroll")                                                     \
        for (int kh = 0; kh < 2; ++kh) {                                      \
            uint32_t a[4][4];                                                 \
            _Pragma("unroll")                                                 \
            for (int mi = 0; mi < 4; ++mi)                                    \
                ldsm_x4(a[mi][0], a[mi][1], a[mi][2], a[mi][3],               \
                        stA + (uint32_t)((wm + mi * 16 + rA) * ROWB           \
                                         + (kh * 2 + selA) * 16));            \
            uint32_t b[4][4];                                                 \
            _Pragma("unroll")                                                 \
            for (int p = 0; p < 4; ++p)                                       \
                ldsm_x4(b[p][0], b[p][1], b[p][2], b[p][3],                   \
                        stB + (uint32_t)((wn + p * 16 + rB) * ROWB            \
                                         + (kh * 2 + selB) * 16));            \
            _Pragma("unroll")                                                 \
            for (int mi = 0; mi < 4; ++mi) {                                  \
                _Pragma("unroll")                                             \
                for (int p = 0; p < 4; ++p) {                                 \
                    mma16816f(acc[mi][2 * p],     a[mi], &b[p][0]);           \
                    mma16816f(acc[mi][2 * p + 1], a[mi], &b[p][2]);           \
                }                                                             \
            }                                                                 \
        }                                                                     \
        const int j = it + GSTAGES - 1;                                       \
        if (j < NITERF)                                                       \
            g_load_stage_f(base + (j & (GSTAGES - 1)) * STAGE, APTR, BPTR,    \
                           m0, n0, j, t);                                     \
    }

#define GEMM_PROLOG_COMMON                                                    \
    extern __shared__ char smraw[];                                           \
    const uint32_t base = smem_u32(smraw);                                    \
    const int t    = threadIdx.x;                                             \
    const int wid  = t >> 5;                                                  \
    const int lane = t & 31;                                                  \
    const int m0   = blockIdx.y * BM;                                         \
    const int wm   = (wid >> 1) * 64;                                         \
    const int wn   = (wid & 1) * 64;                                          \
    const int rA   = lane & 15;                                               \
    const int selA = lane >> 4;                                               \
    const int rB   = ((lane >> 4) << 3) | (lane & 7);                         \
    const int selB = (lane >> 3) & 1;

// Merged Q+K projection (fp16 2-term): grid.x covers 2*HDIM
__global__ void __launch_bounds__(128, 2)
gemm_qk(const __half* __restrict__ A2,
        const __half* __restrict__ Bq,
        const __half* __restrict__ Bk,
        float* __restrict__ Cq,
        float* __restrict__ Ck)
{
    GEMM_PROLOG_COMMON
    const int n0g = blockIdx.x * BN;
    const __half* B2 = (n0g < HDIM) ? Bq : Bk;
    float* C = (n0g < HDIM) ? Cq : Ck;
    const int n0 = n0g & (HDIM - 1);

    GEMM_BODY_F(A2, B2)

    const int er = lane >> 2;
    const int ec = (lane & 3) << 1;
#pragma unroll
    for (int mi = 0; mi < 4; ++mi) {
#pragma unroll
        for (int nj = 0; nj < 8; ++nj) {
            size_t r0 = (size_t)(m0 + wm + mi * 16 + er) * HDIM
                        + (n0 + wn + nj * 8 + ec);
            *(float2*)&C[r0]            = make_float2(acc[mi][nj][0], acc[mi][nj][1]);
            *(float2*)&C[r0 + 8 * HDIM] = make_float2(acc[mi][nj][2], acc[mi][nj][3]);
        }
    }
}

// fp16 GEMM, fp32 output (O projection)
__global__ void __launch_bounds__(128, 2)
gemm_f16(const __half* __restrict__ A2,
         const __half* __restrict__ B2,
         float* __restrict__ C)
{
    GEMM_PROLOG_COMMON
    const int n0 = blockIdx.x * BN;
    GEMM_BODY_F(A2, B2)

    const int er = lane >> 2;
    const int ec = (lane & 3) << 1;
#pragma unroll
    for (int mi = 0; mi < 4; ++mi) {
#pragma unroll
        for (int nj = 0; nj < 8; ++nj) {
            size_t r0 = (size_t)(m0 + wm + mi * 16 + er) * HDIM
                        + (n0 + wn + nj * 8 + ec);
            *(float2*)&C[r0]            = make_float2(acc[mi][nj][0], acc[mi][nj][1]);
            *(float2*)&C[r0 + 8 * HDIM] = make_float2(acc[mi][nj][2], acc[mi][nj][3]);
        }
    }
}

// fp16 GEMM, fused V epilogue: writes fp16 g_Vf [h][s][128]
__global__ void __launch_bounds__(128, 2)
gemm_f16v(const __half* __restrict__ A2,
          const __half* __restrict__ B2,
          __half* __restrict__ Vf)
{
    GEMM_PROLOG_COMMON
    const int n0 = blockIdx.x * BN;
    GEMM_BODY_F(A2, B2)

    const int er = lane >> 2;
    const int ec = (lane & 3) << 1;
#pragma unroll
    for (int mi = 0; mi < 4; ++mi) {
        int s0 = m0 + wm + mi * 16 + er;
#pragma unroll
        for (int nj = 0; nj < 8; ++nj) {
            int col = n0 + wn + nj * 8 + ec;
            int h   = col >> 7;
            int hc  = col & 127;
            size_t b0 = ((size_t)h * S_LEN + s0) * HEADD + hc;
            size_t b1 = ((size_t)h * S_LEN + s0 + 8) * HEADD + hc;
            *(uint32_t*)(Vf + b0) = pkh(__float2half_rn(acc[mi][nj][0]),
                                        __float2half_rn(acc[mi][nj][1]));
            *(uint32_t*)(Vf + b1) = pkh(__float2half_rn(acc[mi][nj][2]),
                                        __float2half_rn(acc[mi][nj][3]));
        }
    }
}

// ===========================================================================
// Fused RoPE + head-dim split (validated)
// ===========================================================================
#define ATT_SCALE 0.08838834764831843f

__global__ void __launch_bounds__(256) rope_split_qk(
    const float* __restrict__ Q, const float* __restrict__ K,
    const int* __restrict__ pos,
    __nv_bfloat16* __restrict__ Q2, __nv_bfloat16* __restrict__ K2o)
{
    int idx = blockIdx.x * 256 + threadIdx.x;
    if (idx >= S_LEN * NHEADS * 16) return;
    int j4 = (idx & 15) << 2;
    int h  = (idx >> 4) & (NHEADS - 1);
    int s  = idx >> 9;
    int p  = pos[s];

    float sn[4], cs[4];
#pragma unroll
    for (int i = 0; i < 4; ++i) {
        float inv = 1.0f / powf(10000.0f, (float)(j4 + i) * (1.0f / 64.0f));
        sincosf((float)p * inv, &sn[i], &cs[i]);
    }

    size_t gb = (size_t)s * HDIM + (size_t)h * HEADD + j4;
    float4 qa4 = *(const float4*)&Q[gb];
    float4 qb4 = *(const float4*)&Q[gb + 64];
    float4 ka4 = *(const float4*)&K[gb];
    float4 kb4 = *(const float4*)&K[gb + 64];
    float qa[4] = {qa4.x, qa4.y, qa4.z, qa4.w};
    float qb[4] = {qb4.x, qb4.y, qb4.z, qb4.w};
    float ka[4] = {ka4.x, ka4.y, ka4.z, ka4.w};
    float kb[4] = {kb4.x, kb4.y, kb4.z, kb4.w};

    __nv_bfloat16 qah[4], qal[4], qbh[4], qbl[4];
    __nv_bfloat16 kah[4], kal[4], kbh[4], kbl[4];
#pragma unroll
    for (int i = 0; i < 4; ++i) {
        float r1 = (qa[i] * cs[i] - qb[i] * sn[i]) * ATT_SCALE;
        float r2 = (qb[i] * cs[i] + qa[i] * sn[i]) * ATT_SCALE;
        split2(r1, qah[i], qal[i]);
        split2(r2, qbh[i], qbl[i]);
        float t1 = ka[i] * cs[i] - kb[i] * sn[i];
        float t2 = kb[i] * cs[i] + ka[i] * sn[i];
        split2(t1, kah[i], kal[i]);
        split2(t2, kbh[i], kbl[i]);
    }

    size_t ob = ((size_t)h * S_LEN + s) * HD2 + j4;
    *(uint2*)(Q2 + ob)       = make_uint2(pkb(qah[0], qah[1]), pkb(qah[2], qah[3]));
    *(uint2*)(Q2 + ob + 64)  = make_uint2(pkb(qbh[0], qbh[1]), pkb(qbh[2], qbh[3]));
    *(uint2*)(Q2 + ob + 128) = make_uint2(pkb(qal[0], qal[1]), pkb(qal[2], qal[3]));
    *(uint2*)(Q2 + ob + 192) = make_uint2(pkb(qbl[0], qbl[1]), pkb(qbl[2], qbl[3]));

    *(uint2*)(K2o + ob)       = make_uint2(pkb(kah[0], kah[1]), pkb(kah[2], kah[3]));
    *(uint2*)(K2o + ob + 64)  = make_uint2(pkb(kbh[0], kbh[1]), pkb(kbh[2], kbh[3]));
    *(uint2*)(K2o + ob + 128) = make_uint2(pkb(kal[0], kal[1]), pkb(kal[2], kal[3]));
    *(uint2*)(K2o + ob + 192) = make_uint2(pkb(kbl[0], kbl[1]), pkb(kbl[2], kbl[3]));
}

// ===========================================================================
// Flash attention v5 (validated R12): 256 threads.
// Scores bf16 3-pass split; fp32 softmax -> fp16 P; PV single-pass fp16.
// ===========================================================================
#define NEG_BIG (-3.0e38f)
#define FROW2  528
#define FROWV  272
#define FROWP  144
#define OFF_K2S  (64 * FROW2)
#define OFF_VS   (OFF_K2S + 2 * 64 * FROW2)
#define OFF_SS   (OFF_VS + 2 * 64 * FROWV)
#define OFF_PS   (OFF_SS + 64 * 68 * 4)
#define OFF_RW   (OFF_PS + 64 * FROWP)
#define FSMEM    (OFF_RW + 3 * 64 * 4)

__device__ __forceinline__ void f_load_kv(uint32_t sb, int buf,
                                          const __nv_bfloat16* __restrict__ K2g,
                                          const __half* __restrict__ Vg,
                                          int t)
{
    uint32_t kb = sb + OFF_K2S + buf * (64 * FROW2);
    for (int c = t; c < 64 * 32; c += 256) {
        int r = c >> 5, ch = c & 31;
        cp_async16(kb + r * FROW2 + ch * 16,
                   (const char*)K2g + (size_t)r * (HD2 * 2) + ch * 16);
    }
    uint32_t vb = sb + OFF_VS + buf * (64 * FROWV);
    for (int c = t; c < 64 * 16; c += 256) {
        int r = c >> 4, ch = c & 15;
        cp_async16(vb + r * FROWV + ch * 16,
                   (const char*)Vg + (size_t)r * (HEADD * 2) + ch * 16);
    }
    cp_commit();
}

__global__ void __launch_bounds__(256) flash2(
    const __nv_bfloat16* __restrict__ Q2,
    const __nv_bfloat16* __restrict__ K2g,
    const __half* __restrict__ Vf,
    __half* __restrict__ A2out)
{
    extern __shared__ char smraw[];
    const uint32_t sb = smem_u32(smraw);
    float* Ss  = (float*)(smraw + OFF_SS);
    __half* Ps = (__half*)(smraw + OFF_PS);
    float* mrow = (float*)(smraw + OFF_RW);
    float* lrow = mrow + 64;
    float* srow = lrow + 64;

    const int h  = blockIdx.x;
    const int qb = (gridDim.y - 1) - blockIdx.y;
    const int q0 = qb * 64;
    const int t = threadIdx.x, wid = t >> 5, lane = t & 31;
    const int wm = (wid >> 2) * 32;
    const int wn = (wid & 3) * 16;
    const int wnv = (wid & 3) * 32;
    const int rA = lane & 15, selA = lane >> 4;
    const int rB = ((lane >> 4) << 3) | (lane & 7), selB = (lane >> 3) & 1;
    const int er = lane >> 2, ec = (lane & 3) << 1;

    const __nv_bfloat16* Qg = Q2 + ((size_t)h * S_LEN + q0) * HD2;
    for (int c = t; c < 64 * 32; c += 256) {
        int r = c >> 5, ch = c & 31;
        cp_async16(sb + r * FROW2 + ch * 16,
                   (const char*)Qg + (size_t)r * (HD2 * 2) + ch * 16);
    }
    cp_commit();
    if (t < 64) { mrow[t] = NEG_BIG; lrow[t] = 0.0f; }

    f_load_kv(sb, 0, K2g + ((size_t)h * S_LEN) * HD2,
              Vf + ((size_t)h * S_LEN) * HEADD, t);

    float oacc[2][4][4];
#pragma unroll
    for (int mi = 0; mi < 2; ++mi)
#pragma unroll
        for (int nj = 0; nj < 4; ++nj)
#pragma unroll
            for (int q = 0; q < 4; ++q) oacc[mi][nj][q] = 0.0f;

    for (int kb = 0; kb <= qb; ++kb) {
        const int buf = kb & 1;
        cp_wait<0>();
        __syncthreads();

        if (kb + 1 <= qb)
            f_load_kv(sb, buf ^ 1,
                      K2g + ((size_t)h * S_LEN + (kb + 1) * 64) * HD2,
                      Vf + ((size_t)h * S_LEN + (kb + 1) * 64) * HEADD, t);

        const uint32_t kbase = sb + OFF_K2S + buf * (64 * FROW2);
        const uint32_t vbase = sb + OFF_VS + buf * (64 * FROWV);

        float sacc[2][2][4];
#pragma unroll
        for (int mi = 0; mi < 2; ++mi)
#pragma unroll
            for (int nj = 0; nj < 2; ++nj)
#pragma unroll
                for (int q = 0; q < 4; ++q) sacc[mi][nj][q] = 0.0f;

        const uint32_t sAoff[3] = {0u, 0u, 256u};
        const uint32_t sBoff[3] = {0u, 256u, 0u};
#pragma unroll
        for (int ps = 0; ps < 3; ++ps) {
#pragma unroll
            for (int k16 = 0; k16 < 8; ++k16) {
                uint32_t a[2][4], b[4];
#pragma unroll
                for (int mi = 0; mi < 2; ++mi)
                    ldsm_x4(a[mi][0], a[mi][1], a[mi][2], a[mi][3],
                            sb + (uint32_t)((wm + mi * 16 + rA) * FROW2)
                               + sAoff[ps] + k16 * 32 + selA * 16);
                ldsm_x4(b[0], b[1], b[2], b[3],
                        kbase + (uint32_t)((wn + rB) * FROW2)
                              + sBoff[ps] + k16 * 32 + selB * 16);
#pragma unroll
                for (int mi = 0; mi < 2; ++mi)
#pragma unroll
                    for (int nj = 0; nj < 2; ++nj)
                        mma16816(sacc[mi][nj], a[mi], &b[nj << 1]);
            }
        }

        const bool diag = (kb == qb);
#pragma unroll
        for (int mi = 0; mi < 2; ++mi) {
#pragma unroll
            for (int nj = 0; nj < 2; ++nj) {
                int row = wm + mi * 16 + er;
                int col = wn + nj * 8 + ec;
                float v0 = sacc[mi][nj][0], v1 = sacc[mi][nj][1];
                float v2 = sacc[mi][nj][2], v3 = sacc[mi][nj][3];
                if (diag) {
                    if (col > row)     v0 = NEG_BIG;
                    if (col + 1 > row) v1 = NEG_BIG;
                    if (col > row + 8)     v2 = NEG_BIG;
                    if (col + 1 > row + 8) v3 = NEG_BIG;
                }
                Ss[row * 68 + col]       = v0;
                Ss[row * 68 + col + 1]   = v1;
                Ss[(row + 8) * 68 + col]     = v2;
                Ss[(row + 8) * 68 + col + 1] = v3;
            }
        }
        __syncthreads();

        {
            int r  = t >> 2;
            int qd = t & 3;
            float* srw = &Ss[r * 68 + qd * 16];
            __half* prw = &Ps[r * 72 + qd * 16];
            float vals[16];
            float mx = NEG_BIG;
#pragma unroll
            for (int i = 0; i < 16; ++i) { vals[i] = srw[i]; mx = fmaxf(mx, vals[i]); }
            mx = fmaxf(mx, __shfl_xor_sync(0xffffffffu, mx, 1));
            mx = fmaxf(mx, __shfl_xor_sync(0xffffffffu, mx, 2));
            float mold = mrow[r];
            float mnew = fmaxf(mold, mx);
            float sum = 0.0f;
#pragma unroll
            for (int i = 0; i < 16; ++i) {
                float p = __expf(vals[i] - mnew);
                prw[i] = __float2half_rn(p);
                sum += p;
            }
            sum += __shfl_xor_sync(0xffffffffu, sum, 1);
            sum += __shfl_xor_sync(0xffffffffu, sum, 2);
            float corr = __expf(mold - mnew);
            if (qd == 0) {
                mrow[r] = mnew;
                lrow[r] = lrow[r] * corr + sum;
                srow[r] = corr;
            }
        }
        __syncthreads();

#pragma unroll
        for (int mi = 0; mi < 2; ++mi) {
            float c0 = srow[wm + mi * 16 + er];
            float c1 = srow[wm + mi * 16 + er + 8];
#pragma unroll
            for (int nj = 0; nj < 4; ++nj) {
                oacc[mi][nj][0] *= c0; oacc[mi][nj][1] *= c0;
                oacc[mi][nj][2] *= c1; oacc[mi][nj][3] *= c1;
            }
        }

        const int vkr = ((lane >> 3) & 1) * 8 + (lane & 7);
        const int vnc = (lane >> 4) * 8;
#pragma unroll
        for (int kk = 0; kk < 4; ++kk) {
            uint32_t a[2][4], b0[4], b1[4];
#pragma unroll
            for (int mi = 0; mi < 2; ++mi)
                ldsm_x4(a[mi][0], a[mi][1], a[mi][2], a[mi][3],
                        sb + OFF_PS + (uint32_t)((wm + mi * 16 + rA) * FROWP)
                           + kk * 32 + selA * 16);
            uint32_t vaddr = vbase + (uint32_t)((kk * 16 + vkr) * FROWV);
            ldsm_x4t(b0[0], b0[1], b0[2], b0[3], vaddr + (wnv + vnc) * 2);
            ldsm_x4t(b1[0], b1[1], b1[2], b1[3], vaddr + (wnv + 16 + vnc) * 2);
#pragma unroll
            for (int mi = 0; mi < 2; ++mi) {
                mma16816f(oacc[mi][0], a[mi], &b0[0]);
                mma16816f(oacc[mi][1], a[mi], &b0[2]);
                mma16816f(oacc[mi][2], a[mi], &b1[0]);
                mma16816f(oacc[mi][3], a[mi], &b1[2]);
            }
        }
    }

    // epilogue: normalize, write fp16 [xh | xh*2^-10] into A2f
#pragma unroll
    for (int mi = 0; mi < 2; ++mi) {
        float l0 = 1.0f / lrow[wm + mi * 16 + er];
        float l1 = 1.0f / lrow[wm + mi * 16 + er + 8];
#pragma unroll
        for (int nj = 0; nj < 4; ++nj) {
            int col = h * HEADD + wnv + nj * 8 + ec;
            size_t r0 = (size_t)(q0 + wm + mi * 16 + er) * KST2 + col;
            size_t r1 = r0 + (size_t)8 * KST2;
            float x0 = oacc[mi][nj][0] * l0, x1 = oacc[mi][nj][1] * l0;
            float y0 = oacc[mi][nj][2] * l1, y1 = oacc[mi][nj][3] * l1;
            *(uint32_t*)(A2out + r0) =
                pkh(__float2half_rn(x0), __float2half_rn(x1));
            *(uint32_t*)(A2out + r0 + KSEG) =
                pkh(__float2half_rn(x0 * SC10), __float2half_rn(x1 * SC10));
            *(uint32_t*)(A2out + r1) =
                pkh(__float2half_rn(y0), __float2half_rn(y1));
            *(uint32_t*)(A2out + r1 + KSEG) =
                pkh(__float2half_rn(y0 * SC10), __float2half_rn(y1 * SC10));
        }
    }
}

// ===========================================================================
// Launch
// ===========================================================================
extern "C" void kernel_launch(void* const* d_in, const int* in_sizes, int n_in,
                              void* d_out, int out_size)
{
    (void)in_sizes; (void)n_in; (void)out_size;

    const float* X   = (const float*)d_in[0];
    const int*   pos = (const int*)d_in[2];
    const float* Wq  = (const float*)d_in[3];
    const float* Wk  = (const float*)d_in[4];
    const float* Wv  = (const float*)d_in[5];
    const float* Wo  = (const float*)d_in[6];
    float* out = (float*)d_out;

    float *Qd, *Kd;
    __nv_bfloat16 *Q2d, *K2d;
    __half *A2fd, *W2qfd, *W2kfd, *W2vfd, *W2ofd, *Vfd;
    cudaGetSymbolAddress((void**)&Qd, g_Q);
    cudaGetSymbolAddress((void**)&Kd, g_K);
    cudaGetSymbolAddress((void**)&A2fd, g_A2f);
    cudaGetSymbolAddress((void**)&W2qfd, g_W2qf);
    cudaGetSymbolAddress((void**)&W2kfd, g_W2kf);
    cudaGetSymbolAddress((void**)&W2vfd, g_W2vf);
    cudaGetSymbolAddress((void**)&W2ofd, g_W2of);
    cudaGetSymbolAddress((void**)&Q2d, g_Q2);
    cudaGetSymbolAddress((void**)&K2d, g_K2a);
    cudaGetSymbolAddress((void**)&Vfd, g_Vf);

    cudaFuncSetAttribute(gemm_qk, cudaFuncAttributeMaxDynamicSharedMemorySize, GSMEM);
    cudaFuncSetAttribute(gemm_f16, cudaFuncAttributeMaxDynamicSharedMemorySize, GSMEM);
    cudaFuncSetAttribute(gemm_f16v, cudaFuncAttributeMaxDynamicSharedMemorySize, GSMEM);
    cudaFuncSetAttribute(flash2, cudaFuncAttributeMaxDynamicSharedMemorySize, FSMEM);

    split_xf<<<(S_LEN * 1024) / 256, 256>>>(X, A2fd, S_LEN * 1024);
    split_wf16<<<(HDIM * 1024) / 256, 256>>>(Wq, W2qfd, HDIM * 1024);
    split_wf16<<<(HDIM * 1024) / 256, 256>>>(Wk, W2kfd, HDIM * 1024);
    split_wf16<<<(HDIM * 1024) / 256, 256>>>(Wv, W2vfd, HDIM * 1024);
    split_wf16<<<(HDIM * 1024) / 256, 256>>>(Wo, W2ofd, HDIM * 1024);

    // Merged Q+K projection (fp16 2-term, 512 CTAs), V projection (fused epi)
    gemm_qk<<<dim3(2 * HDIM / BN, S_LEN / BM), 128, GSMEM>>>(A2fd, W2qfd, W2kfd, Qd, Kd);
    gemm_f16v<<<dim3(HDIM / BN, S_LEN / BM), 128, GSMEM>>>(A2fd, W2vfd, Vfd);

    rope_split_qk<<<(S_LEN * NHEADS * 16) / 256, 256>>>(Qd, Kd, pos, Q2d, K2d);

    flash2<<<dim3(NHEADS, S_LEN / 64), 256, FSMEM>>>(Q2d, K2d, Vfd, A2fd);

    gemm_f16<<<dim3(HDIM / BN, S_LEN / BM), 128, GSMEM>>>(A2fd, W2ofd, out);
}

// round 14
// speedup vs baseline: 1.5546x; 1.2382x over previous
#include <cuda_runtime.h>
#include <cuda_bf16.h>
#include <cuda_fp16.h>
#include <math.h>
#include <stdint.h>

// Problem constants
#define S_LEN  2048
#define HDIM   4096
#define NHEADS 32
#define HEADD  128
#define HD2    256      // Q/K head-dim split storage: [hi(128) | lo(128)]

#define KSEG   4096
#define KST2   8192
#define SC10   0.0009765625f   // 2^-10

// Scratch (device globals)
__device__ float g_Q[S_LEN * HDIM];
__device__ float g_K[S_LEN * HDIM];
__device__ __half        g_A2f[S_LEN * KST2];          // X fp16 [xh | xh*2^-10] / attn out (seg0)
__device__ __half        g_W2qf[HDIM * KST2];          // W fp16 [wh | wl*2^10]
__device__ __half        g_W2kf[HDIM * KST2];
__device__ __half        g_Wvf[HDIM * KSEG];           // plain fp16 weights
__device__ __half        g_Wof[HDIM * KSEG];
__device__ __nv_bfloat16 g_Q2[NHEADS * S_LEN * HD2];   // [h][s][Qh|Ql]
__device__ __nv_bfloat16 g_K2a[NHEADS * S_LEN * HD2];  // [h][s][Kh|Kl]
__device__ __half        g_Vf[NHEADS * S_LEN * HEADD]; // [h][s][128] fp16

// ===========================================================================
// PTX helpers
// ===========================================================================
__device__ __forceinline__ uint32_t smem_u32(const void* p) {
    uint32_t a;
    asm("{ .reg .u64 t; cvta.to.shared.u64 t, %1; cvt.u32.u64 %0, t; }" : "=r"(a) : "l"(p));
    return a;
}
__device__ __forceinline__ void cp_async16(uint32_t dst, const void* src) {
    asm volatile("cp.async.cg.shared.global [%0], [%1], 16;" :: "r"(dst), "l"(src));
}
__device__ __forceinline__ void cp_commit() {
    asm volatile("cp.async.commit_group;" ::: "memory");
}
template <int N> __device__ __forceinline__ void cp_wait() {
    asm volatile("cp.async.wait_group %0;" :: "n"(N) : "memory");
}
__device__ __forceinline__ void ldsm_x4(uint32_t& r0, uint32_t& r1, uint32_t& r2,
                                        uint32_t& r3, uint32_t addr) {
    asm volatile("ldmatrix.sync.aligned.m8n8.x4.shared.b16 {%0,%1,%2,%3}, [%4];"
                 : "=r"(r0), "=r"(r1), "=r"(r2), "=r"(r3) : "r"(addr));
}
__device__ __forceinline__ void ldsm_x4t(uint32_t& r0, uint32_t& r1, uint32_t& r2,
                                         uint32_t& r3, uint32_t addr) {
    asm volatile("ldmatrix.sync.aligned.m8n8.x4.trans.shared.b16 {%0,%1,%2,%3}, [%4];"
                 : "=r"(r0), "=r"(r1), "=r"(r2), "=r"(r3) : "r"(addr));
}
__device__ __forceinline__ void mma16816(float* c, const uint32_t* a, const uint32_t* b) {
    asm volatile(
        "mma.sync.aligned.m16n8k16.row.col.f32.bf16.bf16.f32 "
        "{%0,%1,%2,%3}, {%4,%5,%6,%7}, {%8,%9}, {%0,%1,%2,%3};"
        : "+f"(c[0]), "+f"(c[1]), "+f"(c[2]), "+f"(c[3])
        : "r"(a[0]), "r"(a[1]), "r"(a[2]), "r"(a[3]), "r"(b[0]), "r"(b[1]));
}
__device__ __forceinline__ void mma16816f(float* c, const uint32_t* a, const uint32_t* b) {
    asm volatile(
        "mma.sync.aligned.m16n8k16.row.col.f32.f16.f16.f32 "
        "{%0,%1,%2,%3}, {%4,%5,%6,%7}, {%8,%9}, {%0,%1,%2,%3};"
        : "+f"(c[0]), "+f"(c[1]), "+f"(c[2]), "+f"(c[3])
        : "r"(a[0]), "r"(a[1]), "r"(a[2]), "r"(a[3]), "r"(b[0]), "r"(b[1]));
}

__device__ __forceinline__ uint32_t pkb(__nv_bfloat16 a, __nv_bfloat16 b) {
    __nv_bfloat162 t = __halves2bfloat162(a, b);
    return *reinterpret_cast<uint32_t*>(&t);
}
__device__ __forceinline__ uint32_t pkh(__half a, __half b) {
    __half2 t = __halves2half2(a, b);
    return *reinterpret_cast<uint32_t*>(&t);
}
__device__ __forceinline__ void split2(float x, __nv_bfloat16& h, __nv_bfloat16& l) {
    h = __float2bfloat16_rn(x);
    l = __float2bfloat16_rn(x - __bfloat162float(h));
}

// ===========================================================================
// Split / convert kernels
// ===========================================================================
// X fp32 -> fp16 [xh | xh*2^-10]
__global__ void __launch_bounds__(256) split_xf(const float* __restrict__ src,
                                                __half* __restrict__ dst,
                                                int total4)
{
    int i = blockIdx.x * 256 + threadIdx.x;
    if (i >= total4) return;
    int row = i >> 10;
    int c4  = (i & 1023) << 2;
    float4 v = ((const float4*)src)[i];
    float in[4] = {v.x, v.y, v.z, v.w};
    __half f[4], fs[4];
#pragma unroll
    for (int j = 0; j < 4; ++j) {
        f[j]  = __float2half_rn(in[j]);
        fs[j] = __float2half_rn(in[j] * SC10);
    }
    size_t b = (size_t)row * KST2 + c4;
    *(uint2*)(dst + b)        = make_uint2(pkh(f[0], f[1]), pkh(f[2], f[3]));
    *(uint2*)(dst + b + KSEG) = make_uint2(pkh(fs[0], fs[1]), pkh(fs[2], fs[3]));
}

// W fp32 -> fp16 [wh | wl*2^10]  (2-term, for Q/K)
__global__ void __launch_bounds__(256) split_wf16(const float* __restrict__ src,
                                                  __half* __restrict__ dst,
                                                  int total4)
{
    int i = blockIdx.x * 256 + threadIdx.x;
    if (i >= total4) return;
    int row = i >> 10;
    int c4  = (i & 1023) << 2;
    float4 v = ((const float4*)src)[i];
    float in[4] = {v.x, v.y, v.z, v.w};
    __half h[4], l[4];
#pragma unroll
    for (int j = 0; j < 4; ++j) {
        h[j] = __float2half_rn(in[j]);
        l[j] = __float2half_rn((in[j] - __half2float(h[j])) * 1024.0f);
    }
    size_t b = (size_t)row * KST2 + c4;
    *(uint2*)(dst + b)        = make_uint2(pkh(h[0], h[1]), pkh(h[2], h[3]));
    *(uint2*)(dst + b + KSEG) = make_uint2(pkh(l[0], l[1]), pkh(l[2], l[3]));
}

// W fp32 -> plain fp16 (for V/O)
__global__ void __launch_bounds__(256) conv_wf(const float* __restrict__ src,
                                               __half* __restrict__ dst,
                                               int total4)
{
    int i = blockIdx.x * 256 + threadIdx.x;
    if (i >= total4) return;
    int row = i >> 10;
    int c4  = (i & 1023) << 2;
    float4 v = ((const float4*)src)[i];
    *(uint2*)(dst + (size_t)row * KSEG + c4) =
        make_uint2(pkh(__float2half_rn(v.x), __float2half_rn(v.y)),
                   pkh(__float2half_rn(v.z), __float2half_rn(v.w)));
}

// ===========================================================================
// GEMM common: CTA 128x128, BK=32, 128 threads (2x2 warps, 64x64/warp),
// 4-stage cp.async, 2 CTAs/SM.
// ===========================================================================
#define BM 128
#define BN 128
#define BK 32
#define NITERF  256    // 2-segment fp16 (Q/K)
#define NITERP  128    // plain fp16 (V/O)
#define GSTAGES 4
#define ROWB    80
#define ASZ     (BM * ROWB)
#define STAGE   (2 * ASZ)
#define GSMEM   (GSTAGES * STAGE)

// 2-segment loader: A/B strides KST2, seg offset on both
__device__ __forceinline__ void g_load_stage_f(uint32_t sb,
                                               const __half* __restrict__ A2,
                                               const __half* __restrict__ B2,
                                               int m0, int n0, int j, int t)
{
    const int off  = (j >> 7) ? KSEG : 0;
    const int kloc = (j & 127) * BK;
#pragma unroll
    for (int i = 0; i < 4; ++i) {
        int c   = t + (i << 7);
        int row = c >> 2;
        int kc  = c & 3;
        cp_async16(sb + row * ROWB + kc * 16,
                   A2 + (size_t)(m0 + row) * KST2 + off + kloc + kc * 8);
    }
#pragma unroll
    for (int i = 0; i < 4; ++i) {
        int c   = t + (i << 7);
        int row = c >> 2;
        int kc  = c & 3;
        cp_async16(sb + ASZ + row * ROWB + kc * 16,
                   B2 + (size_t)(n0 + row) * KST2 + off + kloc + kc * 8);
    }
    cp_commit();
}

// plain loader: A stride KST2 (seg0 only), B stride KSEG
__device__ __forceinline__ void g_load_stage_p(uint32_t sb,
                                               const __half* __restrict__ A2,
                                               const __half* __restrict__ B2,
                                               int m0, int n0, int j, int t)
{
    const int kloc = j * BK;
#pragma unroll
    for (int i = 0; i < 4; ++i) {
        int c   = t + (i << 7);
        int row = c >> 2;
        int kc  = c & 3;
        cp_async16(sb + row * ROWB + kc * 16,
                   A2 + (size_t)(m0 + row) * KST2 + kloc + kc * 8);
    }
#pragma unroll
    for (int i = 0; i < 4; ++i) {
        int c   = t + (i << 7);
        int row = c >> 2;
        int kc  = c & 3;
        cp_async16(sb + ASZ + row * ROWB + kc * 16,
                   B2 + (size_t)(n0 + row) * KSEG + kloc + kc * 8);
    }
    cp_commit();
}

#define GEMM_BODY_GEN(LOADFN, NITERS, APTR, BPTR)                             \
    float acc[4][8][4];                                                       \
    _Pragma("unroll")                                                         \
    for (int mi = 0; mi < 4; ++mi)                                            \
        _Pragma("unroll")                                                     \
        for (int nj = 0; nj < 8; ++nj)                                        \
            _Pragma("unroll")                                                 \
            for (int q = 0; q < 4; ++q) acc[mi][nj][q] = 0.0f;                \
    _Pragma("unroll")                                                         \
    for (int it = 0; it < GSTAGES - 1; ++it)                                  \
        LOADFN(base + it * STAGE, APTR, BPTR, m0, n0, it, t);                 \
    for (int it = 0; it < NITERS; ++it) {                                     \
        const int st = it & (GSTAGES - 1);                                    \
        cp_wait<GSTAGES - 2>();                                               \
        __syncthreads();                                                      \
        const uint32_t stA = base + st * STAGE;                               \
        const uint32_t stB = stA + ASZ;                                       \
        _Pragma("unroll")                                                     \
        for (int kh = 0; kh < 2; ++kh) {                                      \
            uint32_t a[4][4];                                                 \
            _Pragma("unroll")                                                 \
            for (int mi = 0; mi < 4; ++mi)                                    \
                ldsm_x4(a[mi][0], a[mi][1], a[mi][2], a[mi][3],               \
                        stA + (uint32_t)((wm + mi * 16 + rA) * ROWB           \
                                         + (kh * 2 + selA) * 16));            \
            uint32_t b[4][4];                                                 \
            _Pragma("unroll")                                                 \
            for (int p = 0; p < 4; ++p)                                       \
                ldsm_x4(b[p][0], b[p][1], b[p][2], b[p][3],                   \
                        stB + (uint32_t)((wn + p * 16 + rB) * ROWB            \
                                         + (kh * 2 + selB) * 16));            \
            _Pragma("unroll")                                                 \
            for (int mi = 0; mi < 4; ++mi) {                                  \
                _Pragma("unroll")                                             \
                for (int p = 0; p < 4; ++p) {                                 \
                    mma16816f(acc[mi][2 * p],     a[mi], &b[p][0]);           \
                    mma16816f(acc[mi][2 * p + 1], a[mi], &b[p][2]);           \
                }                                                             \
            }                                                                 \
        }                                                                     \
        const int j = it + GSTAGES - 1;                                       \
        if (j < NITERS)                                                       \
            LOADFN(base + (j & (GSTAGES - 1)) * STAGE, APTR, BPTR,            \
                   m0, n0, j, t);                                             \
    }

#define GEMM_PROLOG_COMMON                                                    \
    extern __shared__ char smraw[];                                           \
    const uint32_t base = smem_u32(smraw);                                    \
    const int t    = threadIdx.x;                                             \
    const int wid  = t >> 5;                                                  \
    const int lane = t & 31;                                                  \
    const int m0   = blockIdx.y * BM;                                         \
    const int wm   = (wid >> 1) * 64;                                         \
    const int wn   = (wid & 1) * 64;                                          \
    const int rA   = lane & 15;                                               \
    const int selA = lane >> 4;                                               \
    const int rB   = ((lane >> 4) << 3) | (lane & 7);                         \
    const int selB = (lane >> 3) & 1;

// Merged Q+K projection (fp16 2-term): grid.x covers 2*HDIM
__global__ void __launch_bounds__(128, 2)
gemm_qk(const __half* __restrict__ A2,
        const __half* __restrict__ Bq,
        const __half* __restrict__ Bk,
        float* __restrict__ Cq,
        float* __restrict__ Ck)
{
    GEMM_PROLOG_COMMON
    const int n0g = blockIdx.x * BN;
    const __half* B2 = (n0g < HDIM) ? Bq : Bk;
    float* C = (n0g < HDIM) ? Cq : Ck;
    const int n0 = n0g & (HDIM - 1);

    GEMM_BODY_GEN(g_load_stage_f, NITERF, A2, B2)

    const int er = lane >> 2;
    const int ec = (lane & 3) << 1;
#pragma unroll
    for (int mi = 0; mi < 4; ++mi) {
#pragma unroll
        for (int nj = 0; nj < 8; ++nj) {
            size_t r0 = (size_t)(m0 + wm + mi * 16 + er) * HDIM
                        + (n0 + wn + nj * 8 + ec);
            *(float2*)&C[r0]            = make_float2(acc[mi][nj][0], acc[mi][nj][1]);
            *(float2*)&C[r0 + 8 * HDIM] = make_float2(acc[mi][nj][2], acc[mi][nj][3]);
        }
    }
}

// Plain fp16 GEMM, fp32 output (O projection)
__global__ void __launch_bounds__(128, 2)
gemm_f16o(const __half* __restrict__ A2,
          const __half* __restrict__ B2,
          float* __restrict__ C)
{
    GEMM_PROLOG_COMMON
    const int n0 = blockIdx.x * BN;
    GEMM_BODY_GEN(g_load_stage_p, NITERP, A2, B2)

    const int er = lane >> 2;
    const int ec = (lane & 3) << 1;
#pragma unroll
    for (int mi = 0; mi < 4; ++mi) {
#pragma unroll
        for (int nj = 0; nj < 8; ++nj) {
            size_t r0 = (size_t)(m0 + wm + mi * 16 + er) * HDIM
                        + (n0 + wn + nj * 8 + ec);
            *(float2*)&C[r0]            = make_float2(acc[mi][nj][0], acc[mi][nj][1]);
            *(float2*)&C[r0 + 8 * HDIM] = make_float2(acc[mi][nj][2], acc[mi][nj][3]);
        }
    }
}

// Plain fp16 GEMM, fused V epilogue: writes fp16 g_Vf [h][s][128]
__global__ void __launch_bounds__(128, 2)
gemm_f16v(const __half* __restrict__ A2,
          const __half* __restrict__ B2,
          __half* __restrict__ Vf)
{
    GEMM_PROLOG_COMMON
    const int n0 = blockIdx.x * BN;
    GEMM_BODY_GEN(g_load_stage_p, NITERP, A2, B2)

    const int er = lane >> 2;
    const int ec = (lane & 3) << 1;
#pragma unroll
    for (int mi = 0; mi < 4; ++mi) {
        int s0 = m0 + wm + mi * 16 + er;
#pragma unroll
        for (int nj = 0; nj < 8; ++nj) {
            int col = n0 + wn + nj * 8 + ec;
            int h   = col >> 7;
            int hc  = col & 127;
            size_t b0 = ((size_t)h * S_LEN + s0) * HEADD + hc;
            size_t b1 = ((size_t)h * S_LEN + s0 + 8) * HEADD + hc;
            *(uint32_t*)(Vf + b0) = pkh(__float2half_rn(acc[mi][nj][0]),
                                        __float2half_rn(acc[mi][nj][1]));
            *(uint32_t*)(Vf + b1) = pkh(__float2half_rn(acc[mi][nj][2]),
                                        __float2half_rn(acc[mi][nj][3]));
        }
    }
}

// ===========================================================================
// Fused RoPE + head-dim split (validated)
// ===========================================================================
#define ATT_SCALE 0.08838834764831843f

__global__ void __launch_bounds__(256) rope_split_qk(
    const float* __restrict__ Q, const float* __restrict__ K,
    const int* __restrict__ pos,
    __nv_bfloat16* __restrict__ Q2, __nv_bfloat16* __restrict__ K2o)
{
    int idx = blockIdx.x * 256 + threadIdx.x;
    if (idx >= S_LEN * NHEADS * 16) return;
    int j4 = (idx & 15) << 2;
    int h  = (idx >> 4) & (NHEADS - 1);
    int s  = idx >> 9;
    int p  = pos[s];

    float sn[4], cs[4];
#pragma unroll
    for (int i = 0; i < 4; ++i) {
        float inv = 1.0f / powf(10000.0f, (float)(j4 + i) * (1.0f / 64.0f));
        sincosf((float)p * inv, &sn[i], &cs[i]);
    }

    size_t gb = (size_t)s * HDIM + (size_t)h * HEADD + j4;
    float4 qa4 = *(const float4*)&Q[gb];
    float4 qb4 = *(const float4*)&Q[gb + 64];
    float4 ka4 = *(const float4*)&K[gb];
    float4 kb4 = *(const float4*)&K[gb + 64];
    float qa[4] = {qa4.x, qa4.y, qa4.z, qa4.w};
    float qb[4] = {qb4.x, qb4.y, qb4.z, qb4.w};
    float ka[4] = {ka4.x, ka4.y, ka4.z, ka4.w};
    float kb[4] = {kb4.x, kb4.y, kb4.z, kb4.w};

    __nv_bfloat16 qah[4], qal[4], qbh[4], qbl[4];
    __nv_bfloat16 kah[4], kal[4], kbh[4], kbl[4];
#pragma unroll
    for (int i = 0; i < 4; ++i) {
        float r1 = (qa[i] * cs[i] - qb[i] * sn[i]) * ATT_SCALE;
        float r2 = (qb[i] * cs[i] + qa[i] * sn[i]) * ATT_SCALE;
        split2(r1, qah[i], qal[i]);
        split2(r2, qbh[i], qbl[i]);
        float t1 = ka[i] * cs[i] - kb[i] * sn[i];
        float t2 = kb[i] * cs[i] + ka[i] * sn[i];
        split2(t1, kah[i], kal[i]);
        split2(t2, kbh[i], kbl[i]);
    }

    size_t ob = ((size_t)h * S_LEN + s) * HD2 + j4;
    *(uint2*)(Q2 + ob)       = make_uint2(pkb(qah[0], qah[1]), pkb(qah[2], qah[3]));
    *(uint2*)(Q2 + ob + 64)  = make_uint2(pkb(qbh[0], qbh[1]), pkb(qbh[2], qbh[3]));
    *(uint2*)(Q2 + ob + 128) = make_uint2(pkb(qal[0], qal[1]), pkb(qal[2], qal[3]));
    *(uint2*)(Q2 + ob + 192) = make_uint2(pkb(qbl[0], qbl[1]), pkb(qbl[2], qbl[3]));

    *(uint2*)(K2o + ob)       = make_uint2(pkb(kah[0], kah[1]), pkb(kah[2], kah[3]));
    *(uint2*)(K2o + ob + 64)  = make_uint2(pkb(kbh[0], kbh[1]), pkb(kbh[2], kbh[3]));
    *(uint2*)(K2o + ob + 128) = make_uint2(pkb(kal[0], kal[1]), pkb(kal[2], kal[3]));
    *(uint2*)(K2o + ob + 192) = make_uint2(pkb(kbl[0], kbl[1]), pkb(kbl[2], kbl[3]));
}

// ===========================================================================
// Flash attention v5 (validated R12/R13): 256 threads.
// Scores bf16 3-pass split; fp32 softmax -> fp16 P; PV single-pass fp16.
// Epilogue writes only seg0 fp16 (O-proj is plain now).
// ===========================================================================
#define NEG_BIG (-3.0e38f)
#define FROW2  528
#define FROWV  272
#define FROWP  144
#define OFF_K2S  (64 * FROW2)
#define OFF_VS   (OFF_K2S + 2 * 64 * FROW2)
#define OFF_SS   (OFF_VS + 2 * 64 * FROWV)
#define OFF_PS   (OFF_SS + 64 * 68 * 4)
#define OFF_RW   (OFF_PS + 64 * FROWP)
#define FSMEM    (OFF_RW + 3 * 64 * 4)

__device__ __forceinline__ void f_load_kv(uint32_t sb, int buf,
                                          const __nv_bfloat16* __restrict__ K2g,
                                          const __half* __restrict__ Vg,
                                          int t)
{
    uint32_t kb = sb + OFF_K2S + buf * (64 * FROW2);
    for (int c = t; c < 64 * 32; c += 256) {
        int r = c >> 5, ch = c & 31;
        cp_async16(kb + r * FROW2 + ch * 16,
                   (const char*)K2g + (size_t)r * (HD2 * 2) + ch * 16);
    }
    uint32_t vb = sb + OFF_VS + buf * (64 * FROWV);
    for (int c = t; c < 64 * 16; c += 256) {
        int r = c >> 4, ch = c & 15;
        cp_async16(vb + r * FROWV + ch * 16,
                   (const char*)Vg + (size_t)r * (HEADD * 2) + ch * 16);
    }
    cp_commit();
}

__global__ void __launch_bounds__(256) flash2(
    const __nv_bfloat16* __restrict__ Q2,
    const __nv_bfloat16* __restrict__ K2g,
    const __half* __restrict__ Vf,
    __half* __restrict__ A2out)
{
    extern __shared__ char smraw[];
    const uint32_t sb = smem_u32(smraw);
    float* Ss  = (float*)(smraw + OFF_SS);
    __half* Ps = (__half*)(smraw + OFF_PS);
    float* mrow = (float*)(smraw + OFF_RW);
    float* lrow = mrow + 64;
    float* srow = lrow + 64;

    const int h  = blockIdx.x;
    const int qb = (gridDim.y - 1) - blockIdx.y;
    const int q0 = qb * 64;
    const int t = threadIdx.x, wid = t >> 5, lane = t & 31;
    const int wm = (wid >> 2) * 32;
    const int wn = (wid & 3) * 16;
    const int wnv = (wid & 3) * 32;
    const int rA = lane & 15, selA = lane >> 4;
    const int rB = ((lane >> 4) << 3) | (lane & 7), selB = (lane >> 3) & 1;
    const int er = lane >> 2, ec = (lane & 3) << 1;

    const __nv_bfloat16* Qg = Q2 + ((size_t)h * S_LEN + q0) * HD2;
    for (int c = t; c < 64 * 32; c += 256) {
        int r = c >> 5, ch = c & 31;
        cp_async16(sb + r * FROW2 + ch * 16,
                   (const char*)Qg + (size_t)r * (HD2 * 2) + ch * 16);
    }
    cp_commit();
    if (t < 64) { mrow[t] = NEG_BIG; lrow[t] = 0.0f; }

    f_load_kv(sb, 0, K2g + ((size_t)h * S_LEN) * HD2,
              Vf + ((size_t)h * S_LEN) * HEADD, t);

    float oacc[2][4][4];
#pragma unroll
    for (int mi = 0; mi < 2; ++mi)
#pragma unroll
        for (int nj = 0; nj < 4; ++nj)
#pragma unroll
            for (int q = 0; q < 4; ++q) oacc[mi][nj][q] = 0.0f;

    for (int kb = 0; kb <= qb; ++kb) {
        const int buf = kb & 1;
        cp_wait<0>();
        __syncthreads();

        if (kb + 1 <= qb)
            f_load_kv(sb, buf ^ 1,
                      K2g + ((size_t)h * S_LEN + (kb + 1) * 64) * HD2,
                      Vf + ((size_t)h * S_LEN + (kb + 1) * 64) * HEADD, t);

        const uint32_t kbase = sb + OFF_K2S + buf * (64 * FROW2);
        const uint32_t vbase = sb + OFF_VS + buf * (64 * FROWV);

        float sacc[2][2][4];
#pragma unroll
        for (int mi = 0; mi < 2; ++mi)
#pragma unroll
            for (int nj = 0; nj < 2; ++nj)
#pragma unroll
                for (int q = 0; q < 4; ++q) sacc[mi][nj][q] = 0.0f;

        const uint32_t sAoff[3] = {0u, 0u, 256u};
        const uint32_t sBoff[3] = {0u, 256u, 0u};
#pragma unroll
        for (int ps = 0; ps < 3; ++ps) {
#pragma unroll
            for (int k16 = 0; k16 < 8; ++k16) {
                uint32_t a[2][4], b[4];
#pragma unroll
                for (int mi = 0; mi < 2; ++mi)
                    ldsm_x4(a[mi][0], a[mi][1], a[mi][2], a[mi][3],
                            sb + (uint32_t)((wm + mi * 16 + rA) * FROW2)
                               + sAoff[ps] + k16 * 32 + selA * 16);
                ldsm_x4(b[0], b[1], b[2], b[3],
                        kbase + (uint32_t)((wn + rB) * FROW2)
                              + sBoff[ps] + k16 * 32 + selB * 16);
#pragma unroll
                for (int mi = 0; mi < 2; ++mi)
#pragma unroll
                    for (int nj = 0; nj < 2; ++nj)
                        mma16816(sacc[mi][nj], a[mi], &b[nj << 1]);
            }
        }

        const bool diag = (kb == qb);
#pragma unroll
        for (int mi = 0; mi < 2; ++mi) {
#pragma unroll
            for (int nj = 0; nj < 2; ++nj) {
                int row = wm + mi * 16 + er;
                int col = wn + nj * 8 + ec;
                float v0 = sacc[mi][nj][0], v1 = sacc[mi][nj][1];
                float v2 = sacc[mi][nj][2], v3 = sacc[mi][nj][3];
                if (diag) {
                    if (col > row)     v0 = NEG_BIG;
                    if (col + 1 > row) v1 = NEG_BIG;
                    if (col > row + 8)     v2 = NEG_BIG;
                    if (col + 1 > row + 8) v3 = NEG_BIG;
                }
                Ss[row * 68 + col]       = v0;
                Ss[row * 68 + col + 1]   = v1;
                Ss[(row + 8) * 68 + col]     = v2;
                Ss[(row + 8) * 68 + col + 1] = v3;
            }
        }
        __syncthreads();

        {
            int r  = t >> 2;
            int qd = t & 3;
            float* srw = &Ss[r * 68 + qd * 16];
            __half* prw = &Ps[r * 72 + qd * 16];
            float vals[16];
            float mx = NEG_BIG;
#pragma unroll
            for (int i = 0; i < 16; ++i) { vals[i] = srw[i]; mx = fmaxf(mx, vals[i]); }
            mx = fmaxf(mx, __shfl_xor_sync(0xffffffffu, mx, 1));
            mx = fmaxf(mx, __shfl_xor_sync(0xffffffffu, mx, 2));
            float mold = mrow[r];
            float mnew = fmaxf(mold, mx);
            float sum = 0.0f;
#pragma unroll
            for (int i = 0; i < 16; ++i) {
                float p = __expf(vals[i] - mnew);
                prw[i] = __float2half_rn(p);
                sum += p;
            }
            sum += __shfl_xor_sync(0xffffffffu, sum, 1);
            sum += __shfl_xor_sync(0xffffffffu, sum, 2);
            float corr = __expf(mold - mnew);
            if (qd == 0) {
                mrow[r] = mnew;
                lrow[r] = lrow[r] * corr + sum;
                srow[r] = corr;
            }
        }
        __syncthreads();

#pragma unroll
        for (int mi = 0; mi < 2; ++mi) {
            float c0 = srow[wm + mi * 16 + er];
            float c1 = srow[wm + mi * 16 + er + 8];
#pragma unroll
            for (int nj = 0; nj < 4; ++nj) {
                oacc[mi][nj][0] *= c0; oacc[mi][nj][1] *= c0;
                oacc[mi][nj][2] *= c1; oacc[mi][nj][3] *= c1;
            }
        }

        const int vkr = ((lane >> 3) & 1) * 8 + (lane & 7);
        const int vnc = (lane >> 4) * 8;
#pragma unroll
        for (int kk = 0; kk < 4; ++kk) {
            uint32_t a[2][4], b0[4], b1[4];
#pragma unroll
            for (int mi = 0; mi < 2; ++mi)
                ldsm_x4(a[mi][0], a[mi][1], a[mi][2], a[mi][3],
                        sb + OFF_PS + (uint32_t)((wm + mi * 16 + rA) * FROWP)
                           + kk * 32 + selA * 16);
            uint32_t vaddr = vbase + (uint32_t)((kk * 16 + vkr) * FROWV);
            ldsm_x4t(b0[0], b0[1], b0[2], b0[3], vaddr + (wnv + vnc) * 2);
            ldsm_x4t(b1[0], b1[1], b1[2], b1[3], vaddr + (wnv + 16 + vnc) * 2);
#pragma unroll
            for (int mi = 0; mi < 2; ++mi) {
                mma16816f(oacc[mi][0], a[mi], &b0[0]);
                mma16816f(oacc[mi][1], a[mi], &b0[2]);
                mma16816f(oacc[mi][2], a[mi], &b1[0]);
                mma16816f(oacc[mi][3], a[mi], &b1[2]);
            }
        }
    }

    // epilogue: normalize, write plain fp16 (seg0 only — O-proj is plain)
#pragma unroll
    for (int mi = 0; mi < 2; ++mi) {
        float l0 = 1.0f / lrow[wm + mi * 16 + er];
        float l1 = 1.0f / lrow[wm + mi * 16 + er + 8];
#pragma unroll
        for (int nj = 0; nj < 4; ++nj) {
            int col = h * HEADD + wnv + nj * 8 + ec;
            size_t r0 = (size_t)(q0 + wm + mi * 16 + er) * KST2 + col;
            size_t r1 = r0 + (size_t)8 * KST2;
            float x0 = oacc[mi][nj][0] * l0, x1 = oacc[mi][nj][1] * l0;
            float y0 = oacc[mi][nj][2] * l1, y1 = oacc[mi][nj][3] * l1;
            *(uint32_t*)(A2out + r0) =
                pkh(__float2half_rn(x0), __float2half_rn(x1));
            *(uint32_t*)(A2out + r1) =
                pkh(__float2half_rn(y0), __float2half_rn(y1));
        }
    }
}

// ===========================================================================
// Launch
// ===========================================================================
extern "C" void kernel_launch(void* const* d_in, const int* in_sizes, int n_in,
                              void* d_out, int out_size)
{
    (void)in_sizes; (void)n_in; (void)out_size;

    const float* X   = (const float*)d_in[0];
    const int*   pos = (const int*)d_in[2];
    const float* Wq  = (const float*)d_in[3];
    const float* Wk  = (const float*)d_in[4];
    const float* Wv  = (const float*)d_in[5];
    const float* Wo  = (const float*)d_in[6];
    float* out = (float*)d_out;

    float *Qd, *Kd;
    __nv_bfloat16 *Q2d, *K2d;
    __half *A2fd, *W2qfd, *W2kfd, *Wvfd, *Wofd, *Vfd;
    cudaGetSymbolAddress((void**)&Qd, g_Q);
    cudaGetSymbolAddress((void**)&Kd, g_K);
    cudaGetSymbolAddress((void**)&A2fd, g_A2f);
    cudaGetSymbolAddress((void**)&W2qfd, g_W2qf);
    cudaGetSymbolAddress((void**)&W2kfd, g_W2kf);
    cudaGetSymbolAddress((void**)&Wvfd, g_Wvf);
    cudaGetSymbolAddress((void**)&Wofd, g_Wof);
    cudaGetSymbolAddress((void**)&Q2d, g_Q2);
    cudaGetSymbolAddress((void**)&K2d, g_K2a);
    cudaGetSymbolAddress((void**)&Vfd, g_Vf);

    cudaFuncSetAttribute(gemm_qk, cudaFuncAttributeMaxDynamicSharedMemorySize, GSMEM);
    cudaFuncSetAttribute(gemm_f16o, cudaFuncAttributeMaxDynamicSharedMemorySize, GSMEM);
    cudaFuncSetAttribute(gemm_f16v, cudaFuncAttributeMaxDynamicSharedMemorySize, GSMEM);
    cudaFuncSetAttribute(flash2, cudaFuncAttributeMaxDynamicSharedMemorySize, FSMEM);

    split_xf<<<(S_LEN * 1024) / 256, 256>>>(X, A2fd, S_LEN * 1024);
    split_wf16<<<(HDIM * 1024) / 256, 256>>>(Wq, W2qfd, HDIM * 1024);
    split_wf16<<<(HDIM * 1024) / 256, 256>>>(Wk, W2kfd, HDIM * 1024);
    conv_wf<<<(HDIM * 1024) / 256, 256>>>(Wv, Wvfd, HDIM * 1024);
    conv_wf<<<(HDIM * 1024) / 256, 256>>>(Wo, Wofd, HDIM * 1024);

    // Q+K projection (fp16 2-term, 512 CTAs); V projection plain fp16
    gemm_qk<<<dim3(2 * HDIM / BN, S_LEN / BM), 128, GSMEM>>>(A2fd, W2qfd, W2kfd, Qd, Kd);
    gemm_f16v<<<dim3(HDIM / BN, S_LEN / BM), 128, GSMEM>>>(A2fd, Wvfd, Vfd);

    rope_split_qk<<<(S_LEN * NHEADS * 16) / 256, 256>>>(Qd, Kd, pos, Q2d, K2d);

    flash2<<<dim3(NHEADS, S_LEN / 64), 256, FSMEM>>>(Q2d, K2d, Vfd, A2fd);

    // O projection plain fp16
    gemm_f16o<<<dim3(HDIM / BN, S_LEN / BM), 128, GSMEM>>>(A2fd, Wofd, out);
}

// round 15
// speedup vs baseline: 1.6725x; 1.0758x over previous
#include <cuda_runtime.h>
#include <cuda_bf16.h>
#include <cuda_fp16.h>
#include <math.h>
#include <stdint.h>

// Problem constants
#define S_LEN  2048
#define HDIM   4096
#define NHEADS 32
#define HEADD  128
#define HD2    256      // Q/K head-dim split storage: [seg0(128) | seg1(128)]

#define KSEG   4096
#define KST2   8192
#define SC10   0.0009765625f   // 2^-10

// Scratch (device globals)
__device__ float g_Q[S_LEN * HDIM];
__device__ float g_K[S_LEN * HDIM];
__device__ __half g_A2f[S_LEN * KST2];          // X fp16 [xh | xh*2^-10] / attn out (seg0)
__device__ __half g_W2qf[HDIM * KST2];          // W fp16 [wh | wl*2^10]
__device__ __half g_W2kf[HDIM * KST2];
__device__ __half g_Wvf[HDIM * KSEG];           // plain fp16 weights
__device__ __half g_Wof[HDIM * KSEG];
__device__ __half g_Q2f[NHEADS * S_LEN * HD2];  // [h][s][qh*s | qh*s*2^-10]
__device__ __half g_K2f[NHEADS * S_LEN * HD2];  // [h][s][kh   | kl*2^10]
__device__ __half g_Vf[NHEADS * S_LEN * HEADD]; // [h][s][128] fp16

// ===========================================================================
// PTX helpers
// ===========================================================================
__device__ __forceinline__ uint32_t smem_u32(const void* p) {
    uint32_t a;
    asm("{ .reg .u64 t; cvta.to.shared.u64 t, %1; cvt.u32.u64 %0, t; }" : "=r"(a) : "l"(p));
    return a;
}
__device__ __forceinline__ void cp_async16(uint32_t dst, const void* src) {
    asm volatile("cp.async.cg.shared.global [%0], [%1], 16;" :: "r"(dst), "l"(src));
}
__device__ __forceinline__ void cp_commit() {
    asm volatile("cp.async.commit_group;" ::: "memory");
}
template <int N> __device__ __forceinline__ void cp_wait() {
    asm volatile("cp.async.wait_group %0;" :: "n"(N) : "memory");
}
__device__ __forceinline__ void ldsm_x4(uint32_t& r0, uint32_t& r1, uint32_t& r2,
                                        uint32_t& r3, uint32_t addr) {
    asm volatile("ldmatrix.sync.aligned.m8n8.x4.shared.b16 {%0,%1,%2,%3}, [%4];"
                 : "=r"(r0), "=r"(r1), "=r"(r2), "=r"(r3) : "r"(addr));
}
__device__ __forceinline__ void ldsm_x4t(uint32_t& r0, uint32_t& r1, uint32_t& r2,
                                         uint32_t& r3, uint32_t addr) {
    asm volatile("ldmatrix.sync.aligned.m8n8.x4.trans.shared.b16 {%0,%1,%2,%3}, [%4];"
                 : "=r"(r0), "=r"(r1), "=r"(r2), "=r"(r3) : "r"(addr));
}
__device__ __forceinline__ void mma16816f(float* c, const uint32_t* a, const uint32_t* b) {
    asm volatile(
        "mma.sync.aligned.m16n8k16.row.col.f32.f16.f16.f32 "
        "{%0,%1,%2,%3}, {%4,%5,%6,%7}, {%8,%9}, {%0,%1,%2,%3};"
        : "+f"(c[0]), "+f"(c[1]), "+f"(c[2]), "+f"(c[3])
        : "r"(a[0]), "r"(a[1]), "r"(a[2]), "r"(a[3]), "r"(b[0]), "r"(b[1]));
}

__device__ __forceinline__ uint32_t pkh(__half a, __half b) {
    __half2 t = __halves2half2(a, b);
    return *reinterpret_cast<uint32_t*>(&t);
}

// ===========================================================================
// Split / convert kernels
// ===========================================================================
// X fp32 -> fp16 [xh | xh*2^-10]
__global__ void __launch_bounds__(256) split_xf(const float* __restrict__ src,
                                                __half* __restrict__ dst,
                                                int total4)
{
    int i = blockIdx.x * 256 + threadIdx.x;
    if (i >= total4) return;
    int row = i >> 10;
    int c4  = (i & 1023) << 2;
    float4 v = ((const float4*)src)[i];
    float in[4] = {v.x, v.y, v.z, v.w};
    __half f[4], fs[4];
#pragma unroll
    for (int j = 0; j < 4; ++j) {
        f[j]  = __float2half_rn(in[j]);
        fs[j] = __float2half_rn(in[j] * SC10);
    }
    size_t b = (size_t)row * KST2 + c4;
    *(uint2*)(dst + b)        = make_uint2(pkh(f[0], f[1]), pkh(f[2], f[3]));
    *(uint2*)(dst + b + KSEG) = make_uint2(pkh(fs[0], fs[1]), pkh(fs[2], fs[3]));
}

// W fp32 -> fp16 [wh | wl*2^10]  (2-term, for Q/K)
__global__ void __launch_bounds__(256) split_wf16(const float* __restrict__ src,
                                                  __half* __restrict__ dst,
                                                  int total4)
{
    int i = blockIdx.x * 256 + threadIdx.x;
    if (i >= total4) return;
    int row = i >> 10;
    int c4  = (i & 1023) << 2;
    float4 v = ((const float4*)src)[i];
    float in[4] = {v.x, v.y, v.z, v.w};
    __half h[4], l[4];
#pragma unroll
    for (int j = 0; j < 4; ++j) {
        h[j] = __float2half_rn(in[j]);
        l[j] = __float2half_rn((in[j] - __half2float(h[j])) * 1024.0f);
    }
    size_t b = (size_t)row * KST2 + c4;
    *(uint2*)(dst + b)        = make_uint2(pkh(h[0], h[1]), pkh(h[2], h[3]));
    *(uint2*)(dst + b + KSEG) = make_uint2(pkh(l[0], l[1]), pkh(l[2], l[3]));
}

// W fp32 -> plain fp16 (for V/O)
__global__ void __launch_bounds__(256) conv_wf(const float* __restrict__ src,
                                               __half* __restrict__ dst,
                                               int total4)
{
    int i = blockIdx.x * 256 + threadIdx.x;
    if (i >= total4) return;
    int row = i >> 10;
    int c4  = (i & 1023) << 2;
    float4 v = ((const float4*)src)[i];
    *(uint2*)(dst + (size_t)row * KSEG + c4) =
        make_uint2(pkh(__float2half_rn(v.x), __float2half_rn(v.y)),
                   pkh(__float2half_rn(v.z), __float2half_rn(v.w)));
}

// ===========================================================================
// GEMM common: CTA 128x128, BK=32, 128 threads (2x2 warps, 64x64/warp),
// 4-stage cp.async, 2 CTAs/SM.
// ===========================================================================
#define BM 128
#define BN 128
#define BK 32
#define NITERF  256    // 2-segment fp16 (Q/K)
#define NITERP  128    // plain fp16 (V/O)
#define GSTAGES 4
#define ROWB    80
#define ASZ     (BM * ROWB)
#define STAGE   (2 * ASZ)
#define GSMEM   (GSTAGES * STAGE)

// 2-segment loader: A/B strides KST2, seg offset on both
__device__ __forceinline__ void g_load_stage_f(uint32_t sb,
                                               const __half* __restrict__ A2,
                                               const __half* __restrict__ B2,
                                               int m0, int n0, int j, int t)
{
    const int off  = (j >> 7) ? KSEG : 0;
    const int kloc = (j & 127) * BK;
#pragma unroll
    for (int i = 0; i < 4; ++i) {
        int c   = t + (i << 7);
        int row = c >> 2;
        int kc  = c & 3;
        cp_async16(sb + row * ROWB + kc * 16,
                   A2 + (size_t)(m0 + row) * KST2 + off + kloc + kc * 8);
    }
#pragma unroll
    for (int i = 0; i < 4; ++i) {
        int c   = t + (i << 7);
        int row = c >> 2;
        int kc  = c & 3;
        cp_async16(sb + ASZ + row * ROWB + kc * 16,
                   B2 + (size_t)(n0 + row) * KST2 + off + kloc + kc * 8);
    }
    cp_commit();
}

// plain loader: A stride KST2 (seg0 only), B stride KSEG
__device__ __forceinline__ void g_load_stage_p(uint32_t sb,
                                               const __half* __restrict__ A2,
                                               const __half* __restrict__ B2,
                                               int m0, int n0, int j, int t)
{
    const int kloc = j * BK;
#pragma unroll
    for (int i = 0; i < 4; ++i) {
        int c   = t + (i << 7);
        int row = c >> 2;
        int kc  = c & 3;
        cp_async16(sb + row * ROWB + kc * 16,
                   A2 + (size_t)(m0 + row) * KST2 + kloc + kc * 8);
    }
#pragma unroll
    for (int i = 0; i < 4; ++i) {
        int c   = t + (i << 7);
        int row = c >> 2;
        int kc  = c & 3;
        cp_async16(sb + ASZ + row * ROWB + kc * 16,
                   B2 + (size_t)(n0 + row) * KSEG + kloc + kc * 8);
    }
    cp_commit();
}

#define GEMM_BODY_GEN(LOADFN, NITERS, APTR, BPTR)                             \
    float acc[4][8][4];                                                       \
    _Pragma("unroll")                                                         \
    for (int mi = 0; mi < 4; ++mi)                                            \
        _Pragma("unroll")                                                     \
        for (int nj = 0; nj < 8; ++nj)                                        \
            _Pragma("unroll")                                                 \
            for (int q = 0; q < 4; ++q) acc[mi][nj][q] = 0.0f;                \
    _Pragma("unroll")                                                         \
    for (int it = 0; it < GSTAGES - 1; ++it)                                  \
        LOADFN(base + it * STAGE, APTR, BPTR, m0, n0, it, t);                 \
    for (int it = 0; it < NITERS; ++it) {                                     \
        const int st = it & (GSTAGES - 1);                                    \
        cp_wait<GSTAGES - 2>();                                               \
        __syncthreads();                                                      \
        const uint32_t stA = base + st * STAGE;                               \
        const uint32_t stB = stA + ASZ;                                       \
        _Pragma("unroll")                                                     \
        for (int kh = 0; kh < 2; ++kh) {                                      \
            uint32_t a[4][4];                                                 \
            _Pragma("unroll")                                                 \
            for (int mi = 0; mi < 4; ++mi)                                    \
                ldsm_x4(a[mi][0], a[mi][1], a[mi][2], a[mi][3],               \
                        stA + (uint32_t)((wm + mi * 16 + rA) * ROWB           \
                                         + (kh * 2 + selA) * 16));            \
            uint32_t b[4][4];                                                 \
            _Pragma("unroll")                                                 \
            for (int p = 0; p < 4; ++p)                                       \
                ldsm_x4(b[p][0], b[p][1], b[p][2], b[p][3],                   \
                        stB + (uint32_t)((wn + p * 16 + rB) * ROWB            \
                                         + (kh * 2 + selB) * 16));            \
            _Pragma("unroll")                                                 \
            for (int mi = 0; mi < 4; ++mi) {                                  \
                _Pragma("unroll")                                             \
                for (int p = 0; p < 4; ++p) {                                 \
                    mma16816f(acc[mi][2 * p],     a[mi], &b[p][0]);           \
                    mma16816f(acc[mi][2 * p + 1], a[mi], &b[p][2]);           \
                }                                                             \
            }                                                                 \
        }                                                                     \
        const int j = it + GSTAGES - 1;                                       \
        if (j < NITERS)                                                       \
            LOADFN(base + (j & (GSTAGES - 1)) * STAGE, APTR, BPTR,            \
                   m0, n0, j, t);                                             \
    }

#define GEMM_PROLOG_COMMON                                                    \
    extern __shared__ char smraw[];                                           \
    const uint32_t base = smem_u32(smraw);                                    \
    const int t    = threadIdx.x;                                             \
    const int wid  = t >> 5;                                                  \
    const int lane = t & 31;                                                  \
    const int m0   = blockIdx.y * BM;                                         \
    const int wm   = (wid >> 1) * 64;                                         \
    const int wn   = (wid & 1) * 64;                                          \
    const int rA   = lane & 15;                                               \
    const int selA = lane >> 4;                                               \
    const int rB   = ((lane >> 4) << 3) | (lane & 7);                         \
    const int selB = (lane >> 3) & 1;

// Merged Q+K+V projection: grid.x covers 3*HDIM (Q | K | V cols).
// QK CTAs: 2-term (256 iters, fp32 out). V CTAs: plain (128 iters, fp16 out).
__global__ void __launch_bounds__(128, 2)
gemm_qkv(const __half* __restrict__ A2,
         const __half* __restrict__ Bq,
         const __half* __restrict__ Bk,
         const __half* __restrict__ Bv,
         float* __restrict__ Cq,
         float* __restrict__ Ck,
         __half* __restrict__ Vf)
{
    GEMM_PROLOG_COMMON
    const int n0g = blockIdx.x * BN;
    const int er = lane >> 2;
    const int ec = (lane & 3) << 1;

    if (n0g < 2 * HDIM) {
        const __half* B2 = (n0g < HDIM) ? Bq : Bk;
        float* C = (n0g < HDIM) ? Cq : Ck;
        const int n0 = n0g & (HDIM - 1);

        GEMM_BODY_GEN(g_load_stage_f, NITERF, A2, B2)

#pragma unroll
        for (int mi = 0; mi < 4; ++mi) {
#pragma unroll
            for (int nj = 0; nj < 8; ++nj) {
                size_t r0 = (size_t)(m0 + wm + mi * 16 + er) * HDIM
                            + (n0 + wn + nj * 8 + ec);
                *(float2*)&C[r0]            = make_float2(acc[mi][nj][0], acc[mi][nj][1]);
                *(float2*)&C[r0 + 8 * HDIM] = make_float2(acc[mi][nj][2], acc[mi][nj][3]);
            }
        }
    } else {
        const int n0 = n0g - 2 * HDIM;

        GEMM_BODY_GEN(g_load_stage_p, NITERP, A2, Bv)

#pragma unroll
        for (int mi = 0; mi < 4; ++mi) {
            int s0 = m0 + wm + mi * 16 + er;
#pragma unroll
            for (int nj = 0; nj < 8; ++nj) {
                int col = n0 + wn + nj * 8 + ec;
                int h   = col >> 7;
                int hc  = col & 127;
                size_t b0 = ((size_t)h * S_LEN + s0) * HEADD + hc;
                size_t b1 = ((size_t)h * S_LEN + s0 + 8) * HEADD + hc;
                *(uint32_t*)(Vf + b0) = pkh(__float2half_rn(acc[mi][nj][0]),
                                            __float2half_rn(acc[mi][nj][1]));
                *(uint32_t*)(Vf + b1) = pkh(__float2half_rn(acc[mi][nj][2]),
                                            __float2half_rn(acc[mi][nj][3]));
            }
        }
    }
}

// Plain fp16 GEMM, fp32 output (O projection)
__global__ void __launch_bounds__(128, 2)
gemm_f16o(const __half* __restrict__ A2,
          const __half* __restrict__ B2,
          float* __restrict__ C)
{
    GEMM_PROLOG_COMMON
    const int n0 = blockIdx.x * BN;
    GEMM_BODY_GEN(g_load_stage_p, NITERP, A2, B2)

    const int er = lane >> 2;
    const int ec = (lane & 3) << 1;
#pragma unroll
    for (int mi = 0; mi < 4; ++mi) {
#pragma unroll
        for (int nj = 0; nj < 8; ++nj) {
            size_t r0 = (size_t)(m0 + wm + mi * 16 + er) * HDIM
                        + (n0 + wn + nj * 8 + ec);
            *(float2*)&C[r0]            = make_float2(acc[mi][nj][0], acc[mi][nj][1]);
            *(float2*)&C[r0 + 8 * HDIM] = make_float2(acc[mi][nj][2], acc[mi][nj][3]);
        }
    }
}

// ===========================================================================
// Fused RoPE + head-dim fp16 2-term split:
// Q2f = [fp16(q*s) | fp16(q*s*2^-10)], K2f = [fp16(k) | fp16((k-kh)*1024)]
// ===========================================================================
#define ATT_SCALE 0.08838834764831843f

__global__ void __launch_bounds__(256) rope_split_qk(
    const float* __restrict__ Q, const float* __restrict__ K,
    const int* __restrict__ pos,
    __half* __restrict__ Q2, __half* __restrict__ K2o)
{
    int idx = blockIdx.x * 256 + threadIdx.x;
    if (idx >= S_LEN * NHEADS * 16) return;
    int j4 = (idx & 15) << 2;
    int h  = (idx >> 4) & (NHEADS - 1);
    int s  = idx >> 9;
    int p  = pos[s];

    float sn[4], cs[4];
#pragma unroll
    for (int i = 0; i < 4; ++i) {
        float inv = 1.0f / powf(10000.0f, (float)(j4 + i) * (1.0f / 64.0f));
        sincosf((float)p * inv, &sn[i], &cs[i]);
    }

    size_t gb = (size_t)s * HDIM + (size_t)h * HEADD + j4;
    float4 qa4 = *(const float4*)&Q[gb];
    float4 qb4 = *(const float4*)&Q[gb + 64];
    float4 ka4 = *(const float4*)&K[gb];
    float4 kb4 = *(const float4*)&K[gb + 64];
    float qa[4] = {qa4.x, qa4.y, qa4.z, qa4.w};
    float qb[4] = {qb4.x, qb4.y, qb4.z, qb4.w};
    float ka[4] = {ka4.x, ka4.y, ka4.z, ka4.w};
    float kb[4] = {kb4.x, kb4.y, kb4.z, kb4.w};

    __half qh1[4], ql1[4], qh2[4], ql2[4];
    __half kh1[4], kl1[4], kh2[4], kl2[4];
#pragma unroll
    for (int i = 0; i < 4; ++i) {
        float r1 = (qa[i] * cs[i] - qb[i] * sn[i]) * ATT_SCALE;
        float r2 = (qb[i] * cs[i] + qa[i] * sn[i]) * ATT_SCALE;
        qh1[i] = __float2half_rn(r1);  ql1[i] = __float2half_rn(r1 * SC10);
        qh2[i] = __float2half_rn(r2);  ql2[i] = __float2half_rn(r2 * SC10);
        float t1 = ka[i] * cs[i] - kb[i] * sn[i];
        float t2 = kb[i] * cs[i] + ka[i] * sn[i];
        kh1[i] = __float2half_rn(t1);
        kl1[i] = __float2half_rn((t1 - __half2float(kh1[i])) * 1024.0f);
        kh2[i] = __float2half_rn(t2);
        kl2[i] = __float2half_rn((t2 - __half2float(kh2[i])) * 1024.0f);
    }

    size_t ob = ((size_t)h * S_LEN + s) * HD2 + j4;
    *(uint2*)(Q2 + ob)       = make_uint2(pkh(qh1[0], qh1[1]), pkh(qh1[2], qh1[3]));
    *(uint2*)(Q2 + ob + 64)  = make_uint2(pkh(qh2[0], qh2[1]), pkh(qh2[2], qh2[3]));
    *(uint2*)(Q2 + ob + 128) = make_uint2(pkh(ql1[0], ql1[1]), pkh(ql1[2], ql1[3]));
    *(uint2*)(Q2 + ob + 192) = make_uint2(pkh(ql2[0], ql2[1]), pkh(ql2[2], ql2[3]));

    *(uint2*)(K2o + ob)       = make_uint2(pkh(kh1[0], kh1[1]), pkh(kh1[2], kh1[3]));
    *(uint2*)(K2o + ob + 64)  = make_uint2(pkh(kh2[0], kh2[1]), pkh(kh2[2], kh2[3]));
    *(uint2*)(K2o + ob + 128) = make_uint2(pkh(kl1[0], kl1[1]), pkh(kl1[2], kl1[3]));
    *(uint2*)(K2o + ob + 192) = make_uint2(pkh(kl2[0], kl2[1]), pkh(kl2[2], kl2[3]));
}

// ===========================================================================
// Flash attention v6: 256 threads. All-fp16 tensor path.
// Scores: fp16 2-pass (seg-matched). fp32 softmax -> fp16 P. PV fp16 1-pass.
// ===========================================================================
#define NEG_BIG (-3.0e38f)
#define FROW2  528
#define FROWV  272
#define FROWP  144
#define OFF_K2S  (64 * FROW2)
#define OFF_VS   (OFF_K2S + 2 * 64 * FROW2)
#define OFF_SS   (OFF_VS + 2 * 64 * FROWV)
#define OFF_PS   (OFF_SS + 64 * 68 * 4)
#define OFF_RW   (OFF_PS + 64 * FROWP)
#define FSMEM    (OFF_RW + 3 * 64 * 4)

__device__ __forceinline__ void f_load_kv(uint32_t sb, int buf,
                                          const __half* __restrict__ K2g,
                                          const __half* __restrict__ Vg,
                                          int t)
{
    uint32_t kb = sb + OFF_K2S + buf * (64 * FROW2);
    for (int c = t; c < 64 * 32; c += 256) {
        int r = c >> 5, ch = c & 31;
        cp_async16(kb + r * FROW2 + ch * 16,
                   (const char*)K2g + (size_t)r * (HD2 * 2) + ch * 16);
    }
    uint32_t vb = sb + OFF_VS + buf * (64 * FROWV);
    for (int c = t; c < 64 * 16; c += 256) {
        int r = c >> 4, ch = c & 15;
        cp_async16(vb + r * FROWV + ch * 16,
                   (const char*)Vg + (size_t)r * (HEADD * 2) + ch * 16);
    }
    cp_commit();
}

__global__ void __launch_bounds__(256) flash2(
    const __half* __restrict__ Q2,
    const __half* __restrict__ K2g,
    const __half* __restrict__ Vf,
    __half* __restrict__ A2out)
{
    extern __shared__ char smraw[];
    const uint32_t sb = smem_u32(smraw);
    float* Ss  = (float*)(smraw + OFF_SS);
    __half* Ps = (__half*)(smraw + OFF_PS);
    float* mrow = (float*)(smraw + OFF_RW);
    float* lrow = mrow + 64;
    float* srow = lrow + 64;

    const int h  = blockIdx.x;
    const int qb = (gridDim.y - 1) - blockIdx.y;
    const int q0 = qb * 64;
    const int t = threadIdx.x, wid = t >> 5, lane = t & 31;
    const int wm = (wid >> 2) * 32;
    const int wn = (wid & 3) * 16;
    const int wnv = (wid & 3) * 32;
    const int rA = lane & 15, selA = lane >> 4;
    const int rB = ((lane >> 4) << 3) | (lane & 7), selB = (lane >> 3) & 1;
    const int er = lane >> 2, ec = (lane & 3) << 1;

    const __half* Qg = Q2 + ((size_t)h * S_LEN + q0) * HD2;
    for (int c = t; c < 64 * 32; c += 256) {
        int r = c >> 5, ch = c & 31;
        cp_async16(sb + r * FROW2 + ch * 16,
                   (const char*)Qg + (size_t)r * (HD2 * 2) + ch * 16);
    }
    cp_commit();
    if (t < 64) { mrow[t] = NEG_BIG; lrow[t] = 0.0f; }

    f_load_kv(sb, 0, K2g + ((size_t)h * S_LEN) * HD2,
              Vf + ((size_t)h * S_LEN) * HEADD, t);

    float oacc[2][4][4];
#pragma unroll
    for (int mi = 0; mi < 2; ++mi)
#pragma unroll
        for (int nj = 0; nj < 4; ++nj)
#pragma unroll
            for (int q = 0; q < 4; ++q) oacc[mi][nj][q] = 0.0f;

    for (int kb = 0; kb <= qb; ++kb) {
        const int buf = kb & 1;
        cp_wait<0>();
        __syncthreads();

        if (kb + 1 <= qb)
            f_load_kv(sb, buf ^ 1,
                      K2g + ((size_t)h * S_LEN + (kb + 1) * 64) * HD2,
                      Vf + ((size_t)h * S_LEN + (kb + 1) * 64) * HEADD, t);

        const uint32_t kbase = sb + OFF_K2S + buf * (64 * FROW2);
        const uint32_t vbase = sb + OFF_VS + buf * (64 * FROWV);

        // ---- scores: fp16 2-pass, segment-matched offsets ----
        float sacc[2][2][4];
#pragma unroll
        for (int mi = 0; mi < 2; ++mi)
#pragma unroll
            for (int nj = 0; nj < 2; ++nj)
#pragma unroll
                for (int q = 0; q < 4; ++q) sacc[mi][nj][q] = 0.0f;

#pragma unroll
        for (int ps = 0; ps < 2; ++ps) {
            const uint32_t soff = ps * 256u;
#pragma unroll
            for (int k16 = 0; k16 < 8; ++k16) {
                uint32_t a[2][4], b[4];
#pragma unroll
                for (int mi = 0; mi < 2; ++mi)
                    ldsm_x4(a[mi][0], a[mi][1], a[mi][2], a[mi][3],
                            sb + (uint32_t)((wm + mi * 16 + rA) * FROW2)
                               + soff + k16 * 32 + selA * 16);
                ldsm_x4(b[0], b[1], b[2], b[3],
                        kbase + (uint32_t)((wn + rB) * FROW2)
                              + soff + k16 * 32 + selB * 16);
#pragma unroll
                for (int mi = 0; mi < 2; ++mi)
#pragma unroll
                    for (int nj = 0; nj < 2; ++nj)
                        mma16816f(sacc[mi][nj], a[mi], &b[nj << 1]);
            }
        }

        const bool diag = (kb == qb);
#pragma unroll
        for (int mi = 0; mi < 2; ++mi) {
#pragma unroll
            for (int nj = 0; nj < 2; ++nj) {
                int row = wm + mi * 16 + er;
                int col = wn + nj * 8 + ec;
                float v0 = sacc[mi][nj][0], v1 = sacc[mi][nj][1];
                float v2 = sacc[mi][nj][2], v3 = sacc[mi][nj][3];
                if (diag) {
                    if (col > row)     v0 = NEG_BIG;
                    if (col + 1 > row) v1 = NEG_BIG;
                    if (col > row + 8)     v2 = NEG_BIG;
                    if (col + 1 > row + 8) v3 = NEG_BIG;
                }
                Ss[row * 68 + col]       = v0;
                Ss[row * 68 + col + 1]   = v1;
                Ss[(row + 8) * 68 + col]     = v2;
                Ss[(row + 8) * 68 + col + 1] = v3;
            }
        }
        __syncthreads();

        {
            int r  = t >> 2;
            int qd = t & 3;
            float* srw = &Ss[r * 68 + qd * 16];
            __half* prw = &Ps[r * 72 + qd * 16];
            float vals[16];
            float mx = NEG_BIG;
#pragma unroll
            for (int i = 0; i < 16; ++i) { vals[i] = srw[i]; mx = fmaxf(mx, vals[i]); }
            mx = fmaxf(mx, __shfl_xor_sync(0xffffffffu, mx, 1));
            mx = fmaxf(mx, __shfl_xor_sync(0xffffffffu, mx, 2));
            float mold = mrow[r];
            float mnew = fmaxf(mold, mx);
            float sum = 0.0f;
#pragma unroll
            for (int i = 0; i < 16; ++i) {
                float p = __expf(vals[i] - mnew);
                prw[i] = __float2half_rn(p);
                sum += p;
            }
            sum += __shfl_xor_sync(0xffffffffu, sum, 1);
            sum += __shfl_xor_sync(0xffffffffu, sum, 2);
            float corr = __expf(mold - mnew);
            if (qd == 0) {
                mrow[r] = mnew;
                lrow[r] = lrow[r] * corr + sum;
                srow[r] = corr;
            }
        }
        __syncthreads();

#pragma unroll
        for (int mi = 0; mi < 2; ++mi) {
            float c0 = srow[wm + mi * 16 + er];
            float c1 = srow[wm + mi * 16 + er + 8];
#pragma unroll
            for (int nj = 0; nj < 4; ++nj) {
                oacc[mi][nj][0] *= c0; oacc[mi][nj][1] *= c0;
                oacc[mi][nj][2] *= c1; oacc[mi][nj][3] *= c1;
            }
        }

        const int vkr = ((lane >> 3) & 1) * 8 + (lane & 7);
        const int vnc = (lane >> 4) * 8;
#pragma unroll
        for (int kk = 0; kk < 4; ++kk) {
            uint32_t a[2][4], b0[4], b1[4];
#pragma unroll
            for (int mi = 0; mi < 2; ++mi)
                ldsm_x4(a[mi][0], a[mi][1], a[mi][2], a[mi][3],
                        sb + OFF_PS + (uint32_t)((wm + mi * 16 + rA) * FROWP)
                           + kk * 32 + selA * 16);
            uint32_t vaddr = vbase + (uint32_t)((kk * 16 + vkr) * FROWV);
            ldsm_x4t(b0[0], b0[1], b0[2], b0[3], vaddr + (wnv + vnc) * 2);
            ldsm_x4t(b1[0], b1[1], b1[2], b1[3], vaddr + (wnv + 16 + vnc) * 2);
#pragma unroll
            for (int mi = 0; mi < 2; ++mi) {
                mma16816f(oacc[mi][0], a[mi], &b0[0]);
                mma16816f(oacc[mi][1], a[mi], &b0[2]);
                mma16816f(oacc[mi][2], a[mi], &b1[0]);
                mma16816f(oacc[mi][3], a[mi], &b1[2]);
            }
        }
    }

    // epilogue: normalize, write plain fp16 (seg0 only — O-proj is plain)
#pragma unroll
    for (int mi = 0; mi < 2; ++mi) {
        float l0 = 1.0f / lrow[wm + mi * 16 + er];
        float l1 = 1.0f / lrow[wm + mi * 16 + er + 8];
#pragma unroll
        for (int nj = 0; nj < 4; ++nj) {
            int col = h * HEADD + wnv + nj * 8 + ec;
            size_t r0 = (size_t)(q0 + wm + mi * 16 + er) * KST2 + col;
            size_t r1 = r0 + (size_t)8 * KST2;
            float x0 = oacc[mi][nj][0] * l0, x1 = oacc[mi][nj][1] * l0;
            float y0 = oacc[mi][nj][2] * l1, y1 = oacc[mi][nj][3] * l1;
            *(uint32_t*)(A2out + r0) =
                pkh(__float2half_rn(x0), __float2half_rn(x1));
            *(uint32_t*)(A2out + r1) =
                pkh(__float2half_rn(y0), __float2half_rn(y1));
        }
    }
}

// ===========================================================================
// Launch
// ===========================================================================
extern "C" void kernel_launch(void* const* d_in, const int* in_sizes, int n_in,
                              void* d_out, int out_size)
{
    (void)in_sizes; (void)n_in; (void)out_size;

    const float* X   = (const float*)d_in[0];
    const int*   pos = (const int*)d_in[2];
    const float* Wq  = (const float*)d_in[3];
    const float* Wk  = (const float*)d_in[4];
    const float* Wv  = (const float*)d_in[5];
    const float* Wo  = (const float*)d_in[6];
    float* out = (float*)d_out;

    float *Qd, *Kd;
    __half *A2fd, *W2qfd, *W2kfd, *Wvfd, *Wofd, *Q2d, *K2d, *Vfd;
    cudaGetSymbolAddress((void**)&Qd, g_Q);
    cudaGetSymbolAddress((void**)&Kd, g_K);
    cudaGetSymbolAddress((void**)&A2fd, g_A2f);
    cudaGetSymbolAddress((void**)&W2qfd, g_W2qf);
    cudaGetSymbolAddress((void**)&W2kfd, g_W2kf);
    cudaGetSymbolAddress((void**)&Wvfd, g_Wvf);
    cudaGetSymbolAddress((void**)&Wofd, g_Wof);
    cudaGetSymbolAddress((void**)&Q2d, g_Q2f);
    cudaGetSymbolAddress((void**)&K2d, g_K2f);
    cudaGetSymbolAddress((void**)&Vfd, g_Vf);

    cudaFuncSetAttribute(gemm_qkv, cudaFuncAttributeMaxDynamicSharedMemorySize, GSMEM);
    cudaFuncSetAttribute(gemm_f16o, cudaFuncAttributeMaxDynamicSharedMemorySize, GSMEM);
    cudaFuncSetAttribute(flash2, cudaFuncAttributeMaxDynamicSharedMemorySize, FSMEM);

    split_xf<<<(S_LEN * 1024) / 256, 256>>>(X, A2fd, S_LEN * 1024);
    split_wf16<<<(HDIM * 1024) / 256, 256>>>(Wq, W2qfd, HDIM * 1024);
    split_wf16<<<(HDIM * 1024) / 256, 256>>>(Wk, W2kfd, HDIM * 1024);
    conv_wf<<<(HDIM * 1024) / 256, 256>>>(Wv, Wvfd, HDIM * 1024);
    conv_wf<<<(HDIM * 1024) / 256, 256>>>(Wo, Wofd, HDIM * 1024);

    // Merged Q+K+V projection (1536 CTAs: QK 2-term first, V plain tail)
    gemm_qkv<<<dim3(3 * HDIM / BN, S_LEN / BM), 128, GSMEM>>>(
        A2fd, W2qfd, W2kfd, Wvfd, Qd, Kd, Vfd);

    rope_split_qk<<<(S_LEN * NHEADS * 16) / 256, 256>>>(Qd, Kd, pos, Q2d, K2d);

    flash2<<<dim3(NHEADS, S_LEN / 64), 256, FSMEM>>>(Q2d, K2d, Vfd, A2fd);

    gemm_f16o<<<dim3(HDIM / BN, S_LEN / BM), 128, GSMEM>>>(A2fd, Wofd, out);
}

// round 16
// speedup vs baseline: 2.0999x; 1.2555x over previous
#include <cuda_runtime.h>
#include <cuda_fp16.h>
#include <math.h>
#include <stdint.h>

// Problem constants
#define S_LEN  2048
#define HDIM   4096
#define NHEADS 32
#define HEADD  128
#define HD2    256      // Q/K head-dim split storage: [seg0(128) | seg1(128)]

#define KSEG   4096
#define KST2   8192
#define SC10   0.0009765625f   // 2^-10

// Scratch (device globals)
__device__ float g_Q[S_LEN * HDIM];
__device__ float g_K[S_LEN * HDIM];
__device__ __half g_A2f[S_LEN * KST2];          // X fp16 (seg0) / attn out (seg0); stride KST2
__device__ __half g_Wqf[HDIM * KSEG];           // plain fp16 weights
__device__ __half g_Wkf[HDIM * KSEG];
__device__ __half g_Wvf[HDIM * KSEG];
__device__ __half g_Wof[HDIM * KSEG];
__device__ __half g_Q2f[NHEADS * S_LEN * HD2];  // [h][s][qh*s | qh*s*2^-10]
__device__ __half g_K2f[NHEADS * S_LEN * HD2];  // [h][s][kh   | kl*2^10]
__device__ __half g_Vf[NHEADS * S_LEN * HEADD]; // [h][s][128] fp16

// ===========================================================================
// PTX helpers
// ===========================================================================
__device__ __forceinline__ uint32_t smem_u32(const void* p) {
    uint32_t a;
    asm("{ .reg .u64 t; cvta.to.shared.u64 t, %1; cvt.u32.u64 %0, t; }" : "=r"(a) : "l"(p));
    return a;
}
__device__ __forceinline__ void cp_async16(uint32_t dst, const void* src) {
    asm volatile("cp.async.cg.shared.global [%0], [%1], 16;" :: "r"(dst), "l"(src));
}
__device__ __forceinline__ void cp_commit() {
    asm volatile("cp.async.commit_group;" ::: "memory");
}
template <int N> __device__ __forceinline__ void cp_wait() {
    asm volatile("cp.async.wait_group %0;" :: "n"(N) : "memory");
}
__device__ __forceinline__ void ldsm_x4(uint32_t& r0, uint32_t& r1, uint32_t& r2,
                                        uint32_t& r3, uint32_t addr) {
    asm volatile("ldmatrix.sync.aligned.m8n8.x4.shared.b16 {%0,%1,%2,%3}, [%4];"
                 : "=r"(r0), "=r"(r1), "=r"(r2), "=r"(r3) : "r"(addr));
}
__device__ __forceinline__ void ldsm_x4t(uint32_t& r0, uint32_t& r1, uint32_t& r2,
                                         uint32_t& r3, uint32_t addr) {
    asm volatile("ldmatrix.sync.aligned.m8n8.x4.trans.shared.b16 {%0,%1,%2,%3}, [%4];"
                 : "=r"(r0), "=r"(r1), "=r"(r2), "=r"(r3) : "r"(addr));
}
__device__ __forceinline__ void mma16816f(float* c, const uint32_t* a, const uint32_t* b) {
    asm volatile(
        "mma.sync.aligned.m16n8k16.row.col.f32.f16.f16.f32 "
        "{%0,%1,%2,%3}, {%4,%5,%6,%7}, {%8,%9}, {%0,%1,%2,%3};"
        : "+f"(c[0]), "+f"(c[1]), "+f"(c[2]), "+f"(c[3])
        : "r"(a[0]), "r"(a[1]), "r"(a[2]), "r"(a[3]), "r"(b[0]), "r"(b[1]));
}

__device__ __forceinline__ uint32_t pkh(__half a, __half b) {
    __half2 t = __halves2half2(a, b);
    return *reinterpret_cast<uint32_t*>(&t);
}

// ===========================================================================
// Convert kernels
// ===========================================================================
// X fp32 -> fp16 seg0 only (stride KST2)
__global__ void __launch_bounds__(256) conv_xf(const float* __restrict__ src,
                                               __half* __restrict__ dst,
                                               int total4)
{
    int i = blockIdx.x * 256 + threadIdx.x;
    if (i >= total4) return;
    int row = i >> 10;
    int c4  = (i & 1023) << 2;
    float4 v = ((const float4*)src)[i];
    *(uint2*)(dst + (size_t)row * KST2 + c4) =
        make_uint2(pkh(__float2half_rn(v.x), __float2half_rn(v.y)),
                   pkh(__float2half_rn(v.z), __float2half_rn(v.w)));
}

// W fp32 -> plain fp16 (stride KSEG)
__global__ void __launch_bounds__(256) conv_wf(const float* __restrict__ src,
                                               __half* __restrict__ dst,
                                               int total4)
{
    int i = blockIdx.x * 256 + threadIdx.x;
    if (i >= total4) return;
    int row = i >> 10;
    int c4  = (i & 1023) << 2;
    float4 v = ((const float4*)src)[i];
    *(uint2*)(dst + (size_t)row * KSEG + c4) =
        make_uint2(pkh(__float2half_rn(v.x), __float2half_rn(v.y)),
                   pkh(__float2half_rn(v.z), __float2half_rn(v.w)));
}

// ===========================================================================
// GEMM common: CTA 128x128, BK=32, 128 threads (2x2 warps, 64x64/warp),
// 4-stage cp.async, 2 CTAs/SM. All plain fp16 now (K=4096, 128 iters).
// ===========================================================================
#define BM 128
#define BN 128
#define BK 32
#define NITERP  128
#define GSTAGES 4
#define ROWB    80
#define ASZ     (BM * ROWB)
#define STAGE   (2 * ASZ)
#define GSMEM   (GSTAGES * STAGE)

// plain loader: A stride KST2 (seg0 only), B stride KSEG
__device__ __forceinline__ void g_load_stage_p(uint32_t sb,
                                               const __half* __restrict__ A2,
                                               const __half* __restrict__ B2,
                                               int m0, int n0, int j, int t)
{
    const int kloc = j * BK;
#pragma unroll
    for (int i = 0; i < 4; ++i) {
        int c   = t + (i << 7);
        int row = c >> 2;
        int kc  = c & 3;
        cp_async16(sb + row * ROWB + kc * 16,
                   A2 + (size_t)(m0 + row) * KST2 + kloc + kc * 8);
    }
#pragma unroll
    for (int i = 0; i < 4; ++i) {
        int c   = t + (i << 7);
        int row = c >> 2;
        int kc  = c & 3;
        cp_async16(sb + ASZ + row * ROWB + kc * 16,
                   B2 + (size_t)(n0 + row) * KSEG + kloc + kc * 8);
    }
    cp_commit();
}

#define GEMM_BODY_P(APTR, BPTR)                                               \
    float acc[4][8][4];                                                       \
    _Pragma("unroll")                                                         \
    for (int mi = 0; mi < 4; ++mi)                                            \
        _Pragma("unroll")                                                     \
        for (int nj = 0; nj < 8; ++nj)                                        \
            _Pragma("unroll")                                                 \
            for (int q = 0; q < 4; ++q) acc[mi][nj][q] = 0.0f;                \
    _Pragma("unroll")                                                         \
    for (int it = 0; it < GSTAGES - 1; ++it)                                  \
        g_load_stage_p(base + it * STAGE, APTR, BPTR, m0, n0, it, t);         \
    for (int it = 0; it < NITERP; ++it) {                                     \
        const int st = it & (GSTAGES - 1);                                    \
        cp_wait<GSTAGES - 2>();                                               \
        __syncthreads();                                                      \
        const uint32_t stA = base + st * STAGE;                               \
        const uint32_t stB = stA + ASZ;                                       \
        _Pragma("unroll")                                                     \
        for (int kh = 0; kh < 2; ++kh) {                                      \
            uint32_t a[4][4];                                                 \
            _Pragma("unroll")                                                 \
            for (int mi = 0; mi < 4; ++mi)                                    \
                ldsm_x4(a[mi][0], a[mi][1], a[mi][2], a[mi][3],               \
                        stA + (uint32_t)((wm + mi * 16 + rA) * ROWB           \
                                         + (kh * 2 + selA) * 16));            \
            uint32_t b[4][4];                                                 \
            _Pragma("unroll")                                                 \
            for (int p = 0; p < 4; ++p)                                       \
                ldsm_x4(b[p][0], b[p][1], b[p][2], b[p][3],                   \
                        stB + (uint32_t)((wn + p * 16 + rB) * ROWB            \
                                         + (kh * 2 + selB) * 16));            \
            _Pragma("unroll")                                                 \
            for (int mi = 0; mi < 4; ++mi) {                                  \
                _Pragma("unroll")                                             \
                for (int p = 0; p < 4; ++p) {                                 \
                    mma16816f(acc[mi][2 * p],     a[mi], &b[p][0]);           \
                    mma16816f(acc[mi][2 * p + 1], a[mi], &b[p][2]);           \
                }                                                             \
            }                                                                 \
        }                                                                     \
        const int j = it + GSTAGES - 1;                                       \
        if (j < NITERP)                                                       \
            g_load_stage_p(base + (j & (GSTAGES - 1)) * STAGE, APTR, BPTR,    \
                           m0, n0, j, t);                                     \
    }

#define GEMM_PROLOG_COMMON                                                    \
    extern __shared__ char smraw[];                                           \
    const uint32_t base = smem_u32(smraw);                                    \
    const int t    = threadIdx.x;                                             \
    const int wid  = t >> 5;                                                  \
    const int lane = t & 31;                                                  \
    const int m0   = blockIdx.y * BM;                                         \
    const int wm   = (wid >> 1) * 64;                                         \
    const int wn   = (wid & 1) * 64;                                          \
    const int rA   = lane & 15;                                               \
    const int selA = lane >> 4;                                               \
    const int rB   = ((lane >> 4) << 3) | (lane & 7);                         \
    const int selB = (lane >> 3) & 1;

// Merged Q+K+V projection: grid.x covers 3*HDIM (Q | K | V cols), all plain.
__global__ void __launch_bounds__(128, 2)
gemm_qkv(const __half* __restrict__ A2,
         const __half* __restrict__ Bq,
         const __half* __restrict__ Bk,
         const __half* __restrict__ Bv,
         float* __restrict__ Cq,
         float* __restrict__ Ck,
         __half* __restrict__ Vf)
{
    GEMM_PROLOG_COMMON
    const int n0g = blockIdx.x * BN;
    const int n0  = n0g & (HDIM - 1);
    const __half* B2 = (n0g < HDIM) ? Bq : ((n0g < 2 * HDIM) ? Bk : Bv);
    const int er = lane >> 2;
    const int ec = (lane & 3) << 1;

    GEMM_BODY_P(A2, B2)

    if (n0g < 2 * HDIM) {
        float* C = (n0g < HDIM) ? Cq : Ck;
#pragma unroll
        for (int mi = 0; mi < 4; ++mi) {
#pragma unroll
            for (int nj = 0; nj < 8; ++nj) {
                size_t r0 = (size_t)(m0 + wm + mi * 16 + er) * HDIM
                            + (n0 + wn + nj * 8 + ec);
                *(float2*)&C[r0]            = make_float2(acc[mi][nj][0], acc[mi][nj][1]);
                *(float2*)&C[r0 + 8 * HDIM] = make_float2(acc[mi][nj][2], acc[mi][nj][3]);
            }
        }
    } else {
#pragma unroll
        for (int mi = 0; mi < 4; ++mi) {
            int s0 = m0 + wm + mi * 16 + er;
#pragma unroll
            for (int nj = 0; nj < 8; ++nj) {
                int col = n0 + wn + nj * 8 + ec;
                int h   = col >> 7;
                int hc  = col & 127;
                size_t b0 = ((size_t)h * S_LEN + s0) * HEADD + hc;
                size_t b1 = ((size_t)h * S_LEN + s0 + 8) * HEADD + hc;
                *(uint32_t*)(Vf + b0) = pkh(__float2half_rn(acc[mi][nj][0]),
                                            __float2half_rn(acc[mi][nj][1]));
                *(uint32_t*)(Vf + b1) = pkh(__float2half_rn(acc[mi][nj][2]),
                                            __float2half_rn(acc[mi][nj][3]));
            }
        }
    }
}

// Plain fp16 GEMM, fp32 output (O projection)
__global__ void __launch_bounds__(128, 2)
gemm_f16o(const __half* __restrict__ A2,
          const __half* __restrict__ B2,
          float* __restrict__ C)
{
    GEMM_PROLOG_COMMON
    const int n0 = blockIdx.x * BN;
    GEMM_BODY_P(A2, B2)

    const int er = lane >> 2;
    const int ec = (lane & 3) << 1;
#pragma unroll
    for (int mi = 0; mi < 4; ++mi) {
#pragma unroll
        for (int nj = 0; nj < 8; ++nj) {
            size_t r0 = (size_t)(m0 + wm + mi * 16 + er) * HDIM
                        + (n0 + wn + nj * 8 + ec);
            *(float2*)&C[r0]            = make_float2(acc[mi][nj][0], acc[mi][nj][1]);
            *(float2*)&C[r0 + 8 * HDIM] = make_float2(acc[mi][nj][2], acc[mi][nj][3]);
        }
    }
}

// ===========================================================================
// Fused RoPE + head-dim fp16 2-term split (validated R15):
// Q2f = [fp16(q*s) | fp16(q*s*2^-10)], K2f = [fp16(k) | fp16((k-kh)*1024)]
// ===========================================================================
#define ATT_SCALE 0.08838834764831843f

__global__ void __launch_bounds__(256) rope_split_qk(
    const float* __restrict__ Q, const float* __restrict__ K,
    const int* __restrict__ pos,
    __half* __restrict__ Q2, __half* __restrict__ K2o)
{
    int idx = blockIdx.x * 256 + threadIdx.x;
    if (idx >= S_LEN * NHEADS * 16) return;
    int j4 = (idx & 15) << 2;
    int h  = (idx >> 4) & (NHEADS - 1);
    int s  = idx >> 9;
    int p  = pos[s];

    float sn[4], cs[4];
#pragma unroll
    for (int i = 0; i < 4; ++i) {
        float inv = 1.0f / powf(10000.0f, (float)(j4 + i) * (1.0f / 64.0f));
        sincosf((float)p * inv, &sn[i], &cs[i]);
    }

    size_t gb = (size_t)s * HDIM + (size_t)h * HEADD + j4;
    float4 qa4 = *(const float4*)&Q[gb];
    float4 qb4 = *(const float4*)&Q[gb + 64];
    float4 ka4 = *(const float4*)&K[gb];
    float4 kb4 = *(const float4*)&K[gb + 64];
    float qa[4] = {qa4.x, qa4.y, qa4.z, qa4.w};
    float qb[4] = {qb4.x, qb4.y, qb4.z, qb4.w};
    float ka[4] = {ka4.x, ka4.y, ka4.z, ka4.w};
    float kb[4] = {kb4.x, kb4.y, kb4.z, kb4.w};

    __half qh1[4], ql1[4], qh2[4], ql2[4];
    __half kh1[4], kl1[4], kh2[4], kl2[4];
#pragma unroll
    for (int i = 0; i < 4; ++i) {
        float r1 = (qa[i] * cs[i] - qb[i] * sn[i]) * ATT_SCALE;
        float r2 = (qb[i] * cs[i] + qa[i] * sn[i]) * ATT_SCALE;
        qh1[i] = __float2half_rn(r1);  ql1[i] = __float2half_rn(r1 * SC10);
        qh2[i] = __float2half_rn(r2);  ql2[i] = __float2half_rn(r2 * SC10);
        float t1 = ka[i] * cs[i] - kb[i] * sn[i];
        float t2 = kb[i] * cs[i] + ka[i] * sn[i];
        kh1[i] = __float2half_rn(t1);
        kl1[i] = __float2half_rn((t1 - __half2float(kh1[i])) * 1024.0f);
        kh2[i] = __float2half_rn(t2);
        kl2[i] = __float2half_rn((t2 - __half2float(kh2[i])) * 1024.0f);
    }

    size_t ob = ((size_t)h * S_LEN + s) * HD2 + j4;
    *(uint2*)(Q2 + ob)       = make_uint2(pkh(qh1[0], qh1[1]), pkh(qh1[2], qh1[3]));
    *(uint2*)(Q2 + ob + 64)  = make_uint2(pkh(qh2[0], qh2[1]), pkh(qh2[2], qh2[3]));
    *(uint2*)(Q2 + ob + 128) = make_uint2(pkh(ql1[0], ql1[1]), pkh(ql1[2], ql1[3]));
    *(uint2*)(Q2 + ob + 192) = make_uint2(pkh(ql2[0], ql2[1]), pkh(ql2[2], ql2[3]));

    *(uint2*)(K2o + ob)       = make_uint2(pkh(kh1[0], kh1[1]), pkh(kh1[2], kh1[3]));
    *(uint2*)(K2o + ob + 64)  = make_uint2(pkh(kh2[0], kh2[1]), pkh(kh2[2], kh2[3]));
    *(uint2*)(K2o + ob + 128) = make_uint2(pkh(kl1[0], kl1[1]), pkh(kl1[2], kl1[3]));
    *(uint2*)(K2o + ob + 192) = make_uint2(pkh(kl2[0], kl2[1]), pkh(kl2[2], kl2[3]));
}

// ===========================================================================
// Flash attention v6 (validated R15): 256 threads, all-fp16 tensor path.
// Scores: fp16 2-pass (seg-matched). fp32 softmax -> fp16 P. PV fp16 1-pass.
// ===========================================================================
#define NEG_BIG (-3.0e38f)
#define FROW2  528
#define FROWV  272
#define FROWP  144
#define OFF_K2S  (64 * FROW2)
#define OFF_VS   (OFF_K2S + 2 * 64 * FROW2)
#define OFF_SS   (OFF_VS + 2 * 64 * FROWV)
#define OFF_PS   (OFF_SS + 64 * 68 * 4)
#define OFF_RW   (OFF_PS + 64 * FROWP)
#define FSMEM    (OFF_RW + 3 * 64 * 4)

__device__ __forceinline__ void f_load_kv(uint32_t sb, int buf,
                                          const __half* __restrict__ K2g,
                                          const __half* __restrict__ Vg,
                                          int t)
{
    uint32_t kb = sb + OFF_K2S + buf * (64 * FROW2);
    for (int c = t; c < 64 * 32; c += 256) {
        int r = c >> 5, ch = c & 31;
        cp_async16(kb + r * FROW2 + ch * 16,
                   (const char*)K2g + (size_t)r * (HD2 * 2) + ch * 16);
    }
    uint32_t vb = sb + OFF_VS + buf * (64 * FROWV);
    for (int c = t; c < 64 * 16; c += 256) {
        int r = c >> 4, ch = c & 15;
        cp_async16(vb + r * FROWV + ch * 16,
                   (const char*)Vg + (size_t)r * (HEADD * 2) + ch * 16);
    }
    cp_commit();
}

__global__ void __launch_bounds__(256) flash2(
    const __half* __restrict__ Q2,
    const __half* __restrict__ K2g,
    const __half* __restrict__ Vf,
    __half* __restrict__ A2out)
{
    extern __shared__ char smraw[];
    const uint32_t sb = smem_u32(smraw);
    float* Ss  = (float*)(smraw + OFF_SS);
    __half* Ps = (__half*)(smraw + OFF_PS);
    float* mrow = (float*)(smraw + OFF_RW);
    float* lrow = mrow + 64;
    float* srow = lrow + 64;

    const int h  = blockIdx.x;
    const int qb = (gridDim.y - 1) - blockIdx.y;
    const int q0 = qb * 64;
    const int t = threadIdx.x, wid = t >> 5, lane = t & 31;
    const int wm = (wid >> 2) * 32;
    const int wn = (wid & 3) * 16;
    const int wnv = (wid & 3) * 32;
    const int rA = lane & 15, selA = lane >> 4;
    const int rB = ((lane >> 4) << 3) | (lane & 7), selB = (lane >> 3) & 1;
    const int er = lane >> 2, ec = (lane & 3) << 1;

    const __half* Qg = Q2 + ((size_t)h * S_LEN + q0) * HD2;
    for (int c = t; c < 64 * 32; c += 256) {
        int r = c >> 5, ch = c & 31;
        cp_async16(sb + r * FROW2 + ch * 16,
                   (const char*)Qg + (size_t)r * (HD2 * 2) + ch * 16);
    }
    cp_commit();
    if (t < 64) { mrow[t] = NEG_BIG; lrow[t] = 0.0f; }

    f_load_kv(sb, 0, K2g + ((size_t)h * S_LEN) * HD2,
              Vf + ((size_t)h * S_LEN) * HEADD, t);

    float oacc[2][4][4];
#pragma unroll
    for (int mi = 0; mi < 2; ++mi)
#pragma unroll
        for (int nj = 0; nj < 4; ++nj)
#pragma unroll
            for (int q = 0; q < 4; ++q) oacc[mi][nj][q] = 0.0f;

    for (int kb = 0; kb <= qb; ++kb) {
        const int buf = kb & 1;
        cp_wait<0>();
        __syncthreads();

        if (kb + 1 <= qb)
            f_load_kv(sb, buf ^ 1,
                      K2g + ((size_t)h * S_LEN + (kb + 1) * 64) * HD2,
                      Vf + ((size_t)h * S_LEN + (kb + 1) * 64) * HEADD, t);

        const uint32_t kbase = sb + OFF_K2S + buf * (64 * FROW2);
        const uint32_t vbase = sb + OFF_VS + buf * (64 * FROWV);

        float sacc[2][2][4];
#pragma unroll
        for (int mi = 0; mi < 2; ++mi)
#pragma unroll
            for (int nj = 0; nj < 2; ++nj)
#pragma unroll
                for (int q = 0; q < 4; ++q) sacc[mi][nj][q] = 0.0f;

#pragma unroll
        for (int ps = 0; ps < 2; ++ps) {
            const uint32_t soff = ps * 256u;
#pragma unroll
            for (int k16 = 0; k16 < 8; ++k16) {
                uint32_t a[2][4], b[4];
#pragma unroll
                for (int mi = 0; mi < 2; ++mi)
                    ldsm_x4(a[mi][0], a[mi][1], a[mi][2], a[mi][3],
                            sb + (uint32_t)((wm + mi * 16 + rA) * FROW2)
                               + soff + k16 * 32 + selA * 16);
                ldsm_x4(b[0], b[1], b[2], b[3],
                        kbase + (uint32_t)((wn + rB) * FROW2)
                              + soff + k16 * 32 + selB * 16);
#pragma unroll
                for (int mi = 0; mi < 2; ++mi)
#pragma unroll
                    for (int nj = 0; nj < 2; ++nj)
                        mma16816f(sacc[mi][nj], a[mi], &b[nj << 1]);
            }
        }

        const bool diag = (kb == qb);
#pragma unroll
        for (int mi = 0; mi < 2; ++mi) {
#pragma unroll
            for (int nj = 0; nj < 2; ++nj) {
                int row = wm + mi * 16 + er;
                int col = wn + nj * 8 + ec;
                float v0 = sacc[mi][nj][0], v1 = sacc[mi][nj][1];
                float v2 = sacc[mi][nj][2], v3 = sacc[mi][nj][3];
                if (diag) {
                    if (col > row)     v0 = NEG_BIG;
                    if (col + 1 > row) v1 = NEG_BIG;
                    if (col > row + 8)     v2 = NEG_BIG;
                    if (col + 1 > row + 8) v3 = NEG_BIG;
                }
                Ss[row * 68 + col]       = v0;
                Ss[row * 68 + col + 1]   = v1;
                Ss[(row + 8) * 68 + col]     = v2;
                Ss[(row + 8) * 68 + col + 1] = v3;
            }
        }
        __syncthreads();

        {
            int r  = t >> 2;
            int qd = t & 3;
            float* srw = &Ss[r * 68 + qd * 16];
            __half* prw = &Ps[r * 72 + qd * 16];
            float vals[16];
            float mx = NEG_BIG;
#pragma unroll
            for (int i = 0; i < 16; ++i) { vals[i] = srw[i]; mx = fmaxf(mx, vals[i]); }
            mx = fmaxf(mx, __shfl_xor_sync(0xffffffffu, mx, 1));
            mx = fmaxf(mx, __shfl_xor_sync(0xffffffffu, mx, 2));
            float mold = mrow[r];
            float mnew = fmaxf(mold, mx);
            float sum = 0.0f;
#pragma unroll
            for (int i = 0; i < 16; ++i) {
                float p = __expf(vals[i] - mnew);
                prw[i] = __float2half_rn(p);
                sum += p;
            }
            sum += __shfl_xor_sync(0xffffffffu, sum, 1);
            sum += __shfl_xor_sync(0xffffffffu, sum, 2);
            float corr = __expf(mold - mnew);
            if (qd == 0) {
                mrow[r] = mnew;
                lrow[r] = lrow[r] * corr + sum;
                srow[r] = corr;
            }
        }
        __syncthreads();

#pragma unroll
        for (int mi = 0; mi < 2; ++mi) {
            float c0 = srow[wm + mi * 16 + er];
            float c1 = srow[wm + mi * 16 + er + 8];
#pragma unroll
            for (int nj = 0; nj < 4; ++nj) {
                oacc[mi][nj][0] *= c0; oacc[mi][nj][1] *= c0;
                oacc[mi][nj][2] *= c1; oacc[mi][nj][3] *= c1;
            }
        }

        const int vkr = ((lane >> 3) & 1) * 8 + (lane & 7);
        const int vnc = (lane >> 4) * 8;
#pragma unroll
        for (int kk = 0; kk < 4; ++kk) {
            uint32_t a[2][4], b0[4], b1[4];
#pragma unroll
            for (int mi = 0; mi < 2; ++mi)
                ldsm_x4(a[mi][0], a[mi][1], a[mi][2], a[mi][3],
                        sb + OFF_PS + (uint32_t)((wm + mi * 16 + rA) * FROWP)
                           + kk * 32 + selA * 16);
            uint32_t vaddr = vbase + (uint32_t)((kk * 16 + vkr) * FROWV);
            ldsm_x4t(b0[0], b0[1], b0[2], b0[3], vaddr + (wnv + vnc) * 2);
            ldsm_x4t(b1[0], b1[1], b1[2], b1[3], vaddr + (wnv + 16 + vnc) * 2);
#pragma unroll
            for (int mi = 0; mi < 2; ++mi) {
                mma16816f(oacc[mi][0], a[mi], &b0[0]);
                mma16816f(oacc[mi][1], a[mi], &b0[2]);
                mma16816f(oacc[mi][2], a[mi], &b1[0]);
                mma16816f(oacc[mi][3], a[mi], &b1[2]);
            }
        }
    }

    // epilogue: normalize, write plain fp16 (seg0 only)
#pragma unroll
    for (int mi = 0; mi < 2; ++mi) {
        float l0 = 1.0f / lrow[wm + mi * 16 + er];
        float l1 = 1.0f / lrow[wm + mi * 16 + er + 8];
#pragma unroll
        for (int nj = 0; nj < 4; ++nj) {
            int col = h * HEADD + wnv + nj * 8 + ec;
            size_t r0 = (size_t)(q0 + wm + mi * 16 + er) * KST2 + col;
            size_t r1 = r0 + (size_t)8 * KST2;
            float x0 = oacc[mi][nj][0] * l0, x1 = oacc[mi][nj][1] * l0;
            float y0 = oacc[mi][nj][2] * l1, y1 = oacc[mi][nj][3] * l1;
            *(uint32_t*)(A2out + r0) =
                pkh(__float2half_rn(x0), __float2half_rn(x1));
            *(uint32_t*)(A2out + r1) =
                pkh(__float2half_rn(y0), __float2half_rn(y1));
        }
    }
}

// ===========================================================================
// Launch
// ===========================================================================
extern "C" void kernel_launch(void* const* d_in, const int* in_sizes, int n_in,
                              void* d_out, int out_size)
{
    (void)in_sizes; (void)n_in; (void)out_size;

    const float* X   = (const float*)d_in[0];
    const int*   pos = (const int*)d_in[2];
    const float* Wq  = (const float*)d_in[3];
    const float* Wk  = (const float*)d_in[4];
    const float* Wv  = (const float*)d_in[5];
    const float* Wo  = (const float*)d_in[6];
    float* out = (float*)d_out;

    float *Qd, *Kd;
    __half *A2fd, *Wqfd, *Wkfd, *Wvfd, *Wofd, *Q2d, *K2d, *Vfd;
    cudaGetSymbolAddress((void**)&Qd, g_Q);
    cudaGetSymbolAddress((void**)&Kd, g_K);
    cudaGetSymbolAddress((void**)&A2fd, g_A2f);
    cudaGetSymbolAddress((void**)&Wqfd, g_Wqf);
    cudaGetSymbolAddress((void**)&Wkfd, g_Wkf);
    cudaGetSymbolAddress((void**)&Wvfd, g_Wvf);
    cudaGetSymbolAddress((void**)&Wofd, g_Wof);
    cudaGetSymbolAddress((void**)&Q2d, g_Q2f);
    cudaGetSymbolAddress((void**)&K2d, g_K2f);
    cudaGetSymbolAddress((void**)&Vfd, g_Vf);

    cudaFuncSetAttribute(gemm_qkv, cudaFuncAttributeMaxDynamicSharedMemorySize, GSMEM);
    cudaFuncSetAttribute(gemm_f16o, cudaFuncAttributeMaxDynamicSharedMemorySize, GSMEM);
    cudaFuncSetAttribute(flash2, cudaFuncAttributeMaxDynamicSharedMemorySize, FSMEM);

    conv_xf<<<(S_LEN * 1024) / 256, 256>>>(X, A2fd, S_LEN * 1024);
    conv_wf<<<(HDIM * 1024) / 256, 256>>>(Wq, Wqfd, HDIM * 1024);
    conv_wf<<<(HDIM * 1024) / 256, 256>>>(Wk, Wkfd, HDIM * 1024);
    conv_wf<<<(HDIM * 1024) / 256, 256>>>(Wv, Wvfd, HDIM * 1024);
    conv_wf<<<(HDIM * 1024) / 256, 256>>>(Wo, Wofd, HDIM * 1024);

    // Merged Q+K+V projection: 1536 CTAs, all plain fp16 (128 iters)
    gemm_qkv<<<dim3(3 * HDIM / BN, S_LEN / BM), 128, GSMEM>>>(
        A2fd, Wqfd, Wkfd, Wvfd, Qd, Kd, Vfd);

    rope_split_qk<<<(S_LEN * NHEADS * 16) / 256, 256>>>(Qd, Kd, pos, Q2d, K2d);

    flash2<<<dim3(NHEADS, S_LEN / 64), 256, FSMEM>>>(Q2d, K2d, Vfd, A2fd);

    gemm_f16o<<<dim3(HDIM / BN, S_LEN / BM), 128, GSMEM>>>(A2fd, Wofd, out);
}